// round 9
// baseline (speedup 1.0000x reference)
#include <cuda_runtime.h>
#include <cstdint>
#include <cstddef>

#define N_NODES 10000
#define E_ 320
#define D_ 15
#define T_ 16
#define OUT_ 30
#define UK 656
#define SR 324

// ---------------- scratch (device globals) ----------------
__device__ float g_MA[6 * E_ * E_];        // composed QKV mats [1920][320]
__device__ float g_Mq[E_ * E_];
__device__ float g_MKin[E_ * E_];
__device__ float g_MKout[E_ * E_];
__device__ float g_MVin[E_ * E_];
__device__ float g_MVout[E_ * E_];
__device__ float g_PW[E_ * 32];            // fo_w^T @ W, padded to 32 cols
__device__ float g_MqKcat[E_ * 640];       // [320][640] = [Mq^T MKin | Mq^T MKout]
__device__ float g_G[UK * 32];             // [656][32] out-projection matrix
__device__ float g_cq[E_];
__device__ float g_ckin[E_];
__device__ float g_ckout[E_];
__device__ float g_cvin[E_];
__device__ float g_cvout[E_];
__device__ float g_cW[32];
__device__ float g_wv[640];                // [win | wout]
__device__ float g_wb[2];                  // bin, bout
__device__ float g_cqK[640];               // [cq@MKin | cq@MKout]
__device__ float g_XP[(size_t)N_NODES * 1920];
__device__ float g_CTX[(size_t)N_NODES * 10240];
__device__ float g_C0[(size_t)N_NODES * E_];   // compact copy of in-side ctx token 0
__device__ float g_TT[(size_t)N_NODES * 640];
__device__ float g_U[(size_t)(N_NODES + 32) * UK];

struct GemmDesc {
    const float* A; const float* B; float* C; const float* bias;
    int M, N, K, lda, ldb, ldc, op;  // op: 0=NT, 1=NN, 2=TN
};
struct GemmBatch { GemmDesc d[12]; };

// ---------------- big GEMM: 128x128 tile, 8x8 micro, double-buffered ----------------
template <int OP>
__global__ void __launch_bounds__(256) sgemm128(GemmDesc g)
{
    __shared__ float As[2][16][132];
    __shared__ float Bs[2][16][132];
    int tid = threadIdx.x;
    int tx = tid & 15, ty = tid >> 4;
    int m0 = blockIdx.y * 128, n0 = blockIdx.x * 128;
    float acc[8][8] = {};

    int a_m = tid >> 2, a_k = (tid & 3) << 2;
    bool a0ok = (m0 + a_m) < g.M;
    bool a1ok = (m0 + a_m + 64) < g.M;
    const float* Ar0 = g.A + (size_t)(m0 + a_m) * g.lda + a_k;
    const float* Ar1 = g.A + (size_t)(m0 + a_m + 64) * g.lda + a_k;
    int b_n = tid >> 2, b_k4 = (tid & 3) << 2;   // OP==0
    int b_k = tid >> 5, b_nq = (tid & 31) << 2;  // OP==1
    const float* Br0;
    const float* Br1;
    if (OP == 0) {
        Br0 = g.B + (size_t)(n0 + b_n) * g.ldb + b_k4;
        Br1 = g.B + (size_t)(n0 + b_n + 64) * g.ldb + b_k4;
    } else {
        Br0 = g.B + (size_t)b_k * g.ldb + n0 + b_nq;
        Br1 = g.B + (size_t)(b_k + 8) * g.ldb + n0 + b_nq;
    }

    const float4 fz = make_float4(0.f, 0.f, 0.f, 0.f);
    float4 pa0 = a0ok ? *(const float4*)Ar0 : fz;
    float4 pa1 = a1ok ? *(const float4*)Ar1 : fz;
    float4 pb0 = *(const float4*)Br0;
    float4 pb1 = *(const float4*)Br1;

    As[0][a_k + 0][a_m] = pa0.x; As[0][a_k + 1][a_m] = pa0.y;
    As[0][a_k + 2][a_m] = pa0.z; As[0][a_k + 3][a_m] = pa0.w;
    As[0][a_k + 0][a_m + 64] = pa1.x; As[0][a_k + 1][a_m + 64] = pa1.y;
    As[0][a_k + 2][a_m + 64] = pa1.z; As[0][a_k + 3][a_m + 64] = pa1.w;
    if (OP == 0) {
        Bs[0][b_k4 + 0][b_n] = pb0.x; Bs[0][b_k4 + 1][b_n] = pb0.y;
        Bs[0][b_k4 + 2][b_n] = pb0.z; Bs[0][b_k4 + 3][b_n] = pb0.w;
        Bs[0][b_k4 + 0][b_n + 64] = pb1.x; Bs[0][b_k4 + 1][b_n + 64] = pb1.y;
        Bs[0][b_k4 + 2][b_n + 64] = pb1.z; Bs[0][b_k4 + 3][b_n + 64] = pb1.w;
    } else {
        *(float4*)&Bs[0][b_k][b_nq] = pb0;
        *(float4*)&Bs[0][b_k + 8][b_nq] = pb1;
    }
    __syncthreads();

    int buf = 0;
    for (int k0 = 0; k0 < g.K; k0 += 16) {
        bool nxt = (k0 + 16) < g.K;
        if (nxt) {
            int ko = k0 + 16;
            pa0 = a0ok ? *(const float4*)(Ar0 + ko) : fz;
            pa1 = a1ok ? *(const float4*)(Ar1 + ko) : fz;
            if (OP == 0) {
                pb0 = *(const float4*)(Br0 + ko);
                pb1 = *(const float4*)(Br1 + ko);
            } else {
                pb0 = *(const float4*)(Br0 + (size_t)ko * g.ldb);
                pb1 = *(const float4*)(Br1 + (size_t)ko * g.ldb);
            }
        }
        #pragma unroll
        for (int kk = 0; kk < 16; kk++) {
            float a[8], b[8];
            *(float4*)&a[0] = *(float4*)&As[buf][kk][ty * 8];
            *(float4*)&a[4] = *(float4*)&As[buf][kk][ty * 8 + 4];
            *(float4*)&b[0] = *(float4*)&Bs[buf][kk][tx * 8];
            *(float4*)&b[4] = *(float4*)&Bs[buf][kk][tx * 8 + 4];
            #pragma unroll
            for (int r = 0; r < 8; r++)
                #pragma unroll
                for (int c = 0; c < 8; c++)
                    acc[r][c] += a[r] * b[c];
        }
        if (nxt) {
            int nb = buf ^ 1;
            As[nb][a_k + 0][a_m] = pa0.x; As[nb][a_k + 1][a_m] = pa0.y;
            As[nb][a_k + 2][a_m] = pa0.z; As[nb][a_k + 3][a_m] = pa0.w;
            As[nb][a_k + 0][a_m + 64] = pa1.x; As[nb][a_k + 1][a_m + 64] = pa1.y;
            As[nb][a_k + 2][a_m + 64] = pa1.z; As[nb][a_k + 3][a_m + 64] = pa1.w;
            if (OP == 0) {
                Bs[nb][b_k4 + 0][b_n] = pb0.x; Bs[nb][b_k4 + 1][b_n] = pb0.y;
                Bs[nb][b_k4 + 2][b_n] = pb0.z; Bs[nb][b_k4 + 3][b_n] = pb0.w;
                Bs[nb][b_k4 + 0][b_n + 64] = pb1.x; Bs[nb][b_k4 + 1][b_n + 64] = pb1.y;
                Bs[nb][b_k4 + 2][b_n + 64] = pb1.z; Bs[nb][b_k4 + 3][b_n + 64] = pb1.w;
            } else {
                *(float4*)&Bs[nb][b_k][b_nq] = pb0;
                *(float4*)&Bs[nb][b_k + 8][b_nq] = pb1;
            }
            __syncthreads();
            buf = nb;
        }
    }
    #pragma unroll
    for (int r = 0; r < 8; r++) {
        int gm = m0 + ty * 8 + r;
        if (gm >= g.M) break;
        #pragma unroll
        for (int c = 0; c < 8; c++) {
            int gn = n0 + tx * 8 + c;
            g.C[(size_t)gm * g.ldc + gn] = acc[r][c] + (g.bias ? g.bias[gn] : 0.f);
        }
    }
}

// ---------------- small batched GEMM: 64x64 tile, 4x4 micro ----------------
__global__ void __launch_bounds__(256) sgemm64(GemmBatch batch)
{
    GemmDesc g = batch.d[blockIdx.z];
    int m0 = blockIdx.y * 64, n0 = blockIdx.x * 64;
    if (m0 >= g.M || n0 >= g.N) return;
    __shared__ float As[64][17];
    __shared__ float Bs[64][17];
    int tid = threadIdx.x;
    int tx = tid & 15, ty = tid >> 4;
    float acc[4][4] = {};

    for (int k0 = 0; k0 < g.K; k0 += 16) {
        if (g.op == 2) {   // A [K][M]
            #pragma unroll
            for (int i = 0; i < 4; i++) {
                int li = tid + 256 * i;
                int m = li & 63, k = li >> 6;
                int gm = m0 + m;
                As[m][k] = (gm < g.M) ? g.A[(size_t)(k0 + k) * g.lda + gm] : 0.f;
            }
        } else {           // A [M][K]
            #pragma unroll
            for (int i = 0; i < 4; i++) {
                int li = tid + 256 * i;
                int k = li & 15, m = li >> 4;
                int gm = m0 + m;
                As[m][k] = (gm < g.M) ? g.A[(size_t)gm * g.lda + k0 + k] : 0.f;
            }
        }
        if (g.op == 0) {   // B [N][K]
            #pragma unroll
            for (int i = 0; i < 4; i++) {
                int li = tid + 256 * i;
                int k = li & 15, n = li >> 4;
                int gn = n0 + n;
                Bs[n][k] = (gn < g.N) ? g.B[(size_t)gn * g.ldb + k0 + k] : 0.f;
            }
        } else {           // B [K][N]
            #pragma unroll
            for (int i = 0; i < 4; i++) {
                int li = tid + 256 * i;
                int n = li & 63, k = li >> 6;
                int gn = n0 + n;
                Bs[n][k] = (gn < g.N) ? g.B[(size_t)(k0 + k) * g.ldb + gn] : 0.f;
            }
        }
        __syncthreads();
        #pragma unroll
        for (int kk = 0; kk < 16; kk++) {
            float af[4], bf[4];
            #pragma unroll
            for (int r = 0; r < 4; r++) af[r] = As[ty * 4 + r][kk];
            #pragma unroll
            for (int c = 0; c < 4; c++) bf[c] = Bs[tx * 4 + c][kk];
            #pragma unroll
            for (int r = 0; r < 4; r++)
                #pragma unroll
                for (int c = 0; c < 4; c++)
                    acc[r][c] += af[r] * bf[c];
        }
        __syncthreads();
    }
    #pragma unroll
    for (int r = 0; r < 4; r++) {
        int gm = m0 + ty * 4 + r;
        if (gm >= g.M) continue;
        #pragma unroll
        for (int c = 0; c < 4; c++) {
            int gn = n0 + tx * 4 + c;
            if (gn < g.N)
                g.C[(size_t)gm * g.ldc + gn] = acc[r][c] + (g.bias ? g.bias[gn] : 0.f);
        }
    }
}

// ---------------- warp-parallel raw-input vectors + zero init of G ----------------
__global__ void __launch_bounds__(256) compose_small2(
    const float* __restrict__ finw, const float* __restrict__ finb,
    const float* __restrict__ fob,
    const float* __restrict__ inob, const float* __restrict__ outob,
    const float* __restrict__ W)
{
    if (blockIdx.x >= 204) {
        int i = (blockIdx.x - 204) * 256 + threadIdx.x;
        if (i < (UK * 32) / 4) ((float4*)g_G)[i] = make_float4(0.f, 0.f, 0.f, 0.f);
        return;
    }
    int gw = blockIdx.x * 8 + (threadIdx.x >> 5);
    int lane = threadIdx.x & 31;
    float acc = 0.f;
    if (gw < 1600) {
        int grp = gw / 320, j = gw - grp * 320;
        const float* row;
        const float* vec;
        float b;
        if (grp == 0)      { row = finw + (size_t)j * E_;            vec = inob;  b = finb[j]; }
        else if (grp == 1) { row = finw + (size_t)(E_ + j) * E_;     vec = inob;  b = finb[E_ + j]; }
        else if (grp == 2) { row = finw + (size_t)(E_ + j) * E_;     vec = outob; b = finb[E_ + j]; }
        else if (grp == 3) { row = finw + (size_t)(2 * E_ + j) * E_; vec = inob;  b = finb[2 * E_ + j]; }
        else               { row = finw + (size_t)(2 * E_ + j) * E_; vec = outob; b = finb[2 * E_ + j]; }
        #pragma unroll
        for (int i = 0; i < 10; i++) acc += row[lane + 32 * i] * vec[lane + 32 * i];
        #pragma unroll
        for (int o = 16; o; o >>= 1) acc += __shfl_xor_sync(0xffffffffu, acc, o);
        if (lane == 0) {
            acc += b;
            if (grp == 0)      g_cq[j] = acc;
            else if (grp == 1) g_ckin[j] = acc;
            else if (grp == 2) g_ckout[j] = acc;
            else if (grp == 3) g_cvin[j] = acc;
            else               g_cvout[j] = acc;
        }
    } else if (gw < 1632) {
        int o = gw - 1600;
        if (o < OUT_) {
            #pragma unroll
            for (int i = 0; i < 10; i++) {
                int k = lane + 32 * i;
                acc += fob[k] * W[k * OUT_ + o];
            }
        }
        #pragma unroll
        for (int oo = 16; oo; oo >>= 1) acc += __shfl_xor_sync(0xffffffffu, acc, oo);
        if (lane == 0) g_cW[o] = (o < OUT_) ? acc : 0.f;
    }
}

// ---------------- warp-parallel level-2 vectors ----------------
__global__ void __launch_bounds__(256) smallvec_kernel()
{
    int gw = blockIdx.x * 8 + (threadIdx.x >> 5);
    int lane = threadIdx.x & 31;
    float acc = 0.f;
    if (gw < 640) {                        // wv[i] = sum_j Mq[j][i] * ck[j]
        int side = gw >= 320;
        int i = gw - side * 320;
        const float* ck = side ? g_ckout : g_ckin;
        #pragma unroll
        for (int q = 0; q < 10; q++) {
            int j = lane + 32 * q;
            acc += g_Mq[(size_t)j * E_ + i] * ck[j];
        }
        #pragma unroll
        for (int o = 16; o; o >>= 1) acc += __shfl_xor_sync(0xffffffffu, acc, o);
        if (lane == 0) g_wv[gw] = acc;
    } else if (gw < 1280) {                // cqK[c] = sum_j cq[j] * MK[j][c]
        int side = gw >= 960;
        int c = gw - 640 - side * 320;
        const float* MK = side ? g_MKout : g_MKin;
        #pragma unroll
        for (int q = 0; q < 10; q++) {
            int j = lane + 32 * q;
            acc += g_cq[j] * MK[(size_t)j * E_ + c];
        }
        #pragma unroll
        for (int o = 16; o; o >>= 1) acc += __shfl_xor_sync(0xffffffffu, acc, o);
        if (lane == 0) g_cqK[side * 320 + c] = acc;
    } else if (gw < 1340) {                // G rows 640/641 = PW^T cv
        int r = gw - 1280;
        int row = r >= 30;
        int o = r - row * 30;
        const float* cv = row ? g_cvout : g_cvin;
        #pragma unroll
        for (int q = 0; q < 10; q++) {
            int c = lane + 32 * q;
            acc += cv[c] * g_PW[c * 32 + o];
        }
        #pragma unroll
        for (int oo = 16; oo; oo >>= 1) acc += __shfl_xor_sync(0xffffffffu, acc, oo);
        if (lane == 0) g_G[(640 + row) * 32 + o] = acc;
    } else if (gw < 1342) {                // wb = cq . ck
        int w = gw - 1340;
        const float* ck = w ? g_ckout : g_ckin;
        #pragma unroll
        for (int q = 0; q < 10; q++) {
            int j = lane + 32 * q;
            acc += g_cq[j] * ck[j];
        }
        #pragma unroll
        for (int o = 16; o; o >>= 1) acc += __shfl_xor_sync(0xffffffffu, acc, o);
        if (lane == 0) g_wb[w] = acc;
    }
}

// ---------------- per-node 5-head attention ----------------
__global__ void __launch_bounds__(256) attn_kernel(
    const int* __restrict__ in_idx, const int* __restrict__ out_idx,
    const float* __restrict__ in_b, const float* __restrict__ out_b)
{
    int n = blockIdx.x;
    int tid = threadIdx.x;
    extern __shared__ float sm[];
    float* Qs = sm;                 // 16*SR
    float* Ks = Qs + T_ * SR;
    float* Vs = Ks + T_ * SR;
    float* A0 = Vs + T_ * SR;       // 1280
    float* A1 = A0 + 1280;          // 1280
    __shared__ int rows[2][T_];

    if (tid < 32) {
        int s = tid >> 4, t = tid & 15;
        const int* idx = s ? out_idx : in_idx;
        rows[s][t] = t ? idx[n * D_ + t - 1] : n;
    }
    __syncthreads();

    for (int side = 0; side < 2; side++) {
        const float* bias = side ? out_b : in_b;
        int colbase = side * 960;
        for (int e = tid; e < 3840; e += 256) {
            int a = e / 1280, r = e - a * 1280;
            int t = r / 80, j = (r - t * 80) * 4;
            const float* src = g_XP + (size_t)rows[side][t] * 1920 + colbase + a * 320 + j;
            float4 v = *(const float4*)src;
            float4 bv = *(const float4*)(bias + a * 320 + j);
            v.x += bv.x; v.y += bv.y; v.z += bv.z; v.w += bv.w;
            float* dst = (a == 0 ? Qs : (a == 1 ? Ks : Vs)) + t * SR + j;
            *(float4*)dst = v;
        }
        __syncthreads();
        if (tid < 160) {
            int dh = tid & 1;
            int tile = tid >> 1;
            int h = tile >> 4, rem = tile & 15;
            int l0 = (rem >> 2) * 4, mm0 = (rem & 3) * 4;
            const float* qb = Qs + h * 64 + dh * 32;
            const float* kb = Ks + h * 64 + dh * 32;
            float acc[4][4] = {};
            #pragma unroll
            for (int d = 0; d < 32; d += 4) {
                float4 q[4], k4[4];
                #pragma unroll
                for (int r = 0; r < 4; r++) q[r] = *(const float4*)(qb + (l0 + r) * SR + d);
                #pragma unroll
                for (int c = 0; c < 4; c++) k4[c] = *(const float4*)(kb + (mm0 + c) * SR + d);
                #pragma unroll
                for (int r = 0; r < 4; r++)
                    #pragma unroll
                    for (int c = 0; c < 4; c++)
                        acc[r][c] += q[r].x * k4[c].x + q[r].y * k4[c].y
                                   + q[r].z * k4[c].z + q[r].w * k4[c].w;
            }
            float* dst = dh ? A1 : A0;
            #pragma unroll
            for (int r = 0; r < 4; r++)
                #pragma unroll
                for (int c = 0; c < 4; c++)
                    dst[(h * 16 + l0 + r) * 16 + mm0 + c] = acc[r][c];
        }
        __syncthreads();
        if (tid < 80) {
            int base = tid * 16;
            float v[16];
            float mx = -1e30f;
            #pragma unroll
            for (int m = 0; m < 16; m++) {
                v[m] = (A0[base + m] + A1[base + m]) * 0.125f;
                mx = fmaxf(mx, v[m]);
            }
            float ssum = 0.f;
            #pragma unroll
            for (int m = 0; m < 16; m++) { v[m] = __expf(v[m] - mx); ssum += v[m]; }
            float inv = 1.f / ssum;
            #pragma unroll
            for (int m = 0; m < 16; m++) A0[base + m] = v[m] * inv;
        }
        __syncthreads();
        float* ctxout = g_CTX + (size_t)n * 10240 + side * 5120;
        for (int u = tid; u < 640; u += 256) {
            int tp = u / 80;
            int j = (u - tp * 80) * 4;
            int h = j >> 6;
            int t0 = tp * 2;
            float ar0[16], ar1[16];
            #pragma unroll
            for (int q = 0; q < 4; q++) {
                *(float4*)&ar0[q * 4] = *(const float4*)&A0[(h * 16 + t0) * 16 + q * 4];
                *(float4*)&ar1[q * 4] = *(const float4*)&A0[(h * 16 + t0 + 1) * 16 + q * 4];
            }
            float4 acc0 = make_float4(0.f, 0.f, 0.f, 0.f);
            float4 acc1 = make_float4(0.f, 0.f, 0.f, 0.f);
            #pragma unroll
            for (int m = 0; m < 16; m++) {
                float4 v4 = *(const float4*)(Vs + m * SR + j);
                acc0.x += ar0[m] * v4.x; acc0.y += ar0[m] * v4.y;
                acc0.z += ar0[m] * v4.z; acc0.w += ar0[m] * v4.w;
                acc1.x += ar1[m] * v4.x; acc1.y += ar1[m] * v4.y;
                acc1.z += ar1[m] * v4.z; acc1.w += ar1[m] * v4.w;
            }
            *(float4*)(ctxout + (size_t)t0 * 320 + j) = acc0;
            *(float4*)(ctxout + (size_t)(t0 + 1) * 320 + j) = acc1;
            if (side == 0 && t0 == 0)   // compact copy of in-side token 0 for TT GEMM
                *(float4*)(g_C0 + (size_t)n * E_ + j) = acc0;
        }
        __syncthreads();
    }
}

// ---------------- final-layer scores + softmax + U (ctx staged in smem) ----------------
__global__ void __launch_bounds__(256) finscore_kernel()
{
    int n = blockIdx.x;
    int tid = threadIdx.x, lane = tid & 31, w = tid >> 5;
    extern __shared__ float fs[];
    float* Cx = fs;            // 10240: full ctx block for this node
    float* Ts = fs + 10240;    // 640
    __shared__ float sA[32];
    __shared__ float sc[2];
    __shared__ float s_sain;

    // stage ctx (2560 float4) and TT (160 float4) into smem, coalesced
    const float4* csrc = (const float4*)(g_CTX + (size_t)n * 10240);
    for (int i = tid; i < 2560; i += 256) ((float4*)Cx)[i] = csrc[i];
    const float4* tsrc = (const float4*)(g_TT + (size_t)n * 640);
    if (tid < 160) ((float4*)Ts)[tid] = tsrc[tid];
    __syncthreads();

    // 32 token score dots (from smem)
    #pragma unroll
    for (int ii = 0; ii < 4; ii++) {
        int t = w * 4 + ii;
        int side = t >> 4, tok = t & 15;
        const float* cr = Cx + side * 5120 + tok * 320;
        const float* tv = Ts + side * 320;
        float acc = 0.f;
        #pragma unroll
        for (int i = 0; i < 10; i++) acc += cr[lane + 32 * i] * tv[lane + 32 * i];
        #pragma unroll
        for (int o = 16; o; o >>= 1) acc += __shfl_xor_sync(0xffffffffu, acc, o);
        if (lane == 0) sA[t] = acc;
    }
    if (w < 2) {     // sc = ctx0 . w_side + b_side
        const float* tv = g_wv + w * 320;
        float acc = 0.f;
        #pragma unroll
        for (int i = 0; i < 10; i++) acc += Cx[lane + 32 * i] * tv[lane + 32 * i];
        #pragma unroll
        for (int o = 16; o; o >>= 1) acc += __shfl_xor_sync(0xffffffffu, acc, o);
        if (lane == 0) sc[w] = acc + g_wb[w];
    }
    __syncthreads();
    if (tid < 32) {  // softmax over 32 (scale = 320^-0.5)
        float v = (sA[tid] + sc[tid >> 4]) * 0.05590169943749474f;
        float mx = v;
        #pragma unroll
        for (int o = 16; o; o >>= 1) mx = fmaxf(mx, __shfl_xor_sync(0xffffffffu, mx, o));
        float e = __expf(v - mx);
        float ssum = e;
        #pragma unroll
        for (int o = 16; o; o >>= 1) ssum += __shfl_xor_sync(0xffffffffu, ssum, o);
        float a = e / ssum;
        sA[tid] = a;
        float ain = (tid < 16) ? a : 0.f;
        #pragma unroll
        for (int o = 16; o; o >>= 1) ain += __shfl_xor_sync(0xffffffffu, ain, o);
        if (tid == 0) s_sain = ain;
    }
    __syncthreads();
    float* urow = g_U + (size_t)n * UK;
    if (tid < 160) {          // 160 float4 columns = 640 floats (from smem)
        int side = tid >= 80;
        int off = (tid - side * 80) * 4;
        const float* cb = Cx + side * 5120;
        const float* av = sA + side * 16;
        float4 acc = make_float4(0.f, 0.f, 0.f, 0.f);
        #pragma unroll
        for (int t = 0; t < 16; t++) {
            float a = av[t];
            float4 v = *(const float4*)(cb + t * 320 + off);
            acc.x += a * v.x; acc.y += a * v.y;
            acc.z += a * v.z; acc.w += a * v.w;
        }
        *(float4*)(urow + side * 320 + off) = acc;
    } else if (tid < 164) {   // tail 640..655
        int base = 640 + (tid - 160) * 4;
        float4 v = make_float4(0.f, 0.f, 0.f, 0.f);
        if (tid == 160) { v.x = s_sain; v.y = 1.f - s_sain; }
        *(float4*)(urow + base) = v;
    }
}

// ---------------- out = elu(U @ G + cW) ----------------
__global__ void __launch_bounds__(256) outproj_kernel(float* __restrict__ out)
{
    extern __shared__ float sm2[];
    float* Gs = sm2;                 // 656*32
    float* Us = sm2 + UK * 32;       // 32*656
    int tid = threadIdx.x;
    int n0 = blockIdx.x * 32;

    for (int i = tid; i < (UK * 32) / 4; i += 256)
        ((float4*)Gs)[i] = ((const float4*)g_G)[i];
    const float* usrc = g_U + (size_t)n0 * UK;
    for (int i = tid; i < (32 * UK) / 4; i += 256)
        ((float4*)Us)[i] = ((const float4*)usrc)[i];
    __syncthreads();

    int w = tid >> 5, lane = tid & 31;
    for (int nn = w; nn < 32; nn += 8) {
        int n = n0 + nn;
        const float* ur = Us + nn * UK;
        float acc = 0.f;
        for (int i = 0; i < 642; i += 2) {
            acc += ur[i] * Gs[i * 32 + lane];
            acc += ur[i + 1] * Gs[(i + 1) * 32 + lane];
        }
        if (lane < OUT_ && n < N_NODES) {
            acc += g_cW[lane];
            out[n * OUT_ + lane] = acc > 0.f ? acc : expm1f(acc);
        }
    }
}

// ---------------- host ----------------
extern "C" void kernel_launch(void* const* d_in, const int* in_sizes, int n_in,
                              void* d_out, int out_size)
{
    const float* X         = (const float*)d_in[0];
    const int*   in_idx    = (const int*)  d_in[1];
    const int*   out_idx   = (const int*)  d_in[2];
    const float* in_Wq     = (const float*)d_in[3];
    const float* in_Wk     = (const float*)d_in[4];
    const float* in_Wv     = (const float*)d_in[5];
    const float* in_qkv_w  = (const float*)d_in[6];
    const float* in_qkv_b  = (const float*)d_in[7];
    const float* in_o_w    = (const float*)d_in[8];
    const float* in_o_b    = (const float*)d_in[9];
    const float* out_Wq    = (const float*)d_in[10];
    const float* out_Wk    = (const float*)d_in[11];
    const float* out_Wv    = (const float*)d_in[12];
    const float* out_qkv_w = (const float*)d_in[13];
    const float* out_qkv_b = (const float*)d_in[14];
    const float* out_o_w   = (const float*)d_in[15];
    const float* out_o_b   = (const float*)d_in[16];
    const float* fin_qkv_w = (const float*)d_in[17];
    const float* fin_qkv_b = (const float*)d_in[18];
    const float* fin_o_w   = (const float*)d_in[19];
    const float* fin_o_b   = (const float*)d_in[20];
    const float* Wmat      = (const float*)d_in[21];
    float* out = (float*)d_out;

    float *pMA, *pMq, *pMKin, *pMKout, *pMVin, *pMVout, *pPW, *pMqKcat, *pG,
          *pXP, *pCTX, *pC0, *pTT, *pU, *pcqK;
    cudaGetSymbolAddress((void**)&pMA, g_MA);
    cudaGetSymbolAddress((void**)&pMq, g_Mq);
    cudaGetSymbolAddress((void**)&pMKin, g_MKin);
    cudaGetSymbolAddress((void**)&pMKout, g_MKout);
    cudaGetSymbolAddress((void**)&pMVin, g_MVin);
    cudaGetSymbolAddress((void**)&pMVout, g_MVout);
    cudaGetSymbolAddress((void**)&pPW, g_PW);
    cudaGetSymbolAddress((void**)&pMqKcat, g_MqKcat);
    cudaGetSymbolAddress((void**)&pG, g_G);
    cudaGetSymbolAddress((void**)&pXP, g_XP);
    cudaGetSymbolAddress((void**)&pCTX, g_CTX);
    cudaGetSymbolAddress((void**)&pC0, g_C0);
    cudaGetSymbolAddress((void**)&pTT, g_TT);
    cudaGetSymbolAddress((void**)&pU, g_U);
    cudaGetSymbolAddress((void**)&pcqK, g_cqK);

    const int ATTN_SMEM = (3 * T_ * SR + 2 * 1280) * (int)sizeof(float);
    const int FIN_SMEM  = (10240 + 640) * (int)sizeof(float);
    const int OUT_SMEM  = (2 * UK * 32) * (int)sizeof(float);
    cudaFuncSetAttribute(attn_kernel, cudaFuncAttributeMaxDynamicSharedMemorySize, ATTN_SMEM);
    cudaFuncSetAttribute(finscore_kernel, cudaFuncAttributeMaxDynamicSharedMemorySize, FIN_SMEM);
    cudaFuncSetAttribute(outproj_kernel, cudaFuncAttributeMaxDynamicSharedMemorySize, OUT_SMEM);

    // ---- compose level 1 (batched, z=12) ----
    GemmBatch L1 = {};
    const float* Ws6[6] = {in_Wq, in_Wk, in_Wv, out_Wq, out_Wk, out_Wv};
    const float* Qw6[6] = {in_qkv_w, in_qkv_w + E_ * E_, in_qkv_w + 2 * E_ * E_,
                           out_qkv_w, out_qkv_w + E_ * E_, out_qkv_w + 2 * E_ * E_};
    for (int s = 0; s < 6; s++)
        L1.d[s] = {Qw6[s], Ws6[s], pMA + s * E_ * E_, nullptr,
                   E_, E_, E_, E_, E_, E_, 0};
    L1.d[6]  = {fin_qkv_w,               in_o_w,  pMq,    nullptr, E_, E_,  E_, E_, E_, E_, 1};
    L1.d[7]  = {fin_qkv_w + E_ * E_,     in_o_w,  pMKin,  nullptr, E_, E_,  E_, E_, E_, E_, 1};
    L1.d[8]  = {fin_qkv_w + E_ * E_,     out_o_w, pMKout, nullptr, E_, E_,  E_, E_, E_, E_, 1};
    L1.d[9]  = {fin_qkv_w + 2 * E_ * E_, in_o_w,  pMVin,  nullptr, E_, E_,  E_, E_, E_, E_, 1};
    L1.d[10] = {fin_qkv_w + 2 * E_ * E_, out_o_w, pMVout, nullptr, E_, E_,  E_, E_, E_, E_, 1};
    L1.d[11] = {fin_o_w,                 Wmat,    pPW,    nullptr, E_, OUT_, E_, E_, OUT_, 32, 2};
    sgemm64<<<dim3(5, 5, 12), 256>>>(L1);

    // ---- raw-input small vectors + zero G (warp-parallel) ----
    compose_small2<<<225, 256>>>(fin_qkv_w, fin_qkv_b, fin_o_b, in_o_b, out_o_b, Wmat);

    // ---- compose level 2 (batched, z=4) ----
    GemmBatch L2 = {};
    L2.d[0] = {pMq,    pMKin,  pMqKcat,       nullptr, E_, E_,  E_, E_, E_, 640, 2};
    L2.d[1] = {pMq,    pMKout, pMqKcat + E_,  nullptr, E_, E_,  E_, E_, E_, 640, 2};
    L2.d[2] = {pMVin,  pPW,    pG,            nullptr, E_, OUT_, E_, E_, 32, 32, 2};
    L2.d[3] = {pMVout, pPW,    pG + E_ * 32,  nullptr, E_, OUT_, E_, E_, 32, 32, 2};
    sgemm64<<<dim3(5, 5, 4), 256>>>(L2);

    // ---- level-2 vectors (warp-parallel) ----
    smallvec_kernel<<<168, 256>>>();

    // ---- XP = X @ MA^T ----
    GemmDesc xp = {X, pMA, pXP, nullptr, N_NODES, 1920, E_, E_, E_, 1920, 0};
    sgemm128<0><<<dim3(15, 79), 256>>>(xp);

    // ---- per-node attention ----
    attn_kernel<<<N_NODES, 256, ATTN_SMEM>>>(in_idx, out_idx, in_qkv_b, out_qkv_b);

    // ---- [Tin|Tout] = C0 @ MqKcat + cqK ----
    GemmDesc tt = {pC0, pMqKcat, pTT, pcqK, N_NODES, 640, E_, E_, 640, 640, 1};
    sgemm128<1><<<dim3(5, 79), 256>>>(tt);

    // ---- final scores + softmax + U ----
    finscore_kernel<<<N_NODES, 256, FIN_SMEM>>>();

    // ---- out = elu(U @ G + cW) ----
    outproj_kernel<<<(N_NODES + 31) / 32, 256, OUT_SMEM>>>(out);
}

// round 10
// speedup vs baseline: 1.0466x; 1.0466x over previous
#include <cuda_runtime.h>
#include <cstdint>
#include <cstddef>

#define N_NODES 10000
#define E_ 320
#define D_ 15
#define T_ 16
#define OUT_ 30
#define UK 656
#define SR 324

// ---------------- scratch (device globals) ----------------
__device__ float g_MA[6 * E_ * E_];        // composed QKV mats [1920][320]
__device__ float g_Mq[E_ * E_];
__device__ float g_MKin[E_ * E_];
__device__ float g_MKout[E_ * E_];
__device__ float g_MVin[E_ * E_];
__device__ float g_MVout[E_ * E_];
__device__ float g_PW[E_ * 32];            // fo_w^T @ W, padded to 32 cols
__device__ float g_MqKcat[E_ * 640];       // [320][640] = [Mq^T MKin | Mq^T MKout]
__device__ float g_G[UK * 32];             // [656][32] out-projection matrix
__device__ float g_cq[E_];
__device__ float g_ckin[E_];
__device__ float g_ckout[E_];
__device__ float g_cvin[E_];
__device__ float g_cvout[E_];
__device__ float g_cW[32];
__device__ float g_wv[640];                // [win | wout]
__device__ float g_wb[2];                  // bin, bout
__device__ float g_cqK[640];               // [cq@MKin | cq@MKout]
__device__ float g_XP[(size_t)N_NODES * 1920];
__device__ float g_CTX[(size_t)N_NODES * 10240];
__device__ float g_C0[(size_t)N_NODES * E_];   // compact copy of in-side ctx token 0
__device__ float g_TT[(size_t)N_NODES * 640];
__device__ float g_U[(size_t)(N_NODES + 32) * UK];

struct GemmDesc {
    const float* A; const float* B; float* C; const float* bias;
    int M, N, K, lda, ldb, ldc, op;  // op: 0=NT, 1=NN, 2=TN
};
struct GemmBatch { GemmDesc d[12]; };

// ---------------- big GEMM: 128x128 tile, 8x8 micro, double-buffered ----------------
template <int OP>
__global__ void __launch_bounds__(256) sgemm128(GemmDesc g)
{
    __shared__ float As[2][16][132];
    __shared__ float Bs[2][16][132];
    int tid = threadIdx.x;
    int tx = tid & 15, ty = tid >> 4;
    int m0 = blockIdx.y * 128, n0 = blockIdx.x * 128;
    float acc[8][8] = {};

    int a_m = tid >> 2, a_k = (tid & 3) << 2;
    bool a0ok = (m0 + a_m) < g.M;
    bool a1ok = (m0 + a_m + 64) < g.M;
    const float* Ar0 = g.A + (size_t)(m0 + a_m) * g.lda + a_k;
    const float* Ar1 = g.A + (size_t)(m0 + a_m + 64) * g.lda + a_k;
    int b_n = tid >> 2, b_k4 = (tid & 3) << 2;   // OP==0
    int b_k = tid >> 5, b_nq = (tid & 31) << 2;  // OP==1
    const float* Br0;
    const float* Br1;
    if (OP == 0) {
        Br0 = g.B + (size_t)(n0 + b_n) * g.ldb + b_k4;
        Br1 = g.B + (size_t)(n0 + b_n + 64) * g.ldb + b_k4;
    } else {
        Br0 = g.B + (size_t)b_k * g.ldb + n0 + b_nq;
        Br1 = g.B + (size_t)(b_k + 8) * g.ldb + n0 + b_nq;
    }

    const float4 fz = make_float4(0.f, 0.f, 0.f, 0.f);
    float4 pa0 = a0ok ? *(const float4*)Ar0 : fz;
    float4 pa1 = a1ok ? *(const float4*)Ar1 : fz;
    float4 pb0 = *(const float4*)Br0;
    float4 pb1 = *(const float4*)Br1;

    As[0][a_k + 0][a_m] = pa0.x; As[0][a_k + 1][a_m] = pa0.y;
    As[0][a_k + 2][a_m] = pa0.z; As[0][a_k + 3][a_m] = pa0.w;
    As[0][a_k + 0][a_m + 64] = pa1.x; As[0][a_k + 1][a_m + 64] = pa1.y;
    As[0][a_k + 2][a_m + 64] = pa1.z; As[0][a_k + 3][a_m + 64] = pa1.w;
    if (OP == 0) {
        Bs[0][b_k4 + 0][b_n] = pb0.x; Bs[0][b_k4 + 1][b_n] = pb0.y;
        Bs[0][b_k4 + 2][b_n] = pb0.z; Bs[0][b_k4 + 3][b_n] = pb0.w;
        Bs[0][b_k4 + 0][b_n + 64] = pb1.x; Bs[0][b_k4 + 1][b_n + 64] = pb1.y;
        Bs[0][b_k4 + 2][b_n + 64] = pb1.z; Bs[0][b_k4 + 3][b_n + 64] = pb1.w;
    } else {
        *(float4*)&Bs[0][b_k][b_nq] = pb0;
        *(float4*)&Bs[0][b_k + 8][b_nq] = pb1;
    }
    __syncthreads();

    int buf = 0;
    for (int k0 = 0; k0 < g.K; k0 += 16) {
        bool nxt = (k0 + 16) < g.K;
        if (nxt) {
            int ko = k0 + 16;
            pa0 = a0ok ? *(const float4*)(Ar0 + ko) : fz;
            pa1 = a1ok ? *(const float4*)(Ar1 + ko) : fz;
            if (OP == 0) {
                pb0 = *(const float4*)(Br0 + ko);
                pb1 = *(const float4*)(Br1 + ko);
            } else {
                pb0 = *(const float4*)(Br0 + (size_t)ko * g.ldb);
                pb1 = *(const float4*)(Br1 + (size_t)ko * g.ldb);
            }
        }
        #pragma unroll
        for (int kk = 0; kk < 16; kk++) {
            float a[8], b[8];
            *(float4*)&a[0] = *(float4*)&As[buf][kk][ty * 8];
            *(float4*)&a[4] = *(float4*)&As[buf][kk][ty * 8 + 4];
            *(float4*)&b[0] = *(float4*)&Bs[buf][kk][tx * 8];
            *(float4*)&b[4] = *(float4*)&Bs[buf][kk][tx * 8 + 4];
            #pragma unroll
            for (int r = 0; r < 8; r++)
                #pragma unroll
                for (int c = 0; c < 8; c++)
                    acc[r][c] += a[r] * b[c];
        }
        if (nxt) {
            int nb = buf ^ 1;
            As[nb][a_k + 0][a_m] = pa0.x; As[nb][a_k + 1][a_m] = pa0.y;
            As[nb][a_k + 2][a_m] = pa0.z; As[nb][a_k + 3][a_m] = pa0.w;
            As[nb][a_k + 0][a_m + 64] = pa1.x; As[nb][a_k + 1][a_m + 64] = pa1.y;
            As[nb][a_k + 2][a_m + 64] = pa1.z; As[nb][a_k + 3][a_m + 64] = pa1.w;
            if (OP == 0) {
                Bs[nb][b_k4 + 0][b_n] = pb0.x; Bs[nb][b_k4 + 1][b_n] = pb0.y;
                Bs[nb][b_k4 + 2][b_n] = pb0.z; Bs[nb][b_k4 + 3][b_n] = pb0.w;
                Bs[nb][b_k4 + 0][b_n + 64] = pb1.x; Bs[nb][b_k4 + 1][b_n + 64] = pb1.y;
                Bs[nb][b_k4 + 2][b_n + 64] = pb1.z; Bs[nb][b_k4 + 3][b_n + 64] = pb1.w;
            } else {
                *(float4*)&Bs[nb][b_k][b_nq] = pb0;
                *(float4*)&Bs[nb][b_k + 8][b_nq] = pb1;
            }
            __syncthreads();
            buf = nb;
        }
    }
    #pragma unroll
    for (int r = 0; r < 8; r++) {
        int gm = m0 + ty * 8 + r;
        if (gm >= g.M) break;
        #pragma unroll
        for (int c = 0; c < 8; c++) {
            int gn = n0 + tx * 8 + c;
            g.C[(size_t)gm * g.ldc + gn] = acc[r][c] + (g.bias ? g.bias[gn] : 0.f);
        }
    }
}

// ---------------- small batched GEMM: 64x64 tile, 4x4 micro ----------------
__global__ void __launch_bounds__(256) sgemm64(GemmBatch batch)
{
    GemmDesc g = batch.d[blockIdx.z];
    int m0 = blockIdx.y * 64, n0 = blockIdx.x * 64;
    if (m0 >= g.M || n0 >= g.N) return;
    __shared__ float As[64][17];
    __shared__ float Bs[64][17];
    int tid = threadIdx.x;
    int tx = tid & 15, ty = tid >> 4;
    float acc[4][4] = {};

    for (int k0 = 0; k0 < g.K; k0 += 16) {
        if (g.op == 2) {   // A [K][M]
            #pragma unroll
            for (int i = 0; i < 4; i++) {
                int li = tid + 256 * i;
                int m = li & 63, k = li >> 6;
                int gm = m0 + m;
                As[m][k] = (gm < g.M) ? g.A[(size_t)(k0 + k) * g.lda + gm] : 0.f;
            }
        } else {           // A [M][K]
            #pragma unroll
            for (int i = 0; i < 4; i++) {
                int li = tid + 256 * i;
                int k = li & 15, m = li >> 4;
                int gm = m0 + m;
                As[m][k] = (gm < g.M) ? g.A[(size_t)gm * g.lda + k0 + k] : 0.f;
            }
        }
        if (g.op == 0) {   // B [N][K]
            #pragma unroll
            for (int i = 0; i < 4; i++) {
                int li = tid + 256 * i;
                int k = li & 15, n = li >> 4;
                int gn = n0 + n;
                Bs[n][k] = (gn < g.N) ? g.B[(size_t)gn * g.ldb + k0 + k] : 0.f;
            }
        } else {           // B [K][N]
            #pragma unroll
            for (int i = 0; i < 4; i++) {
                int li = tid + 256 * i;
                int n = li & 63, k = li >> 6;
                int gn = n0 + n;
                Bs[n][k] = (gn < g.N) ? g.B[(size_t)(k0 + k) * g.ldb + gn] : 0.f;
            }
        }
        __syncthreads();
        #pragma unroll
        for (int kk = 0; kk < 16; kk++) {
            float af[4], bf[4];
            #pragma unroll
            for (int r = 0; r < 4; r++) af[r] = As[ty * 4 + r][kk];
            #pragma unroll
            for (int c = 0; c < 4; c++) bf[c] = Bs[tx * 4 + c][kk];
            #pragma unroll
            for (int r = 0; r < 4; r++)
                #pragma unroll
                for (int c = 0; c < 4; c++)
                    acc[r][c] += af[r] * bf[c];
        }
        __syncthreads();
    }
    #pragma unroll
    for (int r = 0; r < 4; r++) {
        int gm = m0 + ty * 4 + r;
        if (gm >= g.M) continue;
        #pragma unroll
        for (int c = 0; c < 4; c++) {
            int gn = n0 + tx * 4 + c;
            if (gn < g.N)
                g.C[(size_t)gm * g.ldc + gn] = acc[r][c] + (g.bias ? g.bias[gn] : 0.f);
        }
    }
}

// ---------------- warp-parallel raw-input vectors + zero init of G ----------------
__global__ void __launch_bounds__(256) compose_small2(
    const float* __restrict__ finw, const float* __restrict__ finb,
    const float* __restrict__ fob,
    const float* __restrict__ inob, const float* __restrict__ outob,
    const float* __restrict__ W)
{
    if (blockIdx.x >= 204) {
        int i = (blockIdx.x - 204) * 256 + threadIdx.x;
        if (i < (UK * 32) / 4) ((float4*)g_G)[i] = make_float4(0.f, 0.f, 0.f, 0.f);
        return;
    }
    int gw = blockIdx.x * 8 + (threadIdx.x >> 5);
    int lane = threadIdx.x & 31;
    float acc = 0.f;
    if (gw < 1600) {
        int grp = gw / 320, j = gw - grp * 320;
        const float* row;
        const float* vec;
        float b;
        if (grp == 0)      { row = finw + (size_t)j * E_;            vec = inob;  b = finb[j]; }
        else if (grp == 1) { row = finw + (size_t)(E_ + j) * E_;     vec = inob;  b = finb[E_ + j]; }
        else if (grp == 2) { row = finw + (size_t)(E_ + j) * E_;     vec = outob; b = finb[E_ + j]; }
        else if (grp == 3) { row = finw + (size_t)(2 * E_ + j) * E_; vec = inob;  b = finb[2 * E_ + j]; }
        else               { row = finw + (size_t)(2 * E_ + j) * E_; vec = outob; b = finb[2 * E_ + j]; }
        #pragma unroll
        for (int i = 0; i < 10; i++) acc += row[lane + 32 * i] * vec[lane + 32 * i];
        #pragma unroll
        for (int o = 16; o; o >>= 1) acc += __shfl_xor_sync(0xffffffffu, acc, o);
        if (lane == 0) {
            acc += b;
            if (grp == 0)      g_cq[j] = acc;
            else if (grp == 1) g_ckin[j] = acc;
            else if (grp == 2) g_ckout[j] = acc;
            else if (grp == 3) g_cvin[j] = acc;
            else               g_cvout[j] = acc;
        }
    } else if (gw < 1632) {
        int o = gw - 1600;
        if (o < OUT_) {
            #pragma unroll
            for (int i = 0; i < 10; i++) {
                int k = lane + 32 * i;
                acc += fob[k] * W[k * OUT_ + o];
            }
        }
        #pragma unroll
        for (int oo = 16; oo; oo >>= 1) acc += __shfl_xor_sync(0xffffffffu, acc, oo);
        if (lane == 0) g_cW[o] = (o < OUT_) ? acc : 0.f;
    }
}

// ---------------- warp-parallel level-2 vectors ----------------
__global__ void __launch_bounds__(256) smallvec_kernel()
{
    int gw = blockIdx.x * 8 + (threadIdx.x >> 5);
    int lane = threadIdx.x & 31;
    float acc = 0.f;
    if (gw < 640) {                        // wv[i] = sum_j Mq[j][i] * ck[j]
        int side = gw >= 320;
        int i = gw - side * 320;
        const float* ck = side ? g_ckout : g_ckin;
        #pragma unroll
        for (int q = 0; q < 10; q++) {
            int j = lane + 32 * q;
            acc += g_Mq[(size_t)j * E_ + i] * ck[j];
        }
        #pragma unroll
        for (int o = 16; o; o >>= 1) acc += __shfl_xor_sync(0xffffffffu, acc, o);
        if (lane == 0) g_wv[gw] = acc;
    } else if (gw < 1280) {                // cqK[c] = sum_j cq[j] * MK[j][c]
        int side = gw >= 960;
        int c = gw - 640 - side * 320;
        const float* MK = side ? g_MKout : g_MKin;
        #pragma unroll
        for (int q = 0; q < 10; q++) {
            int j = lane + 32 * q;
            acc += g_cq[j] * MK[(size_t)j * E_ + c];
        }
        #pragma unroll
        for (int o = 16; o; o >>= 1) acc += __shfl_xor_sync(0xffffffffu, acc, o);
        if (lane == 0) g_cqK[side * 320 + c] = acc;
    } else if (gw < 1340) {                // G rows 640/641 = PW^T cv
        int r = gw - 1280;
        int row = r >= 30;
        int o = r - row * 30;
        const float* cv = row ? g_cvout : g_cvin;
        #pragma unroll
        for (int q = 0; q < 10; q++) {
            int c = lane + 32 * q;
            acc += cv[c] * g_PW[c * 32 + o];
        }
        #pragma unroll
        for (int oo = 16; oo; oo >>= 1) acc += __shfl_xor_sync(0xffffffffu, acc, oo);
        if (lane == 0) g_G[(640 + row) * 32 + o] = acc;
    } else if (gw < 1342) {                // wb = cq . ck
        int w = gw - 1340;
        const float* ck = w ? g_ckout : g_ckin;
        #pragma unroll
        for (int q = 0; q < 10; q++) {
            int j = lane + 32 * q;
            acc += g_cq[j] * ck[j];
        }
        #pragma unroll
        for (int o = 16; o; o >>= 1) acc += __shfl_xor_sync(0xffffffffu, acc, o);
        if (lane == 0) g_wb[w] = acc;
    }
}

// ---------------- per-node 5-head attention (R6 form: plain stores) ----------------
__global__ void __launch_bounds__(256) attn_kernel(
    const int* __restrict__ in_idx, const int* __restrict__ out_idx,
    const float* __restrict__ in_b, const float* __restrict__ out_b)
{
    int n = blockIdx.x;
    int tid = threadIdx.x;
    extern __shared__ float sm[];
    float* Qs = sm;                 // 16*SR
    float* Ks = Qs + T_ * SR;
    float* Vs = Ks + T_ * SR;
    float* A0 = Vs + T_ * SR;       // 1280
    float* A1 = A0 + 1280;          // 1280
    __shared__ int rows[2][T_];

    if (tid < 32) {
        int s = tid >> 4, t = tid & 15;
        const int* idx = s ? out_idx : in_idx;
        rows[s][t] = t ? idx[n * D_ + t - 1] : n;
    }
    __syncthreads();

    for (int side = 0; side < 2; side++) {
        const float* bias = side ? out_b : in_b;
        int colbase = side * 960;
        for (int e = tid; e < 3840; e += 256) {
            int a = e / 1280, r = e - a * 1280;
            int t = r / 80, j = (r - t * 80) * 4;
            const float* src = g_XP + (size_t)rows[side][t] * 1920 + colbase + a * 320 + j;
            float4 v = *(const float4*)src;
            float4 bv = *(const float4*)(bias + a * 320 + j);
            v.x += bv.x; v.y += bv.y; v.z += bv.z; v.w += bv.w;
            float* dst = (a == 0 ? Qs : (a == 1 ? Ks : Vs)) + t * SR + j;
            *(float4*)dst = v;
        }
        __syncthreads();
        if (tid < 160) {
            int dh = tid & 1;
            int tile = tid >> 1;
            int h = tile >> 4, rem = tile & 15;
            int l0 = (rem >> 2) * 4, mm0 = (rem & 3) * 4;
            const float* qb = Qs + h * 64 + dh * 32;
            const float* kb = Ks + h * 64 + dh * 32;
            float acc[4][4] = {};
            #pragma unroll
            for (int d = 0; d < 32; d += 4) {
                float4 q[4], k4[4];
                #pragma unroll
                for (int r = 0; r < 4; r++) q[r] = *(const float4*)(qb + (l0 + r) * SR + d);
                #pragma unroll
                for (int c = 0; c < 4; c++) k4[c] = *(const float4*)(kb + (mm0 + c) * SR + d);
                #pragma unroll
                for (int r = 0; r < 4; r++)
                    #pragma unroll
                    for (int c = 0; c < 4; c++)
                        acc[r][c] += q[r].x * k4[c].x + q[r].y * k4[c].y
                                   + q[r].z * k4[c].z + q[r].w * k4[c].w;
            }
            float* dst = dh ? A1 : A0;
            #pragma unroll
            for (int r = 0; r < 4; r++)
                #pragma unroll
                for (int c = 0; c < 4; c++)
                    dst[(h * 16 + l0 + r) * 16 + mm0 + c] = acc[r][c];
        }
        __syncthreads();
        if (tid < 80) {
            int base = tid * 16;
            float v[16];
            float mx = -1e30f;
            #pragma unroll
            for (int m = 0; m < 16; m++) {
                v[m] = (A0[base + m] + A1[base + m]) * 0.125f;
                mx = fmaxf(mx, v[m]);
            }
            float ssum = 0.f;
            #pragma unroll
            for (int m = 0; m < 16; m++) { v[m] = __expf(v[m] - mx); ssum += v[m]; }
            float inv = 1.f / ssum;
            #pragma unroll
            for (int m = 0; m < 16; m++) A0[base + m] = v[m] * inv;
        }
        __syncthreads();
        float* ctxout = g_CTX + (size_t)n * 10240 + side * 5120;
        for (int u = tid; u < 640; u += 256) {
            int tp = u / 80;
            int j = (u - tp * 80) * 4;
            int h = j >> 6;
            int t0 = tp * 2;
            float ar0[16], ar1[16];
            #pragma unroll
            for (int q = 0; q < 4; q++) {
                *(float4*)&ar0[q * 4] = *(const float4*)&A0[(h * 16 + t0) * 16 + q * 4];
                *(float4*)&ar1[q * 4] = *(const float4*)&A0[(h * 16 + t0 + 1) * 16 + q * 4];
            }
            float4 acc0 = make_float4(0.f, 0.f, 0.f, 0.f);
            float4 acc1 = make_float4(0.f, 0.f, 0.f, 0.f);
            #pragma unroll
            for (int m = 0; m < 16; m++) {
                float4 v4 = *(const float4*)(Vs + m * SR + j);
                acc0.x += ar0[m] * v4.x; acc0.y += ar0[m] * v4.y;
                acc0.z += ar0[m] * v4.z; acc0.w += ar0[m] * v4.w;
                acc1.x += ar1[m] * v4.x; acc1.y += ar1[m] * v4.y;
                acc1.z += ar1[m] * v4.z; acc1.w += ar1[m] * v4.w;
            }
            *(float4*)(ctxout + (size_t)t0 * 320 + j) = acc0;
            *(float4*)(ctxout + (size_t)(t0 + 1) * 320 + j) = acc1;
            if (side == 0 && t0 == 0)   // compact copy of in-side token 0 for TT GEMM
                *(float4*)(g_C0 + (size_t)n * E_ + j) = acc0;
        }
        __syncthreads();
    }
}

// ---------------- final-layer scores + softmax + U (R6 form: L2-served CTX) ----------------
__global__ void __launch_bounds__(256) finscore_kernel()
{
    int n = blockIdx.x;
    int tid = threadIdx.x, lane = tid & 31, w = tid >> 5;
    __shared__ float Ts[640];
    __shared__ float sA[32];
    __shared__ float sc[2];
    __shared__ float s_sain;
    const float* ctxn = g_CTX + (size_t)n * 10240;

    for (int i = tid; i < 640; i += 256) Ts[i] = g_TT[(size_t)n * 640 + i];
    __syncthreads();
    #pragma unroll
    for (int ii = 0; ii < 4; ii++) {
        int t = w * 4 + ii;
        int side = t >> 4, tok = t & 15;
        const float* cr = ctxn + side * 5120 + tok * 320;
        const float* tv = Ts + side * 320;
        float acc = 0.f;
        #pragma unroll
        for (int i = 0; i < 10; i++) acc += cr[lane + 32 * i] * tv[lane + 32 * i];
        #pragma unroll
        for (int o = 16; o; o >>= 1) acc += __shfl_xor_sync(0xffffffffu, acc, o);
        if (lane == 0) sA[t] = acc;
    }
    if (w < 2) {     // sc = ctx0 . w_side + b_side
        const float* cr = ctxn;
        const float* tv = g_wv + w * 320;
        float acc = 0.f;
        #pragma unroll
        for (int i = 0; i < 10; i++) acc += cr[lane + 32 * i] * tv[lane + 32 * i];
        #pragma unroll
        for (int o = 16; o; o >>= 1) acc += __shfl_xor_sync(0xffffffffu, acc, o);
        if (lane == 0) sc[w] = acc + g_wb[w];
    }
    __syncthreads();
    if (tid < 32) {  // softmax over 32 (scale = 320^-0.5)
        float v = (sA[tid] + sc[tid >> 4]) * 0.05590169943749474f;
        float mx = v;
        #pragma unroll
        for (int o = 16; o; o >>= 1) mx = fmaxf(mx, __shfl_xor_sync(0xffffffffu, mx, o));
        float e = __expf(v - mx);
        float ssum = e;
        #pragma unroll
        for (int o = 16; o; o >>= 1) ssum += __shfl_xor_sync(0xffffffffu, ssum, o);
        float a = e / ssum;
        sA[tid] = a;
        float ain = (tid < 16) ? a : 0.f;
        #pragma unroll
        for (int o = 16; o; o >>= 1) ain += __shfl_xor_sync(0xffffffffu, ain, o);
        if (tid == 0) s_sain = ain;
    }
    __syncthreads();
    float sain = s_sain;
    float* urow = g_U + (size_t)n * UK;
    if (tid < 160) {          // 160 float4 columns = 640 floats
        int side = tid >= 80;
        int off = (tid - side * 80) * 4;
        const float* cb = ctxn + side * 5120;
        const float* av = sA + side * 16;
        float4 acc = make_float4(0.f, 0.f, 0.f, 0.f);
        #pragma unroll
        for (int t = 0; t < 16; t++) {
            float a = av[t];
            float4 v = *(const float4*)(cb + t * 320 + off);
            acc.x += a * v.x; acc.y += a * v.y;
            acc.z += a * v.z; acc.w += a * v.w;
        }
        *(float4*)(urow + side * 320 + off) = acc;
    } else if (tid < 164) {   // tail 640..655
        int base = 640 + (tid - 160) * 4;
        float4 v = make_float4(0.f, 0.f, 0.f, 0.f);
        if (tid == 160) { v.x = sain; v.y = 1.f - sain; }
        *(float4*)(urow + base) = v;
    }
}

// ---------------- out = elu(U @ G + cW), 4 nodes per warp ----------------
__global__ void __launch_bounds__(256) outproj_kernel(float* __restrict__ out)
{
    extern __shared__ float sm2[];
    float* Gs = sm2;                 // 656*32
    float* Us = sm2 + UK * 32;       // 32*656
    int tid = threadIdx.x;
    int n0 = blockIdx.x * 32;

    for (int i = tid; i < (UK * 32) / 4; i += 256)
        ((float4*)Gs)[i] = ((const float4*)g_G)[i];
    const float* usrc = g_U + (size_t)n0 * UK;
    for (int i = tid; i < (32 * UK) / 4; i += 256)
        ((float4*)Us)[i] = ((const float4*)usrc)[i];
    __syncthreads();

    int w = tid >> 5, lane = tid & 31;
    // warp w handles nodes w*4 .. w*4+3; G loads shared across the 4 nodes
    const float* ur0 = Us + (w * 4 + 0) * UK;
    const float* ur1 = Us + (w * 4 + 1) * UK;
    const float* ur2 = Us + (w * 4 + 2) * UK;
    const float* ur3 = Us + (w * 4 + 3) * UK;
    float a0 = 0.f, a1 = 0.f, a2 = 0.f, a3 = 0.f;
    for (int i = 0; i < UK; i += 4) {
        float g0 = Gs[(i + 0) * 32 + lane];
        float g1 = Gs[(i + 1) * 32 + lane];
        float g2 = Gs[(i + 2) * 32 + lane];
        float g3 = Gs[(i + 3) * 32 + lane];
        float4 u0 = *(const float4*)(ur0 + i);
        float4 u1 = *(const float4*)(ur1 + i);
        float4 u2 = *(const float4*)(ur2 + i);
        float4 u3 = *(const float4*)(ur3 + i);
        a0 += u0.x * g0 + u0.y * g1 + u0.z * g2 + u0.w * g3;
        a1 += u1.x * g0 + u1.y * g1 + u1.z * g2 + u1.w * g3;
        a2 += u2.x * g0 + u2.y * g1 + u2.z * g2 + u2.w * g3;
        a3 += u3.x * g0 + u3.y * g1 + u3.z * g2 + u3.w * g3;
    }
    if (lane < OUT_) {
        float cw = g_cW[lane];
        int n = n0 + w * 4;
        float r0 = a0 + cw, r1 = a1 + cw, r2 = a2 + cw, r3 = a3 + cw;
        if (n + 0 < N_NODES) out[(n + 0) * OUT_ + lane] = r0 > 0.f ? r0 : expm1f(r0);
        if (n + 1 < N_NODES) out[(n + 1) * OUT_ + lane] = r1 > 0.f ? r1 : expm1f(r1);
        if (n + 2 < N_NODES) out[(n + 2) * OUT_ + lane] = r2 > 0.f ? r2 : expm1f(r2);
        if (n + 3 < N_NODES) out[(n + 3) * OUT_ + lane] = r3 > 0.f ? r3 : expm1f(r3);
    }
}

// ---------------- host ----------------
extern "C" void kernel_launch(void* const* d_in, const int* in_sizes, int n_in,
                              void* d_out, int out_size)
{
    const float* X         = (const float*)d_in[0];
    const int*   in_idx    = (const int*)  d_in[1];
    const int*   out_idx   = (const int*)  d_in[2];
    const float* in_Wq     = (const float*)d_in[3];
    const float* in_Wk     = (const float*)d_in[4];
    const float* in_Wv     = (const float*)d_in[5];
    const float* in_qkv_w  = (const float*)d_in[6];
    const float* in_qkv_b  = (const float*)d_in[7];
    const float* in_o_w    = (const float*)d_in[8];
    const float* in_o_b    = (const float*)d_in[9];
    const float* out_Wq    = (const float*)d_in[10];
    const float* out_Wk    = (const float*)d_in[11];
    const float* out_Wv    = (const float*)d_in[12];
    const float* out_qkv_w = (const float*)d_in[13];
    const float* out_qkv_b = (const float*)d_in[14];
    const float* out_o_w   = (const float*)d_in[15];
    const float* out_o_b   = (const float*)d_in[16];
    const float* fin_qkv_w = (const float*)d_in[17];
    const float* fin_qkv_b = (const float*)d_in[18];
    const float* fin_o_w   = (const float*)d_in[19];
    const float* fin_o_b   = (const float*)d_in[20];
    const float* Wmat      = (const float*)d_in[21];
    float* out = (float*)d_out;

    float *pMA, *pMq, *pMKin, *pMKout, *pMVin, *pMVout, *pPW, *pMqKcat, *pG,
          *pXP, *pCTX, *pC0, *pTT, *pU, *pcqK;
    cudaGetSymbolAddress((void**)&pMA, g_MA);
    cudaGetSymbolAddress((void**)&pMq, g_Mq);
    cudaGetSymbolAddress((void**)&pMKin, g_MKin);
    cudaGetSymbolAddress((void**)&pMKout, g_MKout);
    cudaGetSymbolAddress((void**)&pMVin, g_MVin);
    cudaGetSymbolAddress((void**)&pMVout, g_MVout);
    cudaGetSymbolAddress((void**)&pPW, g_PW);
    cudaGetSymbolAddress((void**)&pMqKcat, g_MqKcat);
    cudaGetSymbolAddress((void**)&pG, g_G);
    cudaGetSymbolAddress((void**)&pXP, g_XP);
    cudaGetSymbolAddress((void**)&pCTX, g_CTX);
    cudaGetSymbolAddress((void**)&pC0, g_C0);
    cudaGetSymbolAddress((void**)&pTT, g_TT);
    cudaGetSymbolAddress((void**)&pU, g_U);
    cudaGetSymbolAddress((void**)&pcqK, g_cqK);

    const int ATTN_SMEM = (3 * T_ * SR + 2 * 1280) * (int)sizeof(float);
    const int OUT_SMEM  = (2 * UK * 32) * (int)sizeof(float);
    cudaFuncSetAttribute(attn_kernel, cudaFuncAttributeMaxDynamicSharedMemorySize, ATTN_SMEM);
    cudaFuncSetAttribute(outproj_kernel, cudaFuncAttributeMaxDynamicSharedMemorySize, OUT_SMEM);

    // ---- launch 0: compose level 1 (batched, z=12) ----
    GemmBatch L1 = {};
    const float* Ws6[6] = {in_Wq, in_Wk, in_Wv, out_Wq, out_Wk, out_Wv};
    const float* Qw6[6] = {in_qkv_w, in_qkv_w + E_ * E_, in_qkv_w + 2 * E_ * E_,
                           out_qkv_w, out_qkv_w + E_ * E_, out_qkv_w + 2 * E_ * E_};
    for (int s = 0; s < 6; s++)
        L1.d[s] = {Qw6[s], Ws6[s], pMA + s * E_ * E_, nullptr,
                   E_, E_, E_, E_, E_, E_, 0};
    L1.d[6]  = {fin_qkv_w,               in_o_w,  pMq,    nullptr, E_, E_,  E_, E_, E_, E_, 1};
    L1.d[7]  = {fin_qkv_w + E_ * E_,     in_o_w,  pMKin,  nullptr, E_, E_,  E_, E_, E_, E_, 1};
    L1.d[8]  = {fin_qkv_w + E_ * E_,     out_o_w, pMKout, nullptr, E_, E_,  E_, E_, E_, E_, 1};
    L1.d[9]  = {fin_qkv_w + 2 * E_ * E_, in_o_w,  pMVin,  nullptr, E_, E_,  E_, E_, E_, E_, 1};
    L1.d[10] = {fin_qkv_w + 2 * E_ * E_, out_o_w, pMVout, nullptr, E_, E_,  E_, E_, E_, E_, 1};
    L1.d[11] = {fin_o_w,                 Wmat,    pPW,    nullptr, E_, OUT_, E_, E_, OUT_, 32, 2};
    sgemm64<<<dim3(5, 5, 12), 256>>>(L1);

    // ---- launch 1: raw-input small vectors + zero G ----
    compose_small2<<<225, 256>>>(fin_qkv_w, fin_qkv_b, fin_o_b, in_o_b, out_o_b, Wmat);

    // ---- launch 2: compose level 2 (batched, z=4) ----
    GemmBatch L2 = {};
    L2.d[0] = {pMq,    pMKin,  pMqKcat,       nullptr, E_, E_,  E_, E_, E_, 640, 2};
    L2.d[1] = {pMq,    pMKout, pMqKcat + E_,  nullptr, E_, E_,  E_, E_, E_, 640, 2};
    L2.d[2] = {pMVin,  pPW,    pG,            nullptr, E_, OUT_, E_, E_, 32, 32, 2};
    L2.d[3] = {pMVout, pPW,    pG + E_ * 32,  nullptr, E_, OUT_, E_, E_, 32, 32, 2};
    sgemm64<<<dim3(5, 5, 4), 256>>>(L2);

    // ---- launch 3 (ncu capture slot): XP = X @ MA^T (needs only L1) ----
    GemmDesc xp = {X, pMA, pXP, nullptr, N_NODES, 1920, E_, E_, E_, 1920, 0};
    sgemm128<0><<<dim3(15, 79), 256>>>(xp);

    // ---- launch 4: level-2 vectors (needed before TT/finscore only) ----
    smallvec_kernel<<<168, 256>>>();

    // ---- launch 5: per-node attention ----
    attn_kernel<<<N_NODES, 256, ATTN_SMEM>>>(in_idx, out_idx, in_qkv_b, out_qkv_b);

    // ---- launch 6: [Tin|Tout] = C0 @ MqKcat + cqK ----
    GemmDesc tt = {pC0, pMqKcat, pTT, pcqK, N_NODES, 640, E_, E_, 640, 640, 1};
    sgemm128<1><<<dim3(5, 79), 256>>>(tt);

    // ---- launch 7: final scores + softmax + U ----
    finscore_kernel<<<N_NODES, 256>>>();

    // ---- launch 8: out = elu(U @ G + cW) ----
    outproj_kernel<<<(N_NODES + 31) / 32, 256, OUT_SMEM>>>(out);
}

// round 11
// speedup vs baseline: 1.3228x; 1.2639x over previous
#include <cuda_runtime.h>
#include <cstdint>
#include <cstddef>

#define N_NODES 10000
#define E_ 320
#define D_ 15
#define T_ 16
#define OUT_ 30
#define UK 656
#define SR 324

// ---------------- scratch (device globals) ----------------
__device__ float g_MA[6 * E_ * E_];        // composed QKV mats [1920][320]
__device__ float g_Mq[E_ * E_];
__device__ float g_MKin[E_ * E_];
__device__ float g_MKout[E_ * E_];
__device__ float g_MVin[E_ * E_];
__device__ float g_MVout[E_ * E_];
__device__ float g_PW[E_ * 32];            // fo_w^T @ W, padded to 32 cols
__device__ float g_MqKcat[640 * E_];       // NOW [640][320] = [(Mq^T MKin)^T ; (Mq^T MKout)^T]
__device__ float g_G[UK * 32];             // [656][32] out-projection matrix
__device__ float g_cq[E_];
__device__ float g_ckin[E_];
__device__ float g_ckout[E_];
__device__ float g_cvin[E_];
__device__ float g_cvout[E_];
__device__ float g_cW[32];
__device__ float g_wv[640];                // [win | wout]
__device__ float g_wb[2];                  // bin, bout
__device__ float g_cqK[640];               // [cq@MKin | cq@MKout]
__device__ float g_XP[(size_t)N_NODES * 1920];
__device__ float g_CTX[(size_t)N_NODES * 10240];
__device__ float g_C0[(size_t)N_NODES * E_];   // compact copy of in-side ctx token 0
__device__ float g_TT[(size_t)N_NODES * 640];
__device__ float g_U[(size_t)(N_NODES + 32) * UK];

struct GemmDesc {
    const float* A; const float* B; float* C; const float* bias;
    int M, N, K, lda, ldb, ldc, op;  // op: 0=NT, 1=NN, 2=TN
};
struct GemmBatch { GemmDesc d[12]; };

// ---------------- tf32 helpers ----------------
__device__ __forceinline__ uint32_t f2tf32(float f) {
    uint32_t u;
    asm("cvt.rna.tf32.f32 %0, %1;" : "=r"(u) : "f"(f));
    return u;
}

#define MMA_TF32(d, a, b) \
    asm volatile("mma.sync.aligned.m16n8k8.row.col.f32.tf32.tf32.f32 " \
        "{%0,%1,%2,%3}, {%4,%5,%6,%7}, {%8,%9}, {%0,%1,%2,%3};" \
        : "+f"((d)[0]), "+f"((d)[1]), "+f"((d)[2]), "+f"((d)[3]) \
        : "r"((a)[0]), "r"((a)[1]), "r"((a)[2]), "r"((a)[3]), \
          "r"((b)[0]), "r"((b)[1]))

// ---------------- tf32 tensor-core GEMM (NT): C[m][n] = sum_k A[m][k]*B[n][k] ----------------
// Requires N % 128 == 0, K % 32 == 0, pointers float4-aligned, lda/ldb % 4 == 0.
// 128x128 block tile, 8 warps of 64x32, mma m16n8k8 tf32, fp32 accumulate.
__global__ void __launch_bounds__(256) tf32gemm(GemmDesc g)
{
    __shared__ uint32_t As[128][36];   // [m][k], pad 36 -> conflict-free frag loads
    __shared__ uint32_t Bs[128][36];   // [n][k]
    int tid = threadIdx.x;
    int warp = tid >> 5, lane = tid & 31;
    int wm = (warp >> 2) * 64;         // warp m-offset: 0 or 64
    int wn = (warp & 3) * 32;          // warp n-offset: 0,32,64,96
    int gr = lane >> 2, gc = lane & 3; // fragment row-group / col-in-group
    int m0 = blockIdx.y * 128, n0 = blockIdx.x * 128;

    float acc[4][4][4];
    #pragma unroll
    for (int mt = 0; mt < 4; mt++)
        #pragma unroll
        for (int nt = 0; nt < 4; nt++)
            #pragma unroll
            for (int r = 0; r < 4; r++) acc[mt][nt][r] = 0.f;

    // tile fill coords: thread t -> row t>>1, cols (t&1)*16 .. +15 (4 float4)
    int fr = tid >> 1;
    int fc = (tid & 1) << 4;
    const float* Ap = g.A + (size_t)(m0 + fr) * g.lda + fc;
    const float* Bp = g.B + (size_t)(n0 + fr) * g.ldb + fc;
    bool aok = (m0 + fr) < g.M;
    const float4 fz4 = make_float4(0.f, 0.f, 0.f, 0.f);

    for (int k0 = 0; k0 < g.K; k0 += 32) {
        #pragma unroll
        for (int i = 0; i < 4; i++) {
            float4 av = aok ? *(const float4*)(Ap + k0 + i * 4) : fz4;
            uint4 ua = make_uint4(f2tf32(av.x), f2tf32(av.y), f2tf32(av.z), f2tf32(av.w));
            *(uint4*)&As[fr][fc + i * 4] = ua;
            float4 bv = *(const float4*)(Bp + k0 + i * 4);
            uint4 ub = make_uint4(f2tf32(bv.x), f2tf32(bv.y), f2tf32(bv.z), f2tf32(bv.w));
            *(uint4*)&Bs[fr][fc + i * 4] = ub;
        }
        __syncthreads();
        #pragma unroll
        for (int ks = 0; ks < 32; ks += 8) {
            uint32_t af[4][4], bf[4][2];
            #pragma unroll
            for (int mt = 0; mt < 4; mt++) {
                int r = wm + mt * 16 + gr;
                af[mt][0] = As[r][ks + gc];
                af[mt][1] = As[r + 8][ks + gc];
                af[mt][2] = As[r][ks + gc + 4];
                af[mt][3] = As[r + 8][ks + gc + 4];
            }
            #pragma unroll
            for (int nt = 0; nt < 4; nt++) {
                int c = wn + nt * 8 + gr;
                bf[nt][0] = Bs[c][ks + gc];
                bf[nt][1] = Bs[c][ks + gc + 4];
            }
            #pragma unroll
            for (int mt = 0; mt < 4; mt++)
                #pragma unroll
                for (int nt = 0; nt < 4; nt++)
                    MMA_TF32(acc[mt][nt], af[mt], bf[nt]);
        }
        __syncthreads();
    }

    // epilogue: c0,c1 at (gr, 2*gc+{0,1}); c2,c3 at (gr+8, ...)
    #pragma unroll
    for (int mt = 0; mt < 4; mt++) {
        int r = m0 + wm + mt * 16 + gr;
        bool ok0 = r < g.M, ok1 = (r + 8) < g.M;
        float* Crow0 = g.C + (size_t)r * g.ldc;
        #pragma unroll
        for (int nt = 0; nt < 4; nt++) {
            int c = n0 + wn + nt * 8 + 2 * gc;
            float b0 = 0.f, b1 = 0.f;
            if (g.bias) { b0 = g.bias[c]; b1 = g.bias[c + 1]; }
            if (ok0) {
                float2 v = make_float2(acc[mt][nt][0] + b0, acc[mt][nt][1] + b1);
                *(float2*)(Crow0 + c) = v;
            }
            if (ok1) {
                float2 v = make_float2(acc[mt][nt][2] + b0, acc[mt][nt][3] + b1);
                *(float2*)(Crow0 + (size_t)8 * g.ldc + c) = v;
            }
        }
    }
}

// ---------------- big fp32 GEMM: 128x128 tile, 8x8 micro, double-buffered ----------------
template <int OP>
__global__ void __launch_bounds__(256) sgemm128(GemmDesc g)
{
    __shared__ float As[2][16][132];
    __shared__ float Bs[2][16][132];
    int tid = threadIdx.x;
    int tx = tid & 15, ty = tid >> 4;
    int m0 = blockIdx.y * 128, n0 = blockIdx.x * 128;
    float acc[8][8] = {};

    int a_m = tid >> 2, a_k = (tid & 3) << 2;
    bool a0ok = (m0 + a_m) < g.M;
    bool a1ok = (m0 + a_m + 64) < g.M;
    const float* Ar0 = g.A + (size_t)(m0 + a_m) * g.lda + a_k;
    const float* Ar1 = g.A + (size_t)(m0 + a_m + 64) * g.lda + a_k;
    int b_n = tid >> 2, b_k4 = (tid & 3) << 2;   // OP==0
    int b_k = tid >> 5, b_nq = (tid & 31) << 2;  // OP==1
    const float* Br0;
    const float* Br1;
    if (OP == 0) {
        Br0 = g.B + (size_t)(n0 + b_n) * g.ldb + b_k4;
        Br1 = g.B + (size_t)(n0 + b_n + 64) * g.ldb + b_k4;
    } else {
        Br0 = g.B + (size_t)b_k * g.ldb + n0 + b_nq;
        Br1 = g.B + (size_t)(b_k + 8) * g.ldb + n0 + b_nq;
    }

    const float4 fz = make_float4(0.f, 0.f, 0.f, 0.f);
    float4 pa0 = a0ok ? *(const float4*)Ar0 : fz;
    float4 pa1 = a1ok ? *(const float4*)Ar1 : fz;
    float4 pb0 = *(const float4*)Br0;
    float4 pb1 = *(const float4*)Br1;

    As[0][a_k + 0][a_m] = pa0.x; As[0][a_k + 1][a_m] = pa0.y;
    As[0][a_k + 2][a_m] = pa0.z; As[0][a_k + 3][a_m] = pa0.w;
    As[0][a_k + 0][a_m + 64] = pa1.x; As[0][a_k + 1][a_m + 64] = pa1.y;
    As[0][a_k + 2][a_m + 64] = pa1.z; As[0][a_k + 3][a_m + 64] = pa1.w;
    if (OP == 0) {
        Bs[0][b_k4 + 0][b_n] = pb0.x; Bs[0][b_k4 + 1][b_n] = pb0.y;
        Bs[0][b_k4 + 2][b_n] = pb0.z; Bs[0][b_k4 + 3][b_n] = pb0.w;
        Bs[0][b_k4 + 0][b_n + 64] = pb1.x; Bs[0][b_k4 + 1][b_n + 64] = pb1.y;
        Bs[0][b_k4 + 2][b_n + 64] = pb1.z; Bs[0][b_k4 + 3][b_n + 64] = pb1.w;
    } else {
        *(float4*)&Bs[0][b_k][b_nq] = pb0;
        *(float4*)&Bs[0][b_k + 8][b_nq] = pb1;
    }
    __syncthreads();

    int buf = 0;
    for (int k0 = 0; k0 < g.K; k0 += 16) {
        bool nxt = (k0 + 16) < g.K;
        if (nxt) {
            int ko = k0 + 16;
            pa0 = a0ok ? *(const float4*)(Ar0 + ko) : fz;
            pa1 = a1ok ? *(const float4*)(Ar1 + ko) : fz;
            if (OP == 0) {
                pb0 = *(const float4*)(Br0 + ko);
                pb1 = *(const float4*)(Br1 + ko);
            } else {
                pb0 = *(const float4*)(Br0 + (size_t)ko * g.ldb);
                pb1 = *(const float4*)(Br1 + (size_t)ko * g.ldb);
            }
        }
        #pragma unroll
        for (int kk = 0; kk < 16; kk++) {
            float a[8], b[8];
            *(float4*)&a[0] = *(float4*)&As[buf][kk][ty * 8];
            *(float4*)&a[4] = *(float4*)&As[buf][kk][ty * 8 + 4];
            *(float4*)&b[0] = *(float4*)&Bs[buf][kk][tx * 8];
            *(float4*)&b[4] = *(float4*)&Bs[buf][kk][tx * 8 + 4];
            #pragma unroll
            for (int r = 0; r < 8; r++)
                #pragma unroll
                for (int c = 0; c < 8; c++)
                    acc[r][c] += a[r] * b[c];
        }
        if (nxt) {
            int nb = buf ^ 1;
            As[nb][a_k + 0][a_m] = pa0.x; As[nb][a_k + 1][a_m] = pa0.y;
            As[nb][a_k + 2][a_m] = pa0.z; As[nb][a_k + 3][a_m] = pa0.w;
            As[nb][a_k + 0][a_m + 64] = pa1.x; As[nb][a_k + 1][a_m + 64] = pa1.y;
            As[nb][a_k + 2][a_m + 64] = pa1.z; As[nb][a_k + 3][a_m + 64] = pa1.w;
            if (OP == 0) {
                Bs[nb][b_k4 + 0][b_n] = pb0.x; Bs[nb][b_k4 + 1][b_n] = pb0.y;
                Bs[nb][b_k4 + 2][b_n] = pb0.z; Bs[nb][b_k4 + 3][b_n] = pb0.w;
                Bs[nb][b_k4 + 0][b_n + 64] = pb1.x; Bs[nb][b_k4 + 1][b_n + 64] = pb1.y;
                Bs[nb][b_k4 + 2][b_n + 64] = pb1.z; Bs[nb][b_k4 + 3][b_n + 64] = pb1.w;
            } else {
                *(float4*)&Bs[nb][b_k][b_nq] = pb0;
                *(float4*)&Bs[nb][b_k + 8][b_nq] = pb1;
            }
            __syncthreads();
            buf = nb;
        }
    }
    #pragma unroll
    for (int r = 0; r < 8; r++) {
        int gm = m0 + ty * 8 + r;
        if (gm >= g.M) break;
        #pragma unroll
        for (int c = 0; c < 8; c++) {
            int gn = n0 + tx * 8 + c;
            g.C[(size_t)gm * g.ldc + gn] = acc[r][c] + (g.bias ? g.bias[gn] : 0.f);
        }
    }
}

// ---------------- small batched GEMM: 64x64 tile, 4x4 micro ----------------
__global__ void __launch_bounds__(256) sgemm64(GemmBatch batch)
{
    GemmDesc g = batch.d[blockIdx.z];
    int m0 = blockIdx.y * 64, n0 = blockIdx.x * 64;
    if (m0 >= g.M || n0 >= g.N) return;
    __shared__ float As[64][17];
    __shared__ float Bs[64][17];
    int tid = threadIdx.x;
    int tx = tid & 15, ty = tid >> 4;
    float acc[4][4] = {};

    for (int k0 = 0; k0 < g.K; k0 += 16) {
        if (g.op == 2) {   // A [K][M]
            #pragma unroll
            for (int i = 0; i < 4; i++) {
                int li = tid + 256 * i;
                int m = li & 63, k = li >> 6;
                int gm = m0 + m;
                As[m][k] = (gm < g.M) ? g.A[(size_t)(k0 + k) * g.lda + gm] : 0.f;
            }
        } else {           // A [M][K]
            #pragma unroll
            for (int i = 0; i < 4; i++) {
                int li = tid + 256 * i;
                int k = li & 15, m = li >> 4;
                int gm = m0 + m;
                As[m][k] = (gm < g.M) ? g.A[(size_t)gm * g.lda + k0 + k] : 0.f;
            }
        }
        if (g.op == 0) {   // B [N][K]
            #pragma unroll
            for (int i = 0; i < 4; i++) {
                int li = tid + 256 * i;
                int k = li & 15, n = li >> 4;
                int gn = n0 + n;
                Bs[n][k] = (gn < g.N) ? g.B[(size_t)gn * g.ldb + k0 + k] : 0.f;
            }
        } else {           // B [K][N]
            #pragma unroll
            for (int i = 0; i < 4; i++) {
                int li = tid + 256 * i;
                int n = li & 63, k = li >> 6;
                int gn = n0 + n;
                Bs[n][k] = (gn < g.N) ? g.B[(size_t)(k0 + k) * g.ldb + gn] : 0.f;
            }
        }
        __syncthreads();
        #pragma unroll
        for (int kk = 0; kk < 16; kk++) {
            float af[4], bf[4];
            #pragma unroll
            for (int r = 0; r < 4; r++) af[r] = As[ty * 4 + r][kk];
            #pragma unroll
            for (int c = 0; c < 4; c++) bf[c] = Bs[tx * 4 + c][kk];
            #pragma unroll
            for (int r = 0; r < 4; r++)
                #pragma unroll
                for (int c = 0; c < 4; c++)
                    acc[r][c] += af[r] * bf[c];
        }
        __syncthreads();
    }
    #pragma unroll
    for (int r = 0; r < 4; r++) {
        int gm = m0 + ty * 4 + r;
        if (gm >= g.M) continue;
        #pragma unroll
        for (int c = 0; c < 4; c++) {
            int gn = n0 + tx * 4 + c;
            if (gn < g.N)
                g.C[(size_t)gm * g.ldc + gn] = acc[r][c] + (g.bias ? g.bias[gn] : 0.f);
        }
    }
}

// ---------------- warp-parallel raw-input vectors + zero init of G ----------------
__global__ void __launch_bounds__(256) compose_small2(
    const float* __restrict__ finw, const float* __restrict__ finb,
    const float* __restrict__ fob,
    const float* __restrict__ inob, const float* __restrict__ outob,
    const float* __restrict__ W)
{
    if (blockIdx.x >= 204) {
        int i = (blockIdx.x - 204) * 256 + threadIdx.x;
        if (i < (UK * 32) / 4) ((float4*)g_G)[i] = make_float4(0.f, 0.f, 0.f, 0.f);
        return;
    }
    int gw = blockIdx.x * 8 + (threadIdx.x >> 5);
    int lane = threadIdx.x & 31;
    float acc = 0.f;
    if (gw < 1600) {
        int grp = gw / 320, j = gw - grp * 320;
        const float* row;
        const float* vec;
        float b;
        if (grp == 0)      { row = finw + (size_t)j * E_;            vec = inob;  b = finb[j]; }
        else if (grp == 1) { row = finw + (size_t)(E_ + j) * E_;     vec = inob;  b = finb[E_ + j]; }
        else if (grp == 2) { row = finw + (size_t)(E_ + j) * E_;     vec = outob; b = finb[E_ + j]; }
        else if (grp == 3) { row = finw + (size_t)(2 * E_ + j) * E_; vec = inob;  b = finb[2 * E_ + j]; }
        else               { row = finw + (size_t)(2 * E_ + j) * E_; vec = outob; b = finb[2 * E_ + j]; }
        #pragma unroll
        for (int i = 0; i < 10; i++) acc += row[lane + 32 * i] * vec[lane + 32 * i];
        #pragma unroll
        for (int o = 16; o; o >>= 1) acc += __shfl_xor_sync(0xffffffffu, acc, o);
        if (lane == 0) {
            acc += b;
            if (grp == 0)      g_cq[j] = acc;
            else if (grp == 1) g_ckin[j] = acc;
            else if (grp == 2) g_ckout[j] = acc;
            else if (grp == 3) g_cvin[j] = acc;
            else               g_cvout[j] = acc;
        }
    } else if (gw < 1632) {
        int o = gw - 1600;
        if (o < OUT_) {
            #pragma unroll
            for (int i = 0; i < 10; i++) {
                int k = lane + 32 * i;
                acc += fob[k] * W[k * OUT_ + o];
            }
        }
        #pragma unroll
        for (int oo = 16; oo; oo >>= 1) acc += __shfl_xor_sync(0xffffffffu, acc, oo);
        if (lane == 0) g_cW[o] = (o < OUT_) ? acc : 0.f;
    }
}

// ---------------- warp-parallel level-2 vectors ----------------
__global__ void __launch_bounds__(256) smallvec_kernel()
{
    int gw = blockIdx.x * 8 + (threadIdx.x >> 5);
    int lane = threadIdx.x & 31;
    float acc = 0.f;
    if (gw < 640) {                        // wv[i] = sum_j Mq[j][i] * ck[j]
        int side = gw >= 320;
        int i = gw - side * 320;
        const float* ck = side ? g_ckout : g_ckin;
        #pragma unroll
        for (int q = 0; q < 10; q++) {
            int j = lane + 32 * q;
            acc += g_Mq[(size_t)j * E_ + i] * ck[j];
        }
        #pragma unroll
        for (int o = 16; o; o >>= 1) acc += __shfl_xor_sync(0xffffffffu, acc, o);
        if (lane == 0) g_wv[gw] = acc;
    } else if (gw < 1280) {                // cqK[c] = sum_j cq[j] * MK[j][c]
        int side = gw >= 960;
        int c = gw - 640 - side * 320;
        const float* MK = side ? g_MKout : g_MKin;
        #pragma unroll
        for (int q = 0; q < 10; q++) {
            int j = lane + 32 * q;
            acc += g_cq[j] * MK[(size_t)j * E_ + c];
        }
        #pragma unroll
        for (int o = 16; o; o >>= 1) acc += __shfl_xor_sync(0xffffffffu, acc, o);
        if (lane == 0) g_cqK[side * 320 + c] = acc;
    } else if (gw < 1340) {                // G rows 640/641 = PW^T cv
        int r = gw - 1280;
        int row = r >= 30;
        int o = r - row * 30;
        const float* cv = row ? g_cvout : g_cvin;
        #pragma unroll
        for (int q = 0; q < 10; q++) {
            int c = lane + 32 * q;
            acc += cv[c] * g_PW[c * 32 + o];
        }
        #pragma unroll
        for (int oo = 16; oo; oo >>= 1) acc += __shfl_xor_sync(0xffffffffu, acc, oo);
        if (lane == 0) g_G[(640 + row) * 32 + o] = acc;
    } else if (gw < 1342) {                // wb = cq . ck
        int w = gw - 1340;
        const float* ck = w ? g_ckout : g_ckin;
        #pragma unroll
        for (int q = 0; q < 10; q++) {
            int j = lane + 32 * q;
            acc += g_cq[j] * ck[j];
        }
        #pragma unroll
        for (int o = 16; o; o >>= 1) acc += __shfl_xor_sync(0xffffffffu, acc, o);
        if (lane == 0) g_wb[w] = acc;
    }
}

// ---------------- per-node 5-head attention ----------------
__global__ void __launch_bounds__(256) attn_kernel(
    const int* __restrict__ in_idx, const int* __restrict__ out_idx,
    const float* __restrict__ in_b, const float* __restrict__ out_b)
{
    int n = blockIdx.x;
    int tid = threadIdx.x;
    extern __shared__ float sm[];
    float* Qs = sm;                 // 16*SR
    float* Ks = Qs + T_ * SR;
    float* Vs = Ks + T_ * SR;
    float* A0 = Vs + T_ * SR;       // 1280
    float* A1 = A0 + 1280;          // 1280
    __shared__ int rows[2][T_];

    if (tid < 32) {
        int s = tid >> 4, t = tid & 15;
        const int* idx = s ? out_idx : in_idx;
        rows[s][t] = t ? idx[n * D_ + t - 1] : n;
    }
    __syncthreads();

    for (int side = 0; side < 2; side++) {
        const float* bias = side ? out_b : in_b;
        int colbase = side * 960;
        for (int e = tid; e < 3840; e += 256) {
            int a = e / 1280, r = e - a * 1280;
            int t = r / 80, j = (r - t * 80) * 4;
            const float* src = g_XP + (size_t)rows[side][t] * 1920 + colbase + a * 320 + j;
            float4 v = *(const float4*)src;
            float4 bv = *(const float4*)(bias + a * 320 + j);
            v.x += bv.x; v.y += bv.y; v.z += bv.z; v.w += bv.w;
            float* dst = (a == 0 ? Qs : (a == 1 ? Ks : Vs)) + t * SR + j;
            *(float4*)dst = v;
        }
        __syncthreads();
        if (tid < 160) {
            int dh = tid & 1;
            int tile = tid >> 1;
            int h = tile >> 4, rem = tile & 15;
            int l0 = (rem >> 2) * 4, mm0 = (rem & 3) * 4;
            const float* qb = Qs + h * 64 + dh * 32;
            const float* kb = Ks + h * 64 + dh * 32;
            float acc[4][4] = {};
            #pragma unroll
            for (int d = 0; d < 32; d += 4) {
                float4 q[4], k4[4];
                #pragma unroll
                for (int r = 0; r < 4; r++) q[r] = *(const float4*)(qb + (l0 + r) * SR + d);
                #pragma unroll
                for (int c = 0; c < 4; c++) k4[c] = *(const float4*)(kb + (mm0 + c) * SR + d);
                #pragma unroll
                for (int r = 0; r < 4; r++)
                    #pragma unroll
                    for (int c = 0; c < 4; c++)
                        acc[r][c] += q[r].x * k4[c].x + q[r].y * k4[c].y
                                   + q[r].z * k4[c].z + q[r].w * k4[c].w;
            }
            float* dst = dh ? A1 : A0;
            #pragma unroll
            for (int r = 0; r < 4; r++)
                #pragma unroll
                for (int c = 0; c < 4; c++)
                    dst[(h * 16 + l0 + r) * 16 + mm0 + c] = acc[r][c];
        }
        __syncthreads();
        if (tid < 80) {
            int base = tid * 16;
            float v[16];
            float mx = -1e30f;
            #pragma unroll
            for (int m = 0; m < 16; m++) {
                v[m] = (A0[base + m] + A1[base + m]) * 0.125f;
                mx = fmaxf(mx, v[m]);
            }
            float ssum = 0.f;
            #pragma unroll
            for (int m = 0; m < 16; m++) { v[m] = __expf(v[m] - mx); ssum += v[m]; }
            float inv = 1.f / ssum;
            #pragma unroll
            for (int m = 0; m < 16; m++) A0[base + m] = v[m] * inv;
        }
        __syncthreads();
        float* ctxout = g_CTX + (size_t)n * 10240 + side * 5120;
        for (int u = tid; u < 640; u += 256) {
            int tp = u / 80;
            int j = (u - tp * 80) * 4;
            int h = j >> 6;
            int t0 = tp * 2;
            float ar0[16], ar1[16];
            #pragma unroll
            for (int q = 0; q < 4; q++) {
                *(float4*)&ar0[q * 4] = *(const float4*)&A0[(h * 16 + t0) * 16 + q * 4];
                *(float4*)&ar1[q * 4] = *(const float4*)&A0[(h * 16 + t0 + 1) * 16 + q * 4];
            }
            float4 acc0 = make_float4(0.f, 0.f, 0.f, 0.f);
            float4 acc1 = make_float4(0.f, 0.f, 0.f, 0.f);
            #pragma unroll
            for (int m = 0; m < 16; m++) {
                float4 v4 = *(const float4*)(Vs + m * SR + j);
                acc0.x += ar0[m] * v4.x; acc0.y += ar0[m] * v4.y;
                acc0.z += ar0[m] * v4.z; acc0.w += ar0[m] * v4.w;
                acc1.x += ar1[m] * v4.x; acc1.y += ar1[m] * v4.y;
                acc1.z += ar1[m] * v4.z; acc1.w += ar1[m] * v4.w;
            }
            *(float4*)(ctxout + (size_t)t0 * 320 + j) = acc0;
            *(float4*)(ctxout + (size_t)(t0 + 1) * 320 + j) = acc1;
            if (side == 0 && t0 == 0)   // compact copy of in-side token 0 for TT GEMM
                *(float4*)(g_C0 + (size_t)n * E_ + j) = acc0;
        }
        __syncthreads();
    }
}

// ---------------- final-layer scores + softmax + U (L2-served CTX) ----------------
__global__ void __launch_bounds__(256) finscore_kernel()
{
    int n = blockIdx.x;
    int tid = threadIdx.x, lane = tid & 31, w = tid >> 5;
    __shared__ float Ts[640];
    __shared__ float sA[32];
    __shared__ float sc[2];
    __shared__ float s_sain;
    const float* ctxn = g_CTX + (size_t)n * 10240;

    for (int i = tid; i < 640; i += 256) Ts[i] = g_TT[(size_t)n * 640 + i];
    __syncthreads();
    #pragma unroll
    for (int ii = 0; ii < 4; ii++) {
        int t = w * 4 + ii;
        int side = t >> 4, tok = t & 15;
        const float* cr = ctxn + side * 5120 + tok * 320;
        const float* tv = Ts + side * 320;
        float acc = 0.f;
        #pragma unroll
        for (int i = 0; i < 10; i++) acc += cr[lane + 32 * i] * tv[lane + 32 * i];
        #pragma unroll
        for (int o = 16; o; o >>= 1) acc += __shfl_xor_sync(0xffffffffu, acc, o);
        if (lane == 0) sA[t] = acc;
    }
    if (w < 2) {     // sc = ctx0 . w_side + b_side
        const float* cr = ctxn;
        const float* tv = g_wv + w * 320;
        float acc = 0.f;
        #pragma unroll
        for (int i = 0; i < 10; i++) acc += cr[lane + 32 * i] * tv[lane + 32 * i];
        #pragma unroll
        for (int o = 16; o; o >>= 1) acc += __shfl_xor_sync(0xffffffffu, acc, o);
        if (lane == 0) sc[w] = acc + g_wb[w];
    }
    __syncthreads();
    if (tid < 32) {  // softmax over 32 (scale = 320^-0.5)
        float v = (sA[tid] + sc[tid >> 4]) * 0.05590169943749474f;
        float mx = v;
        #pragma unroll
        for (int o = 16; o; o >>= 1) mx = fmaxf(mx, __shfl_xor_sync(0xffffffffu, mx, o));
        float e = __expf(v - mx);
        float ssum = e;
        #pragma unroll
        for (int o = 16; o; o >>= 1) ssum += __shfl_xor_sync(0xffffffffu, ssum, o);
        float a = e / ssum;
        sA[tid] = a;
        float ain = (tid < 16) ? a : 0.f;
        #pragma unroll
        for (int o = 16; o; o >>= 1) ain += __shfl_xor_sync(0xffffffffu, ain, o);
        if (tid == 0) s_sain = ain;
    }
    __syncthreads();
    float sain = s_sain;
    float* urow = g_U + (size_t)n * UK;
    if (tid < 160) {          // 160 float4 columns = 640 floats
        int side = tid >= 80;
        int off = (tid - side * 80) * 4;
        const float* cb = ctxn + side * 5120;
        const float* av = sA + side * 16;
        float4 acc = make_float4(0.f, 0.f, 0.f, 0.f);
        #pragma unroll
        for (int t = 0; t < 16; t++) {
            float a = av[t];
            float4 v = *(const float4*)(cb + t * 320 + off);
            acc.x += a * v.x; acc.y += a * v.y;
            acc.z += a * v.z; acc.w += a * v.w;
        }
        *(float4*)(urow + side * 320 + off) = acc;
    } else if (tid < 164) {   // tail 640..655
        int base = 640 + (tid - 160) * 4;
        float4 v = make_float4(0.f, 0.f, 0.f, 0.f);
        if (tid == 160) { v.x = sain; v.y = 1.f - sain; }
        *(float4*)(urow + base) = v;
    }
}

// ---------------- out = elu(U @ G + cW), 4 nodes per warp ----------------
__global__ void __launch_bounds__(256) outproj_kernel(float* __restrict__ out)
{
    extern __shared__ float sm2[];
    float* Gs = sm2;                 // 656*32
    float* Us = sm2 + UK * 32;       // 32*656
    int tid = threadIdx.x;
    int n0 = blockIdx.x * 32;

    for (int i = tid; i < (UK * 32) / 4; i += 256)
        ((float4*)Gs)[i] = ((const float4*)g_G)[i];
    const float* usrc = g_U + (size_t)n0 * UK;
    for (int i = tid; i < (32 * UK) / 4; i += 256)
        ((float4*)Us)[i] = ((const float4*)usrc)[i];
    __syncthreads();

    int w = tid >> 5, lane = tid & 31;
    const float* ur0 = Us + (w * 4 + 0) * UK;
    const float* ur1 = Us + (w * 4 + 1) * UK;
    const float* ur2 = Us + (w * 4 + 2) * UK;
    const float* ur3 = Us + (w * 4 + 3) * UK;
    float a0 = 0.f, a1 = 0.f, a2 = 0.f, a3 = 0.f;
    for (int i = 0; i < UK; i += 4) {
        float g0 = Gs[(i + 0) * 32 + lane];
        float g1 = Gs[(i + 1) * 32 + lane];
        float g2 = Gs[(i + 2) * 32 + lane];
        float g3 = Gs[(i + 3) * 32 + lane];
        float4 u0 = *(const float4*)(ur0 + i);
        float4 u1 = *(const float4*)(ur1 + i);
        float4 u2 = *(const float4*)(ur2 + i);
        float4 u3 = *(const float4*)(ur3 + i);
        a0 += u0.x * g0 + u0.y * g1 + u0.z * g2 + u0.w * g3;
        a1 += u1.x * g0 + u1.y * g1 + u1.z * g2 + u1.w * g3;
        a2 += u2.x * g0 + u2.y * g1 + u2.z * g2 + u2.w * g3;
        a3 += u3.x * g0 + u3.y * g1 + u3.z * g2 + u3.w * g3;
    }
    if (lane < OUT_) {
        float cw = g_cW[lane];
        int n = n0 + w * 4;
        float r0 = a0 + cw, r1 = a1 + cw, r2 = a2 + cw, r3 = a3 + cw;
        if (n + 0 < N_NODES) out[(n + 0) * OUT_ + lane] = r0 > 0.f ? r0 : expm1f(r0);
        if (n + 1 < N_NODES) out[(n + 1) * OUT_ + lane] = r1 > 0.f ? r1 : expm1f(r1);
        if (n + 2 < N_NODES) out[(n + 2) * OUT_ + lane] = r2 > 0.f ? r2 : expm1f(r2);
        if (n + 3 < N_NODES) out[(n + 3) * OUT_ + lane] = r3 > 0.f ? r3 : expm1f(r3);
    }
}

// ---------------- host ----------------
extern "C" void kernel_launch(void* const* d_in, const int* in_sizes, int n_in,
                              void* d_out, int out_size)
{
    const float* X         = (const float*)d_in[0];
    const int*   in_idx    = (const int*)  d_in[1];
    const int*   out_idx   = (const int*)  d_in[2];
    const float* in_Wq     = (const float*)d_in[3];
    const float* in_Wk     = (const float*)d_in[4];
    const float* in_Wv     = (const float*)d_in[5];
    const float* in_qkv_w  = (const float*)d_in[6];
    const float* in_qkv_b  = (const float*)d_in[7];
    const float* in_o_w    = (const float*)d_in[8];
    const float* in_o_b    = (const float*)d_in[9];
    const float* out_Wq    = (const float*)d_in[10];
    const float* out_Wk    = (const float*)d_in[11];
    const float* out_Wv    = (const float*)d_in[12];
    const float* out_qkv_w = (const float*)d_in[13];
    const float* out_qkv_b = (const float*)d_in[14];
    const float* out_o_w   = (const float*)d_in[15];
    const float* out_o_b   = (const float*)d_in[16];
    const float* fin_qkv_w = (const float*)d_in[17];
    const float* fin_qkv_b = (const float*)d_in[18];
    const float* fin_o_w   = (const float*)d_in[19];
    const float* fin_o_b   = (const float*)d_in[20];
    const float* Wmat      = (const float*)d_in[21];
    float* out = (float*)d_out;

    float *pMA, *pMq, *pMKin, *pMKout, *pMVin, *pMVout, *pPW, *pMqKcatT, *pG,
          *pXP, *pCTX, *pC0, *pTT, *pU, *pcqK;
    cudaGetSymbolAddress((void**)&pMA, g_MA);
    cudaGetSymbolAddress((void**)&pMq, g_Mq);
    cudaGetSymbolAddress((void**)&pMKin, g_MKin);
    cudaGetSymbolAddress((void**)&pMKout, g_MKout);
    cudaGetSymbolAddress((void**)&pMVin, g_MVin);
    cudaGetSymbolAddress((void**)&pMVout, g_MVout);
    cudaGetSymbolAddress((void**)&pPW, g_PW);
    cudaGetSymbolAddress((void**)&pMqKcatT, g_MqKcat);
    cudaGetSymbolAddress((void**)&pG, g_G);
    cudaGetSymbolAddress((void**)&pXP, g_XP);
    cudaGetSymbolAddress((void**)&pCTX, g_CTX);
    cudaGetSymbolAddress((void**)&pC0, g_C0);
    cudaGetSymbolAddress((void**)&pTT, g_TT);
    cudaGetSymbolAddress((void**)&pU, g_U);
    cudaGetSymbolAddress((void**)&pcqK, g_cqK);

    const int ATTN_SMEM = (3 * T_ * SR + 2 * 1280) * (int)sizeof(float);
    const int OUT_SMEM  = (2 * UK * 32) * (int)sizeof(float);
    cudaFuncSetAttribute(attn_kernel, cudaFuncAttributeMaxDynamicSharedMemorySize, ATTN_SMEM);
    cudaFuncSetAttribute(outproj_kernel, cudaFuncAttributeMaxDynamicSharedMemorySize, OUT_SMEM);

    // ---- launch 0: compose level 1 (batched, z=12) ----
    GemmBatch L1 = {};
    const float* Ws6[6] = {in_Wq, in_Wk, in_Wv, out_Wq, out_Wk, out_Wv};
    const float* Qw6[6] = {in_qkv_w, in_qkv_w + E_ * E_, in_qkv_w + 2 * E_ * E_,
                           out_qkv_w, out_qkv_w + E_ * E_, out_qkv_w + 2 * E_ * E_};
    for (int s = 0; s < 6; s++)
        L1.d[s] = {Qw6[s], Ws6[s], pMA + s * E_ * E_, nullptr,
                   E_, E_, E_, E_, E_, E_, 0};
    L1.d[6]  = {fin_qkv_w,               in_o_w,  pMq,    nullptr, E_, E_,  E_, E_, E_, E_, 1};
    L1.d[7]  = {fin_qkv_w + E_ * E_,     in_o_w,  pMKin,  nullptr, E_, E_,  E_, E_, E_, E_, 1};
    L1.d[8]  = {fin_qkv_w + E_ * E_,     out_o_w, pMKout, nullptr, E_, E_,  E_, E_, E_, E_, 1};
    L1.d[9]  = {fin_qkv_w + 2 * E_ * E_, in_o_w,  pMVin,  nullptr, E_, E_,  E_, E_, E_, E_, 1};
    L1.d[10] = {fin_qkv_w + 2 * E_ * E_, out_o_w, pMVout, nullptr, E_, E_,  E_, E_, E_, E_, 1};
    L1.d[11] = {fin_o_w,                 Wmat,    pPW,    nullptr, E_, OUT_, E_, E_, OUT_, 32, 2};
    sgemm64<<<dim3(5, 5, 12), 256>>>(L1);

    // ---- launch 1: raw-input small vectors + zero G ----
    compose_small2<<<225, 256>>>(fin_qkv_w, fin_qkv_b, fin_o_b, in_o_b, out_o_b, Wmat);

    // ---- launch 2: compose level 2 (batched, z=4) ----
    // MqKcatT[n][m] = sum_k MK[k][n]*Mq[k][m]  (= (Mq^T MK)^T), stored [640][320]
    GemmBatch L2 = {};
    L2.d[0] = {pMKin,  pMq, pMqKcatT,            nullptr, E_, E_,  E_, E_, E_, E_, 2};
    L2.d[1] = {pMKout, pMq, pMqKcatT + E_ * E_,  nullptr, E_, E_,  E_, E_, E_, E_, 2};
    L2.d[2] = {pMVin,  pPW, pG,                  nullptr, E_, OUT_, E_, E_, 32, 32, 2};
    L2.d[3] = {pMVout, pPW, pG + E_ * 32,        nullptr, E_, OUT_, E_, E_, 32, 32, 2};
    sgemm64<<<dim3(5, 5, 4), 256>>>(L2);

    // ---- launch 3 (ncu capture slot): XP = X @ MA^T  (tf32 tensor cores) ----
    GemmDesc xp = {X, pMA, pXP, nullptr, N_NODES, 1920, E_, E_, E_, 1920, 0};
    tf32gemm<<<dim3(15, 79), 256>>>(xp);

    // ---- launch 4: level-2 vectors ----
    smallvec_kernel<<<168, 256>>>();

    // ---- launch 5: per-node attention ----
    attn_kernel<<<N_NODES, 256, ATTN_SMEM>>>(in_idx, out_idx, in_qkv_b, out_qkv_b);

    // ---- launch 6: [Tin|Tout] = C0 @ MqKcatT^T + cqK  (tf32 NT) ----
    GemmDesc tt = {pC0, pMqKcatT, pTT, pcqK, N_NODES, 640, E_, E_, E_, 640, 0};
    tf32gemm<<<dim3(5, 79), 256>>>(tt);

    // ---- launch 7: final scores + softmax + U ----
    finscore_kernel<<<N_NODES, 256>>>();

    // ---- launch 8: out = elu(U @ G + cW) ----
    outproj_kernel<<<(N_NODES + 31) / 32, 256, OUT_SMEM>>>(out);
}

// round 13
// speedup vs baseline: 1.3416x; 1.0142x over previous
#include <cuda_runtime.h>
#include <cstdint>
#include <cstddef>

#define N_NODES 10000
#define E_ 320
#define D_ 15
#define T_ 16
#define OUT_ 30
#define UK 656
#define SR 324
#define TFPAD 40

// ---------------- scratch (device globals) ----------------
__device__ float g_MA[6 * E_ * E_];        // composed QKV mats [1920][320]
__device__ float g_Mq[E_ * E_];
__device__ float g_MKin[E_ * E_];
__device__ float g_MKout[E_ * E_];
__device__ float g_MVin[E_ * E_];
__device__ float g_MVout[E_ * E_];
__device__ float g_PW[E_ * 32];            // fo_w^T @ W, padded to 32 cols
__device__ float g_MqKcat[640 * E_];       // [640][320] = [(Mq^T MKin)^T ; (Mq^T MKout)^T]
__device__ float g_G[UK * 32];             // [656][32] out-projection matrix
__device__ float g_cq[E_];
__device__ float g_ckin[E_];
__device__ float g_ckout[E_];
__device__ float g_cvin[E_];
__device__ float g_cvout[E_];
__device__ float g_cW[32];
__device__ float g_wv[640];                // [win | wout]
__device__ float g_wb[2];                  // bin, bout
__device__ float g_cqK[640];               // [cq@MKin | cq@MKout]
__device__ float g_XP[(size_t)N_NODES * 1920];
__device__ float g_CTX[(size_t)N_NODES * 10240];
__device__ float g_C0[(size_t)N_NODES * E_];   // compact copy of in-side ctx token 0
__device__ float g_TT[(size_t)N_NODES * 640];
__device__ float g_U[(size_t)(N_NODES + 32) * UK];

struct GemmDesc {
    const float* A; const float* B; float* C; const float* bias;
    int M, N, K, lda, ldb, ldc, op;  // op: 0=NT, 1=NN, 2=TN
};
struct GemmBatch { GemmDesc d[12]; };

// ---------------- async-copy + mma helpers ----------------
__device__ __forceinline__ void cp_async16(uint32_t dst, const void* src, int src_bytes) {
    asm volatile("cp.async.ca.shared.global [%0], [%1], 16, %2;"
                 :: "r"(dst), "l"(src), "r"(src_bytes) : "memory");
}
__device__ __forceinline__ void cp_commit() {
    asm volatile("cp.async.commit_group;" ::: "memory");
}
template <int N>
__device__ __forceinline__ void cp_wait() {
    asm volatile("cp.async.wait_group %0;" :: "n"(N) : "memory");
}

#define MMA_TF32(d, a, b) \
    asm volatile("mma.sync.aligned.m16n8k8.row.col.f32.tf32.tf32.f32 " \
        "{%0,%1,%2,%3}, {%4,%5,%6,%7}, {%8,%9}, {%0,%1,%2,%3};" \
        : "+f"((d)[0]), "+f"((d)[1]), "+f"((d)[2]), "+f"((d)[3]) \
        : "r"((a)[0]), "r"((a)[1]), "r"((a)[2]), "r"((a)[3]), \
          "r"((b)[0]), "r"((b)[1]))

// ---------------- tf32 tensor-core GEMM (NT): C[m][n] = sum_k A[m][k]*B[n][k] ----------------
// N % 128 == 0, K % 32 == 0, float4-aligned pointers, lda/ldb % 4 == 0. M tail guarded (zfill).
// 128x128 block, 8 warps of 64x32. cp.async double-buffered. k-relabeled fragment loads
// (thread gc uses k-slots {2gc, 2gc+1} in BOTH A and B -> LDS.64, conflict-free with PAD=40).
// Raw fp32 bits fed to tf32 mma (HW truncates low mantissa).
__global__ void __launch_bounds__(256) tf32gemm(GemmDesc g)
{
    extern __shared__ uint32_t ts[];
    uint32_t* Asm = ts;                       // [2][128][TFPAD]
    uint32_t* Bsm = ts + 2 * 128 * TFPAD;     // [2][128][TFPAD]
    int tid = threadIdx.x, warp = tid >> 5, lane = tid & 31;
    int wm = (warp >> 2) * 64, wn = (warp & 3) * 32;
    int gr = lane >> 2, gc2 = (lane & 3) << 1;
    int m0 = blockIdx.y * 128, n0 = blockIdx.x * 128;

    float acc[4][4][4] = {};

    // fill coords: thread -> row tid>>1, 16 cols starting at (tid&1)*16
    int fr = tid >> 1, fc = (tid & 1) << 4;
    const float* Ap = g.A + (size_t)(m0 + fr) * g.lda + fc;
    const float* Bp = g.B + (size_t)(n0 + fr) * g.ldb + fc;
    int asz = ((m0 + fr) < g.M) ? 16 : 0;

    uint32_t aBase = (uint32_t)__cvta_generic_to_shared(Asm);
    uint32_t bBase = (uint32_t)__cvta_generic_to_shared(Bsm);
    uint32_t aDst = aBase + (fr * TFPAD + fc) * 4;
    uint32_t bDst = bBase + (fr * TFPAD + fc) * 4;
    const uint32_t bufStride = 128 * TFPAD * 4;

    int niter = g.K / 32;
    // prologue: tiles 0 and 1 in flight
    #pragma unroll
    for (int i = 0; i < 4; i++) {
        cp_async16(aDst + i * 16, Ap + i * 4, asz);
        cp_async16(bDst + i * 16, Bp + i * 4, 16);
    }
    cp_commit();
    if (niter > 1) {
        #pragma unroll
        for (int i = 0; i < 4; i++) {
            cp_async16(aDst + bufStride + i * 16, Ap + 32 + i * 4, asz);
            cp_async16(bDst + bufStride + i * 16, Bp + 32 + i * 4, 16);
        }
        cp_commit();
    }

    for (int it = 0; it < niter; it++) {
        if (it + 1 < niter) cp_wait<1>(); else cp_wait<0>();
        __syncthreads();
        const uint32_t* Ab = Asm + (it & 1) * (128 * TFPAD);
        const uint32_t* Bb = Bsm + (it & 1) * (128 * TFPAD);
        #pragma unroll
        for (int ks = 0; ks < 32; ks += 8) {
            uint32_t af[4][4], bf[4][2];
            #pragma unroll
            for (int mt = 0; mt < 4; mt++) {
                int r = wm + mt * 16 + gr;
                uint2 v0 = *(const uint2*)&Ab[r * TFPAD + ks + gc2];
                uint2 v1 = *(const uint2*)&Ab[(r + 8) * TFPAD + ks + gc2];
                af[mt][0] = v0.x; af[mt][2] = v0.y;
                af[mt][1] = v1.x; af[mt][3] = v1.y;
            }
            #pragma unroll
            for (int nt = 0; nt < 4; nt++) {
                int c = wn + nt * 8 + gr;
                uint2 w0 = *(const uint2*)&Bb[c * TFPAD + ks + gc2];
                bf[nt][0] = w0.x; bf[nt][1] = w0.y;
            }
            #pragma unroll
            for (int mt = 0; mt < 4; mt++)
                #pragma unroll
                for (int nt = 0; nt < 4; nt++)
                    MMA_TF32(acc[mt][nt], af[mt], bf[nt]);
        }
        __syncthreads();
        if (it + 2 < niter) {
            int ko = (it + 2) * 32;
            uint32_t boff = (it & 1) * bufStride;
            #pragma unroll
            for (int i = 0; i < 4; i++) {
                cp_async16(aDst + boff + i * 16, Ap + ko + i * 4, asz);
                cp_async16(bDst + boff + i * 16, Bp + ko + i * 4, 16);
            }
            cp_commit();
        }
    }

    // epilogue: c0,c1 at (gr, 2*gc+{0,1}); c2,c3 at (gr+8, ...)
    int gc = lane & 3;
    #pragma unroll
    for (int mt = 0; mt < 4; mt++) {
        int r = m0 + wm + mt * 16 + gr;
        bool ok0 = r < g.M, ok1 = (r + 8) < g.M;
        float* Crow0 = g.C + (size_t)r * g.ldc;
        #pragma unroll
        for (int nt = 0; nt < 4; nt++) {
            int c = n0 + wn + nt * 8 + 2 * gc;
            float b0 = 0.f, b1 = 0.f;
            if (g.bias) { b0 = g.bias[c]; b1 = g.bias[c + 1]; }
            if (ok0) {
                float2 v = make_float2(acc[mt][nt][0] + b0, acc[mt][nt][1] + b1);
                *(float2*)(Crow0 + c) = v;
            }
            if (ok1) {
                float2 v = make_float2(acc[mt][nt][2] + b0, acc[mt][nt][3] + b1);
                *(float2*)(Crow0 + (size_t)8 * g.ldc + c) = v;
            }
        }
    }
}

// ---------------- small batched GEMM: 64x64 tile, 4x4 micro ----------------
__global__ void __launch_bounds__(256) sgemm64(GemmBatch batch)
{
    GemmDesc g = batch.d[blockIdx.z];
    int m0 = blockIdx.y * 64, n0 = blockIdx.x * 64;
    if (m0 >= g.M || n0 >= g.N) return;
    __shared__ float As[64][17];
    __shared__ float Bs[64][17];
    int tid = threadIdx.x;
    int tx = tid & 15, ty = tid >> 4;
    float acc[4][4] = {};

    for (int k0 = 0; k0 < g.K; k0 += 16) {
        if (g.op == 2) {   // A [K][M]
            #pragma unroll
            for (int i = 0; i < 4; i++) {
                int li = tid + 256 * i;
                int m = li & 63, k = li >> 6;
                int gm = m0 + m;
                As[m][k] = (gm < g.M) ? g.A[(size_t)(k0 + k) * g.lda + gm] : 0.f;
            }
        } else {           // A [M][K]
            #pragma unroll
            for (int i = 0; i < 4; i++) {
                int li = tid + 256 * i;
                int k = li & 15, m = li >> 4;
                int gm = m0 + m;
                As[m][k] = (gm < g.M) ? g.A[(size_t)gm * g.lda + k0 + k] : 0.f;
            }
        }
        if (g.op == 0) {   // B [N][K]
            #pragma unroll
            for (int i = 0; i < 4; i++) {
                int li = tid + 256 * i;
                int k = li & 15, n = li >> 4;
                int gn = n0 + n;
                Bs[n][k] = (gn < g.N) ? g.B[(size_t)gn * g.ldb + k0 + k] : 0.f;
            }
        } else {           // B [K][N]
            #pragma unroll
            for (int i = 0; i < 4; i++) {
                int li = tid + 256 * i;
                int n = li & 63, k = li >> 6;
                int gn = n0 + n;
                Bs[n][k] = (gn < g.N) ? g.B[(size_t)(k0 + k) * g.ldb + gn] : 0.f;
            }
        }
        __syncthreads();
        #pragma unroll
        for (int kk = 0; kk < 16; kk++) {
            float af[4], bf[4];
            #pragma unroll
            for (int r = 0; r < 4; r++) af[r] = As[ty * 4 + r][kk];
            #pragma unroll
            for (int c = 0; c < 4; c++) bf[c] = Bs[tx * 4 + c][kk];
            #pragma unroll
            for (int r = 0; r < 4; r++)
                #pragma unroll
                for (int c = 0; c < 4; c++)
                    acc[r][c] += af[r] * bf[c];
        }
        __syncthreads();
    }
    #pragma unroll
    for (int r = 0; r < 4; r++) {
        int gm = m0 + ty * 4 + r;
        if (gm >= g.M) continue;
        #pragma unroll
        for (int c = 0; c < 4; c++) {
            int gn = n0 + tx * 4 + c;
            if (gn < g.N)
                g.C[(size_t)gm * g.ldc + gn] = acc[r][c] + (g.bias ? g.bias[gn] : 0.f);
        }
    }
}

// ---------------- warp-parallel raw-input vectors + zero init of G ----------------
__global__ void __launch_bounds__(256) compose_small2(
    const float* __restrict__ finw, const float* __restrict__ finb,
    const float* __restrict__ fob,
    const float* __restrict__ inob, const float* __restrict__ outob,
    const float* __restrict__ W)
{
    if (blockIdx.x >= 204) {
        int i = (blockIdx.x - 204) * 256 + threadIdx.x;
        if (i < (UK * 32) / 4) ((float4*)g_G)[i] = make_float4(0.f, 0.f, 0.f, 0.f);
        return;
    }
    int gw = blockIdx.x * 8 + (threadIdx.x >> 5);
    int lane = threadIdx.x & 31;
    float acc = 0.f;
    if (gw < 1600) {
        int grp = gw / 320, j = gw - grp * 320;
        const float* row;
        const float* vec;
        float b;
        if (grp == 0)      { row = finw + (size_t)j * E_;            vec = inob;  b = finb[j]; }
        else if (grp == 1) { row = finw + (size_t)(E_ + j) * E_;     vec = inob;  b = finb[E_ + j]; }
        else if (grp == 2) { row = finw + (size_t)(E_ + j) * E_;     vec = outob; b = finb[E_ + j]; }
        else if (grp == 3) { row = finw + (size_t)(2 * E_ + j) * E_; vec = inob;  b = finb[2 * E_ + j]; }
        else               { row = finw + (size_t)(2 * E_ + j) * E_; vec = outob; b = finb[2 * E_ + j]; }
        #pragma unroll
        for (int i = 0; i < 10; i++) acc += row[lane + 32 * i] * vec[lane + 32 * i];
        #pragma unroll
        for (int o = 16; o; o >>= 1) acc += __shfl_xor_sync(0xffffffffu, acc, o);
        if (lane == 0) {
            acc += b;
            if (grp == 0)      g_cq[j] = acc;
            else if (grp == 1) g_ckin[j] = acc;
            else if (grp == 2) g_ckout[j] = acc;
            else if (grp == 3) g_cvin[j] = acc;
            else               g_cvout[j] = acc;
        }
    } else if (gw < 1632) {
        int o = gw - 1600;
        if (o < OUT_) {
            #pragma unroll
            for (int i = 0; i < 10; i++) {
                int k = lane + 32 * i;
                acc += fob[k] * W[k * OUT_ + o];
            }
        }
        #pragma unroll
        for (int oo = 16; oo; oo >>= 1) acc += __shfl_xor_sync(0xffffffffu, acc, oo);
        if (lane == 0) g_cW[o] = (o < OUT_) ? acc : 0.f;
    }
}

// ---------------- warp-parallel level-2 vectors ----------------
__global__ void __launch_bounds__(256) smallvec_kernel()
{
    int gw = blockIdx.x * 8 + (threadIdx.x >> 5);
    int lane = threadIdx.x & 31;
    float acc = 0.f;
    if (gw < 640) {                        // wv[i] = sum_j Mq[j][i] * ck[j]
        int side = gw >= 320;
        int i = gw - side * 320;
        const float* ck = side ? g_ckout : g_ckin;
        #pragma unroll
        for (int q = 0; q < 10; q++) {
            int j = lane + 32 * q;
            acc += g_Mq[(size_t)j * E_ + i] * ck[j];
        }
        #pragma unroll
        for (int o = 16; o; o >>= 1) acc += __shfl_xor_sync(0xffffffffu, acc, o);
        if (lane == 0) g_wv[gw] = acc;
    } else if (gw < 1280) {                // cqK[c] = sum_j cq[j] * MK[j][c]
        int side = gw >= 960;
        int c = gw - 640 - side * 320;
        const float* MK = side ? g_MKout : g_MKin;
        #pragma unroll
        for (int q = 0; q < 10; q++) {
            int j = lane + 32 * q;
            acc += g_cq[j] * MK[(size_t)j * E_ + c];
        }
        #pragma unroll
        for (int o = 16; o; o >>= 1) acc += __shfl_xor_sync(0xffffffffu, acc, o);
        if (lane == 0) g_cqK[side * 320 + c] = acc;
    } else if (gw < 1340) {                // G rows 640/641 = PW^T cv
        int r = gw - 1280;
        int row = r >= 30;
        int o = r - row * 30;
        const float* cv = row ? g_cvout : g_cvin;
        #pragma unroll
        for (int q = 0; q < 10; q++) {
            int c = lane + 32 * q;
            acc += cv[c] * g_PW[c * 32 + o];
        }
        #pragma unroll
        for (int oo = 16; oo; oo >>= 1) acc += __shfl_xor_sync(0xffffffffu, acc, oo);
        if (lane == 0) g_G[(640 + row) * 32 + o] = acc;
    } else if (gw < 1342) {                // wb = cq . ck
        int w = gw - 1340;
        const float* ck = w ? g_ckout : g_ckin;
        #pragma unroll
        for (int q = 0; q < 10; q++) {
            int j = lane + 32 * q;
            acc += g_cq[j] * ck[j];
        }
        #pragma unroll
        for (int o = 16; o; o >>= 1) acc += __shfl_xor_sync(0xffffffffu, acc, o);
        if (lane == 0) g_wb[w] = acc;
    }
}

// ---------------- per-node 5-head attention ----------------
__global__ void __launch_bounds__(256) attn_kernel(
    const int* __restrict__ in_idx, const int* __restrict__ out_idx,
    const float* __restrict__ in_b, const float* __restrict__ out_b)
{
    int n = blockIdx.x;
    int tid = threadIdx.x;
    extern __shared__ float sm[];
    float* Qs = sm;                 // 16*SR
    float* Ks = Qs + T_ * SR;
    float* Vs = Ks + T_ * SR;
    float* A0 = Vs + T_ * SR;       // 1280
    float* A1 = A0 + 1280;          // 1280
    __shared__ int rows[2][T_];

    if (tid < 32) {
        int s = tid >> 4, t = tid & 15;
        const int* idx = s ? out_idx : in_idx;
        rows[s][t] = t ? idx[n * D_ + t - 1] : n;
    }
    __syncthreads();

    for (int side = 0; side < 2; side++) {
        const float* bias = side ? out_b : in_b;
        int colbase = side * 960;
        for (int e = tid; e < 3840; e += 256) {
            int a = e / 1280, r = e - a * 1280;
            int t = r / 80, j = (r - t * 80) * 4;
            const float* src = g_XP + (size_t)rows[side][t] * 1920 + colbase + a * 320 + j;
            float4 v = *(const float4*)src;
            float4 bv = *(const float4*)(bias + a * 320 + j);
            v.x += bv.x; v.y += bv.y; v.z += bv.z; v.w += bv.w;
            float* dst = (a == 0 ? Qs : (a == 1 ? Ks : Vs)) + t * SR + j;
            *(float4*)dst = v;
        }
        __syncthreads();
        if (tid < 160) {
            int dh = tid & 1;
            int tile = tid >> 1;
            int h = tile >> 4, rem = tile & 15;
            int l0 = (rem >> 2) * 4, mm0 = (rem & 3) * 4;
            const float* qb = Qs + h * 64 + dh * 32;
            const float* kb = Ks + h * 64 + dh * 32;
            float acc[4][4] = {};
            #pragma unroll
            for (int d = 0; d < 32; d += 4) {
                float4 q[4], k4[4];
                #pragma unroll
                for (int r = 0; r < 4; r++) q[r] = *(const float4*)(qb + (l0 + r) * SR + d);
                #pragma unroll
                for (int c = 0; c < 4; c++) k4[c] = *(const float4*)(kb + (mm0 + c) * SR + d);
                #pragma unroll
                for (int r = 0; r < 4; r++)
                    #pragma unroll
                    for (int c = 0; c < 4; c++)
                        acc[r][c] += q[r].x * k4[c].x + q[r].y * k4[c].y
                                   + q[r].z * k4[c].z + q[r].w * k4[c].w;
            }
            float* dst = dh ? A1 : A0;
            #pragma unroll
            for (int r = 0; r < 4; r++)
                #pragma unroll
                for (int c = 0; c < 4; c++)
                    dst[(h * 16 + l0 + r) * 16 + mm0 + c] = acc[r][c];
        }
        __syncthreads();
        if (tid < 80) {
            int base = tid * 16;
            float v[16];
            float mx = -1e30f;
            #pragma unroll
            for (int m = 0; m < 16; m++) {
                v[m] = (A0[base + m] + A1[base + m]) * 0.125f;
                mx = fmaxf(mx, v[m]);
            }
            float ssum = 0.f;
            #pragma unroll
            for (int m = 0; m < 16; m++) { v[m] = __expf(v[m] - mx); ssum += v[m]; }
            float inv = 1.f / ssum;
            #pragma unroll
            for (int m = 0; m < 16; m++) A0[base + m] = v[m] * inv;
        }
        __syncthreads();
        float* ctxout = g_CTX + (size_t)n * 10240 + side * 5120;
        for (int u = tid; u < 640; u += 256) {
            int tp = u / 80;
            int j = (u - tp * 80) * 4;
            int h = j >> 6;
            int t0 = tp * 2;
            float ar0[16], ar1[16];
            #pragma unroll
            for (int q = 0; q < 4; q++) {
                *(float4*)&ar0[q * 4] = *(const float4*)&A0[(h * 16 + t0) * 16 + q * 4];
                *(float4*)&ar1[q * 4] = *(const float4*)&A0[(h * 16 + t0 + 1) * 16 + q * 4];
            }
            float4 acc0 = make_float4(0.f, 0.f, 0.f, 0.f);
            float4 acc1 = make_float4(0.f, 0.f, 0.f, 0.f);
            #pragma unroll
            for (int m = 0; m < 16; m++) {
                float4 v4 = *(const float4*)(Vs + m * SR + j);
                acc0.x += ar0[m] * v4.x; acc0.y += ar0[m] * v4.y;
                acc0.z += ar0[m] * v4.z; acc0.w += ar0[m] * v4.w;
                acc1.x += ar1[m] * v4.x; acc1.y += ar1[m] * v4.y;
                acc1.z += ar1[m] * v4.z; acc1.w += ar1[m] * v4.w;
            }
            *(float4*)(ctxout + (size_t)t0 * 320 + j) = acc0;
            *(float4*)(ctxout + (size_t)(t0 + 1) * 320 + j) = acc1;
            if (side == 0 && t0 == 0)   // compact copy of in-side token 0 for TT GEMM
                *(float4*)(g_C0 + (size_t)n * E_ + j) = acc0;
        }
        __syncthreads();
    }
}

// ---------------- final-layer scores + softmax + U (L2-served CTX) ----------------
__global__ void __launch_bounds__(256) finscore_kernel()
{
    int n = blockIdx.x;
    int tid = threadIdx.x, lane = tid & 31, w = tid >> 5;
    __shared__ float Ts[640];
    __shared__ float sA[32];
    __shared__ float sc[2];
    __shared__ float s_sain;
    const float* ctxn = g_CTX + (size_t)n * 10240;

    for (int i = tid; i < 640; i += 256) Ts[i] = g_TT[(size_t)n * 640 + i];
    __syncthreads();
    #pragma unroll
    for (int ii = 0; ii < 4; ii++) {
        int t = w * 4 + ii;
        int side = t >> 4, tok = t & 15;
        const float* cr = ctxn + side * 5120 + tok * 320;
        const float* tv = Ts + side * 320;
        float acc = 0.f;
        #pragma unroll
        for (int i = 0; i < 10; i++) acc += cr[lane + 32 * i] * tv[lane + 32 * i];
        #pragma unroll
        for (int o = 16; o; o >>= 1) acc += __shfl_xor_sync(0xffffffffu, acc, o);
        if (lane == 0) sA[t] = acc;
    }
    if (w < 2) {     // sc = ctx0 . w_side + b_side
        const float* cr = ctxn;
        const float* tv = g_wv + w * 320;
        float acc = 0.f;
        #pragma unroll
        for (int i = 0; i < 10; i++) acc += cr[lane + 32 * i] * tv[lane + 32 * i];
        #pragma unroll
        for (int o = 16; o; o >>= 1) acc += __shfl_xor_sync(0xffffffffu, acc, o);
        if (lane == 0) sc[w] = acc + g_wb[w];
    }
    __syncthreads();
    if (tid < 32) {  // softmax over 32 (scale = 320^-0.5)
        float v = (sA[tid] + sc[tid >> 4]) * 0.05590169943749474f;
        float mx = v;
        #pragma unroll
        for (int o = 16; o; o >>= 1) mx = fmaxf(mx, __shfl_xor_sync(0xffffffffu, mx, o));
        float e = __expf(v - mx);
        float ssum = e;
        #pragma unroll
        for (int o = 16; o; o >>= 1) ssum += __shfl_xor_sync(0xffffffffu, ssum, o);
        float a = e / ssum;
        sA[tid] = a;
        float ain = (tid < 16) ? a : 0.f;
        #pragma unroll
        for (int o = 16; o; o >>= 1) ain += __shfl_xor_sync(0xffffffffu, ain, o);
        if (tid == 0) s_sain = ain;
    }
    __syncthreads();
    float sain = s_sain;
    float* urow = g_U + (size_t)n * UK;
    if (tid < 160) {          // 160 float4 columns = 640 floats
        int side = tid >= 80;
        int off = (tid - side * 80) * 4;
        const float* cb = ctxn + side * 5120;
        const float* av = sA + side * 16;
        float4 acc = make_float4(0.f, 0.f, 0.f, 0.f);
        #pragma unroll
        for (int t = 0; t < 16; t++) {
            float a = av[t];
            float4 v = *(const float4*)(cb + t * 320 + off);
            acc.x += a * v.x; acc.y += a * v.y;
            acc.z += a * v.z; acc.w += a * v.w;
        }
        *(float4*)(urow + side * 320 + off) = acc;
    } else if (tid < 164) {   // tail 640..655
        int base = 640 + (tid - 160) * 4;
        float4 v = make_float4(0.f, 0.f, 0.f, 0.f);
        if (tid == 160) { v.x = sain; v.y = 1.f - sain; }
        *(float4*)(urow + base) = v;
    }
}

// ---------------- out = elu(U @ G + cW), 4 nodes per warp ----------------
__global__ void __launch_bounds__(256) outproj_kernel(float* __restrict__ out)
{
    extern __shared__ float sm2[];
    float* Gs = sm2;                 // 656*32
    float* Us = sm2 + UK * 32;       // 32*656
    int tid = threadIdx.x;
    int n0 = blockIdx.x * 32;

    for (int i = tid; i < (UK * 32) / 4; i += 256)
        ((float4*)Gs)[i] = ((const float4*)g_G)[i];
    const float* usrc = g_U + (size_t)n0 * UK;
    for (int i = tid; i < (32 * UK) / 4; i += 256)
        ((float4*)Us)[i] = ((const float4*)usrc)[i];
    __syncthreads();

    int w = tid >> 5, lane = tid & 31;
    const float* ur0 = Us + (w * 4 + 0) * UK;
    const float* ur1 = Us + (w * 4 + 1) * UK;
    const float* ur2 = Us + (w * 4 + 2) * UK;
    const float* ur3 = Us + (w * 4 + 3) * UK;
    float a0 = 0.f, a1 = 0.f, a2 = 0.f, a3 = 0.f;
    for (int i = 0; i < UK; i += 4) {
        float g0 = Gs[(i + 0) * 32 + lane];
        float g1 = Gs[(i + 1) * 32 + lane];
        float g2 = Gs[(i + 2) * 32 + lane];
        float g3 = Gs[(i + 3) * 32 + lane];
        float4 u0 = *(const float4*)(ur0 + i);
        float4 u1 = *(const float4*)(ur1 + i);
        float4 u2 = *(const float4*)(ur2 + i);
        float4 u3 = *(const float4*)(ur3 + i);
        a0 += u0.x * g0 + u0.y * g1 + u0.z * g2 + u0.w * g3;
        a1 += u1.x * g0 + u1.y * g1 + u1.z * g2 + u1.w * g3;
        a2 += u2.x * g0 + u2.y * g1 + u2.z * g2 + u2.w * g3;
        a3 += u3.x * g0 + u3.y * g1 + u3.z * g2 + u3.w * g3;
    }
    if (lane < OUT_) {
        float cw = g_cW[lane];
        int n = n0 + w * 4;
        float r0 = a0 + cw, r1 = a1 + cw, r2 = a2 + cw, r3 = a3 + cw;
        if (n + 0 < N_NODES) out[(n + 0) * OUT_ + lane] = r0 > 0.f ? r0 : expm1f(r0);
        if (n + 1 < N_NODES) out[(n + 1) * OUT_ + lane] = r1 > 0.f ? r1 : expm1f(r1);
        if (n + 2 < N_NODES) out[(n + 2) * OUT_ + lane] = r2 > 0.f ? r2 : expm1f(r2);
        if (n + 3 < N_NODES) out[(n + 3) * OUT_ + lane] = r3 > 0.f ? r3 : expm1f(r3);
    }
}

// ---------------- host ----------------
extern "C" void kernel_launch(void* const* d_in, const int* in_sizes, int n_in,
                              void* d_out, int out_size)
{
    const float* X         = (const float*)d_in[0];
    const int*   in_idx    = (const int*)  d_in[1];
    const int*   out_idx   = (const int*)  d_in[2];
    const float* in_Wq     = (const float*)d_in[3];
    const float* in_Wk     = (const float*)d_in[4];
    const float* in_Wv     = (const float*)d_in[5];
    const float* in_qkv_w  = (const float*)d_in[6];
    const float* in_qkv_b  = (const float*)d_in[7];
    const float* in_o_w    = (const float*)d_in[8];
    const float* in_o_b    = (const float*)d_in[9];
    const float* out_Wq    = (const float*)d_in[10];
    const float* out_Wk    = (const float*)d_in[11];
    const float* out_Wv    = (const float*)d_in[12];
    const float* out_qkv_w = (const float*)d_in[13];
    const float* out_qkv_b = (const float*)d_in[14];
    const float* out_o_w   = (const float*)d_in[15];
    const float* out_o_b   = (const float*)d_in[16];
    const float* fin_qkv_w = (const float*)d_in[17];
    const float* fin_qkv_b = (const float*)d_in[18];
    const float* fin_o_w   = (const float*)d_in[19];
    const float* fin_o_b   = (const float*)d_in[20];
    const float* Wmat      = (const float*)d_in[21];
    float* out = (float*)d_out;

    float *pMA, *pMq, *pMKin, *pMKout, *pMVin, *pMVout, *pPW, *pMqKcatT, *pG,
          *pXP, *pCTX, *pC0, *pTT, *pU, *pcqK;
    cudaGetSymbolAddress((void**)&pMA, g_MA);
    cudaGetSymbolAddress((void**)&pMq, g_Mq);
    cudaGetSymbolAddress((void**)&pMKin, g_MKin);
    cudaGetSymbolAddress((void**)&pMKout, g_MKout);
    cudaGetSymbolAddress((void**)&pMVin, g_MVin);
    cudaGetSymbolAddress((void**)&pMVout, g_MVout);
    cudaGetSymbolAddress((void**)&pPW, g_PW);
    cudaGetSymbolAddress((void**)&pMqKcatT, g_MqKcat);
    cudaGetSymbolAddress((void**)&pG, g_G);
    cudaGetSymbolAddress((void**)&pXP, g_XP);
    cudaGetSymbolAddress((void**)&pCTX, g_CTX);
    cudaGetSymbolAddress((void**)&pC0, g_C0);
    cudaGetSymbolAddress((void**)&pTT, g_TT);
    cudaGetSymbolAddress((void**)&pU, g_U);
    cudaGetSymbolAddress((void**)&pcqK, g_cqK);

    const int ATTN_SMEM = (3 * T_ * SR + 2 * 1280) * (int)sizeof(float);
    const int OUT_SMEM  = (2 * UK * 32) * (int)sizeof(float);
    const int TF_SMEM   = 2 * 2 * 128 * TFPAD * (int)sizeof(uint32_t);   // 81920
    cudaFuncSetAttribute(attn_kernel, cudaFuncAttributeMaxDynamicSharedMemorySize, ATTN_SMEM);
    cudaFuncSetAttribute(outproj_kernel, cudaFuncAttributeMaxDynamicSharedMemorySize, OUT_SMEM);
    cudaFuncSetAttribute(tf32gemm, cudaFuncAttributeMaxDynamicSharedMemorySize, TF_SMEM);

    // ---- launch 0: compose level 1 (batched, z=12) ----
    GemmBatch L1 = {};
    const float* Ws6[6] = {in_Wq, in_Wk, in_Wv, out_Wq, out_Wk, out_Wv};
    const float* Qw6[6] = {in_qkv_w, in_qkv_w + E_ * E_, in_qkv_w + 2 * E_ * E_,
                           out_qkv_w, out_qkv_w + E_ * E_, out_qkv_w + 2 * E_ * E_};
    for (int s = 0; s < 6; s++)
        L1.d[s] = {Qw6[s], Ws6[s], pMA + s * E_ * E_, nullptr,
                   E_, E_, E_, E_, E_, E_, 0};
    L1.d[6]  = {fin_qkv_w,               in_o_w,  pMq,    nullptr, E_, E_,  E_, E_, E_, E_, 1};
    L1.d[7]  = {fin_qkv_w + E_ * E_,     in_o_w,  pMKin,  nullptr, E_, E_,  E_, E_, E_, E_, 1};
    L1.d[8]  = {fin_qkv_w + E_ * E_,     out_o_w, pMKout, nullptr, E_, E_,  E_, E_, E_, E_, 1};
    L1.d[9]  = {fin_qkv_w + 2 * E_ * E_, in_o_w,  pMVin,  nullptr, E_, E_,  E_, E_, E_, E_, 1};
    L1.d[10] = {fin_qkv_w + 2 * E_ * E_, out_o_w, pMVout, nullptr, E_, E_,  E_, E_, E_, E_, 1};
    L1.d[11] = {fin_o_w,                 Wmat,    pPW,    nullptr, E_, OUT_, E_, E_, OUT_, 32, 2};
    sgemm64<<<dim3(5, 5, 12), 256>>>(L1);

    // ---- launch 1: XP = X @ MA^T  (tf32 tensor cores; needs only L1) ----
    GemmDesc xp = {X, pMA, pXP, nullptr, N_NODES, 1920, E_, E_, E_, 1920, 0};
    tf32gemm<<<dim3(15, 79), 256, TF_SMEM>>>(xp);

    // ---- launch 2: raw-input small vectors + zero G ----
    compose_small2<<<225, 256>>>(fin_qkv_w, fin_qkv_b, fin_o_b, in_o_b, out_o_b, Wmat);

    // ---- launch 3 (ncu capture slot): per-node attention ----
    attn_kernel<<<N_NODES, 256, ATTN_SMEM>>>(in_idx, out_idx, in_qkv_b, out_qkv_b);

    // ---- launch 4: compose level 2 (batched, z=4) ----
    GemmBatch L2 = {};
    L2.d[0] = {pMKin,  pMq, pMqKcatT,            nullptr, E_, E_,  E_, E_, E_, E_, 2};
    L2.d[1] = {pMKout, pMq, pMqKcatT + E_ * E_,  nullptr, E_, E_,  E_, E_, E_, E_, 2};
    L2.d[2] = {pMVin,  pPW, pG,                  nullptr, E_, OUT_, E_, E_, 32, 32, 2};
    L2.d[3] = {pMVout, pPW, pG + E_ * 32,        nullptr, E_, OUT_, E_, E_, 32, 32, 2};
    sgemm64<<<dim3(5, 5, 4), 256>>>(L2);

    // ---- launch 5: level-2 vectors ----
    smallvec_kernel<<<168, 256>>>();

    // ---- launch 6: [Tin|Tout] = C0 @ MqKcatT^T + cqK  (tf32 NT) ----
    GemmDesc tt = {pC0, pMqKcatT, pTT, pcqK, N_NODES, 640, E_, E_, E_, 640, 0};
    tf32gemm<<<dim3(5, 79), 256, TF_SMEM>>>(tt);

    // ---- launch 7: final scores + softmax + U ----
    finscore_kernel<<<N_NODES, 256>>>();

    // ---- launch 8: out = elu(U @ G + cW) ----
    outproj_kernel<<<(N_NODES + 31) / 32, 256, OUT_SMEM>>>(out);
}

// round 14
// speedup vs baseline: 1.4173x; 1.0564x over previous
#include <cuda_runtime.h>
#include <cstdint>
#include <cstddef>

#define N_NODES 10000
#define E_ 320
#define D_ 15
#define T_ 16
#define OUT_ 30
#define UK 656
#define SR 324
#define TFPAD 40

// ---------------- scratch (device globals) ----------------
__device__ float g_MA[6 * E_ * E_];        // composed QKV mats [1920][320]
__device__ float g_Mq[E_ * E_];
__device__ float g_MKin[E_ * E_];
__device__ float g_MKout[E_ * E_];
__device__ float g_MVin[E_ * E_];
__device__ float g_MVout[E_ * E_];
__device__ float g_PW[E_ * 32];            // fo_w^T @ W, padded to 32 cols
__device__ float g_MqKcat[640 * E_];       // [640][320] = [(Mq^T MKin)^T ; (Mq^T MKout)^T]
__device__ float g_G[UK * 32];             // [656][32] out-projection matrix
__device__ float g_cq[E_];
__device__ float g_ckin[E_];
__device__ float g_ckout[E_];
__device__ float g_cvin[E_];
__device__ float g_cvout[E_];
__device__ float g_cW[32];
__device__ float g_wv[640];                // [win | wout]
__device__ float g_wb[2];                  // bin, bout
__device__ float g_cqK[640];               // [cq@MKin | cq@MKout]
__device__ float g_XP[(size_t)N_NODES * 1920];
__device__ float g_CTX[(size_t)N_NODES * 10240];
__device__ float g_C0[(size_t)N_NODES * E_];   // compact copy of in-side ctx token 0
__device__ float g_TT[(size_t)N_NODES * 640];
__device__ float g_U[(size_t)(N_NODES + 32) * UK];

struct GemmDesc {
    const float* A; const float* B; float* C; const float* bias;
    int M, N, K, lda, ldb, ldc, op;  // op: 0=NT, 1=NN, 2=TN
};
struct GemmBatch { GemmDesc d[12]; };

// ---------------- async-copy + mma helpers ----------------
__device__ __forceinline__ void cp_async16(uint32_t dst, const void* src, int src_bytes) {
    asm volatile("cp.async.ca.shared.global [%0], [%1], 16, %2;"
                 :: "r"(dst), "l"(src), "r"(src_bytes) : "memory");
}
__device__ __forceinline__ void cp_commit() {
    asm volatile("cp.async.commit_group;" ::: "memory");
}
template <int N>
__device__ __forceinline__ void cp_wait() {
    asm volatile("cp.async.wait_group %0;" :: "n"(N) : "memory");
}

#define MMA_TF32(d, a, b) \
    asm volatile("mma.sync.aligned.m16n8k8.row.col.f32.tf32.tf32.f32 " \
        "{%0,%1,%2,%3}, {%4,%5,%6,%7}, {%8,%9}, {%0,%1,%2,%3};" \
        : "+f"((d)[0]), "+f"((d)[1]), "+f"((d)[2]), "+f"((d)[3]) \
        : "r"((a)[0]), "r"((a)[1]), "r"((a)[2]), "r"((a)[3]), \
          "r"((b)[0]), "r"((b)[1]))

// ---------------- tf32 tensor-core GEMM (NT): C[m][n] = sum_k A[m][k]*B[n][k] ----------------
__global__ void __launch_bounds__(256) tf32gemm(GemmDesc g)
{
    extern __shared__ uint32_t ts[];
    uint32_t* Asm = ts;                       // [2][128][TFPAD]
    uint32_t* Bsm = ts + 2 * 128 * TFPAD;     // [2][128][TFPAD]
    int tid = threadIdx.x, warp = tid >> 5, lane = tid & 31;
    int wm = (warp >> 2) * 64, wn = (warp & 3) * 32;
    int gr = lane >> 2, gc2 = (lane & 3) << 1;
    int m0 = blockIdx.y * 128, n0 = blockIdx.x * 128;

    float acc[4][4][4] = {};

    int fr = tid >> 1, fc = (tid & 1) << 4;
    const float* Ap = g.A + (size_t)(m0 + fr) * g.lda + fc;
    const float* Bp = g.B + (size_t)(n0 + fr) * g.ldb + fc;
    int asz = ((m0 + fr) < g.M) ? 16 : 0;

    uint32_t aBase = (uint32_t)__cvta_generic_to_shared(Asm);
    uint32_t bBase = (uint32_t)__cvta_generic_to_shared(Bsm);
    uint32_t aDst = aBase + (fr * TFPAD + fc) * 4;
    uint32_t bDst = bBase + (fr * TFPAD + fc) * 4;
    const uint32_t bufStride = 128 * TFPAD * 4;

    int niter = g.K / 32;
    #pragma unroll
    for (int i = 0; i < 4; i++) {
        cp_async16(aDst + i * 16, Ap + i * 4, asz);
        cp_async16(bDst + i * 16, Bp + i * 4, 16);
    }
    cp_commit();
    if (niter > 1) {
        #pragma unroll
        for (int i = 0; i < 4; i++) {
            cp_async16(aDst + bufStride + i * 16, Ap + 32 + i * 4, asz);
            cp_async16(bDst + bufStride + i * 16, Bp + 32 + i * 4, 16);
        }
        cp_commit();
    }

    for (int it = 0; it < niter; it++) {
        if (it + 1 < niter) cp_wait<1>(); else cp_wait<0>();
        __syncthreads();
        const uint32_t* Ab = Asm + (it & 1) * (128 * TFPAD);
        const uint32_t* Bb = Bsm + (it & 1) * (128 * TFPAD);
        #pragma unroll
        for (int ks = 0; ks < 32; ks += 8) {
            uint32_t af[4][4], bf[4][2];
            #pragma unroll
            for (int mt = 0; mt < 4; mt++) {
                int r = wm + mt * 16 + gr;
                uint2 v0 = *(const uint2*)&Ab[r * TFPAD + ks + gc2];
                uint2 v1 = *(const uint2*)&Ab[(r + 8) * TFPAD + ks + gc2];
                af[mt][0] = v0.x; af[mt][2] = v0.y;
                af[mt][1] = v1.x; af[mt][3] = v1.y;
            }
            #pragma unroll
            for (int nt = 0; nt < 4; nt++) {
                int c = wn + nt * 8 + gr;
                uint2 w0 = *(const uint2*)&Bb[c * TFPAD + ks + gc2];
                bf[nt][0] = w0.x; bf[nt][1] = w0.y;
            }
            #pragma unroll
            for (int mt = 0; mt < 4; mt++)
                #pragma unroll
                for (int nt = 0; nt < 4; nt++)
                    MMA_TF32(acc[mt][nt], af[mt], bf[nt]);
        }
        __syncthreads();
        if (it + 2 < niter) {
            int ko = (it + 2) * 32;
            uint32_t boff = (it & 1) * bufStride;
            #pragma unroll
            for (int i = 0; i < 4; i++) {
                cp_async16(aDst + boff + i * 16, Ap + ko + i * 4, asz);
                cp_async16(bDst + boff + i * 16, Bp + ko + i * 4, 16);
            }
            cp_commit();
        }
    }

    int gc = lane & 3;
    #pragma unroll
    for (int mt = 0; mt < 4; mt++) {
        int r = m0 + wm + mt * 16 + gr;
        bool ok0 = r < g.M, ok1 = (r + 8) < g.M;
        float* Crow0 = g.C + (size_t)r * g.ldc;
        #pragma unroll
        for (int nt = 0; nt < 4; nt++) {
            int c = n0 + wn + nt * 8 + 2 * gc;
            float b0 = 0.f, b1 = 0.f;
            if (g.bias) { b0 = g.bias[c]; b1 = g.bias[c + 1]; }
            if (ok0) {
                float2 v = make_float2(acc[mt][nt][0] + b0, acc[mt][nt][1] + b1);
                *(float2*)(Crow0 + c) = v;
            }
            if (ok1) {
                float2 v = make_float2(acc[mt][nt][2] + b0, acc[mt][nt][3] + b1);
                *(float2*)(Crow0 + (size_t)8 * g.ldc + c) = v;
            }
        }
    }
}

// ---------------- small batched GEMM: 64x64 tile, 4x4 micro ----------------
__global__ void __launch_bounds__(256) sgemm64(GemmBatch batch)
{
    GemmDesc g = batch.d[blockIdx.z];
    int m0 = blockIdx.y * 64, n0 = blockIdx.x * 64;
    if (m0 >= g.M || n0 >= g.N) return;
    __shared__ float As[64][17];
    __shared__ float Bs[64][17];
    int tid = threadIdx.x;
    int tx = tid & 15, ty = tid >> 4;
    float acc[4][4] = {};

    for (int k0 = 0; k0 < g.K; k0 += 16) {
        if (g.op == 2) {   // A [K][M]
            #pragma unroll
            for (int i = 0; i < 4; i++) {
                int li = tid + 256 * i;
                int m = li & 63, k = li >> 6;
                int gm = m0 + m;
                As[m][k] = (gm < g.M) ? g.A[(size_t)(k0 + k) * g.lda + gm] : 0.f;
            }
        } else {           // A [M][K]
            #pragma unroll
            for (int i = 0; i < 4; i++) {
                int li = tid + 256 * i;
                int k = li & 15, m = li >> 4;
                int gm = m0 + m;
                As[m][k] = (gm < g.M) ? g.A[(size_t)gm * g.lda + k0 + k] : 0.f;
            }
        }
        if (g.op == 0) {   // B [N][K]
            #pragma unroll
            for (int i = 0; i < 4; i++) {
                int li = tid + 256 * i;
                int k = li & 15, n = li >> 4;
                int gn = n0 + n;
                Bs[n][k] = (gn < g.N) ? g.B[(size_t)gn * g.ldb + k0 + k] : 0.f;
            }
        } else {           // B [K][N]
            #pragma unroll
            for (int i = 0; i < 4; i++) {
                int li = tid + 256 * i;
                int n = li & 63, k = li >> 6;
                int gn = n0 + n;
                Bs[n][k] = (gn < g.N) ? g.B[(size_t)(k0 + k) * g.ldb + gn] : 0.f;
            }
        }
        __syncthreads();
        #pragma unroll
        for (int kk = 0; kk < 16; kk++) {
            float af[4], bf[4];
            #pragma unroll
            for (int r = 0; r < 4; r++) af[r] = As[ty * 4 + r][kk];
            #pragma unroll
            for (int c = 0; c < 4; c++) bf[c] = Bs[tx * 4 + c][kk];
            #pragma unroll
            for (int r = 0; r < 4; r++)
                #pragma unroll
                for (int c = 0; c < 4; c++)
                    acc[r][c] += af[r] * bf[c];
        }
        __syncthreads();
    }
    #pragma unroll
    for (int r = 0; r < 4; r++) {
        int gm = m0 + ty * 4 + r;
        if (gm >= g.M) continue;
        #pragma unroll
        for (int c = 0; c < 4; c++) {
            int gn = n0 + tx * 4 + c;
            if (gn < g.N)
                g.C[(size_t)gm * g.ldc + gn] = acc[r][c] + (g.bias ? g.bias[gn] : 0.f);
        }
    }
}

// ---------------- warp-parallel raw-input vectors + zero init of G ----------------
__global__ void __launch_bounds__(256) compose_small2(
    const float* __restrict__ finw, const float* __restrict__ finb,
    const float* __restrict__ fob,
    const float* __restrict__ inob, const float* __restrict__ outob,
    const float* __restrict__ W)
{
    if (blockIdx.x >= 204) {
        int i = (blockIdx.x - 204) * 256 + threadIdx.x;
        if (i < (UK * 32) / 4) ((float4*)g_G)[i] = make_float4(0.f, 0.f, 0.f, 0.f);
        return;
    }
    int gw = blockIdx.x * 8 + (threadIdx.x >> 5);
    int lane = threadIdx.x & 31;
    float acc = 0.f;
    if (gw < 1600) {
        int grp = gw / 320, j = gw - grp * 320;
        const float* row;
        const float* vec;
        float b;
        if (grp == 0)      { row = finw + (size_t)j * E_;            vec = inob;  b = finb[j]; }
        else if (grp == 1) { row = finw + (size_t)(E_ + j) * E_;     vec = inob;  b = finb[E_ + j]; }
        else if (grp == 2) { row = finw + (size_t)(E_ + j) * E_;     vec = outob; b = finb[E_ + j]; }
        else if (grp == 3) { row = finw + (size_t)(2 * E_ + j) * E_; vec = inob;  b = finb[2 * E_ + j]; }
        else               { row = finw + (size_t)(2 * E_ + j) * E_; vec = outob; b = finb[2 * E_ + j]; }
        #pragma unroll
        for (int i = 0; i < 10; i++) acc += row[lane + 32 * i] * vec[lane + 32 * i];
        #pragma unroll
        for (int o = 16; o; o >>= 1) acc += __shfl_xor_sync(0xffffffffu, acc, o);
        if (lane == 0) {
            acc += b;
            if (grp == 0)      g_cq[j] = acc;
            else if (grp == 1) g_ckin[j] = acc;
            else if (grp == 2) g_ckout[j] = acc;
            else if (grp == 3) g_cvin[j] = acc;
            else               g_cvout[j] = acc;
        }
    } else if (gw < 1632) {
        int o = gw - 1600;
        if (o < OUT_) {
            #pragma unroll
            for (int i = 0; i < 10; i++) {
                int k = lane + 32 * i;
                acc += fob[k] * W[k * OUT_ + o];
            }
        }
        #pragma unroll
        for (int oo = 16; oo; oo >>= 1) acc += __shfl_xor_sync(0xffffffffu, acc, oo);
        if (lane == 0) g_cW[o] = (o < OUT_) ? acc : 0.f;
    }
}

// ---------------- warp-parallel level-2 vectors ----------------
__global__ void __launch_bounds__(256) smallvec_kernel()
{
    int gw = blockIdx.x * 8 + (threadIdx.x >> 5);
    int lane = threadIdx.x & 31;
    float acc = 0.f;
    if (gw < 640) {                        // wv[i] = sum_j Mq[j][i] * ck[j]
        int side = gw >= 320;
        int i = gw - side * 320;
        const float* ck = side ? g_ckout : g_ckin;
        #pragma unroll
        for (int q = 0; q < 10; q++) {
            int j = lane + 32 * q;
            acc += g_Mq[(size_t)j * E_ + i] * ck[j];
        }
        #pragma unroll
        for (int o = 16; o; o >>= 1) acc += __shfl_xor_sync(0xffffffffu, acc, o);
        if (lane == 0) g_wv[gw] = acc;
    } else if (gw < 1280) {                // cqK[c] = sum_j cq[j] * MK[j][c]
        int side = gw >= 960;
        int c = gw - 640 - side * 320;
        const float* MK = side ? g_MKout : g_MKin;
        #pragma unroll
        for (int q = 0; q < 10; q++) {
            int j = lane + 32 * q;
            acc += g_cq[j] * MK[(size_t)j * E_ + c];
        }
        #pragma unroll
        for (int o = 16; o; o >>= 1) acc += __shfl_xor_sync(0xffffffffu, acc, o);
        if (lane == 0) g_cqK[side * 320 + c] = acc;
    } else if (gw < 1340) {                // G rows 640/641 = PW^T cv
        int r = gw - 1280;
        int row = r >= 30;
        int o = r - row * 30;
        const float* cv = row ? g_cvout : g_cvin;
        #pragma unroll
        for (int q = 0; q < 10; q++) {
            int c = lane + 32 * q;
            acc += cv[c] * g_PW[c * 32 + o];
        }
        #pragma unroll
        for (int oo = 16; oo; oo >>= 1) acc += __shfl_xor_sync(0xffffffffu, acc, oo);
        if (lane == 0) g_G[(640 + row) * 32 + o] = acc;
    } else if (gw < 1342) {                // wb = cq . ck
        int w = gw - 1340;
        const float* ck = w ? g_ckout : g_ckin;
        #pragma unroll
        for (int q = 0; q < 10; q++) {
            int j = lane + 32 * q;
            acc += g_cq[j] * ck[j];
        }
        #pragma unroll
        for (int o = 16; o; o >>= 1) acc += __shfl_xor_sync(0xffffffffu, acc, o);
        if (lane == 0) g_wb[w] = acc;
    }
}

// ---------------- per-node 5-head attention (LDS-reduced phases) ----------------
__global__ void __launch_bounds__(256, 3) attn_kernel(
    const int* __restrict__ in_idx, const int* __restrict__ out_idx,
    const float* __restrict__ in_b, const float* __restrict__ out_b)
{
    int n = blockIdx.x;
    int tid = threadIdx.x;
    extern __shared__ float sm[];
    float* Qs = sm;                 // 16*SR
    float* Ks = Qs + T_ * SR;
    float* Vs = Ks + T_ * SR;
    float* A0 = Vs + T_ * SR;       // 1280
    float* A1 = A0 + 1280;          // 1280
    __shared__ int rows[2][T_];

    if (tid < 32) {
        int s = tid >> 4, t = tid & 15;
        const int* idx = s ? out_idx : in_idx;
        rows[s][t] = t ? idx[n * D_ + t - 1] : n;
    }
    __syncthreads();

    for (int side = 0; side < 2; side++) {
        const float* bias = side ? out_b : in_b;
        int colbase = side * 960;
        // gather Q,K,V rows + bias (float4)
        for (int e = tid; e < 3840; e += 256) {
            int a = e / 1280, r = e - a * 1280;
            int t = r / 80, j = (r - t * 80) * 4;
            const float* src = g_XP + (size_t)rows[side][t] * 1920 + colbase + a * 320 + j;
            float4 v = *(const float4*)src;
            float4 bv = *(const float4*)(bias + a * 320 + j);
            v.x += bv.x; v.y += bv.y; v.z += bv.z; v.w += bv.w;
            float* dst = (a == 0 ? Qs : (a == 1 ? Ks : Vs)) + t * SR + j;
            *(float4*)dst = v;
        }
        __syncthreads();
        // scores: 8l x 4m tiles, 2 d-halves -> 80 threads; K cached across 8 q-rows
        if (tid < 80) {
            int dh = tid & 1;
            int tile = tid >> 1;            // 0..39
            int h = tile >> 3, rem = tile & 7;
            int l0 = (rem >> 2) * 8, mm0 = (rem & 3) * 4;
            const float* qb = Qs + h * 64 + dh * 32;
            const float* kb = Ks + h * 64 + dh * 32;
            float acc[8][4] = {};
            #pragma unroll
            for (int d = 0; d < 32; d += 4) {
                float4 k4[4];
                #pragma unroll
                for (int c = 0; c < 4; c++) k4[c] = *(const float4*)(kb + (mm0 + c) * SR + d);
                #pragma unroll
                for (int r = 0; r < 8; r++) {
                    float4 q = *(const float4*)(qb + (l0 + r) * SR + d);
                    #pragma unroll
                    for (int c = 0; c < 4; c++)
                        acc[r][c] += q.x * k4[c].x + q.y * k4[c].y
                                   + q.z * k4[c].z + q.w * k4[c].w;
                }
            }
            float* dst = dh ? A1 : A0;
            #pragma unroll
            for (int r = 0; r < 8; r++)
                #pragma unroll
                for (int c = 0; c < 4; c++)
                    dst[(h * 16 + l0 + r) * 16 + mm0 + c] = acc[r][c];
        }
        __syncthreads();
        // softmax: 80 (h,l) rows of 16
        if (tid < 80) {
            int base = tid * 16;
            float v[16];
            float mx = -1e30f;
            #pragma unroll
            for (int m = 0; m < 16; m++) {
                v[m] = (A0[base + m] + A1[base + m]) * 0.125f;
                mx = fmaxf(mx, v[m]);
            }
            float ssum = 0.f;
            #pragma unroll
            for (int m = 0; m < 16; m++) { v[m] = __expf(v[m] - mx); ssum += v[m]; }
            float inv = 1.f / ssum;
            #pragma unroll
            for (int m = 0; m < 16; m++) A0[base + m] = v[m] * inv;
        }
        __syncthreads();
        // ctx = A @ V : 4 tokens per thread-unit, A-chunks amortized over 4 outputs
        float* ctxout = g_CTX + (size_t)n * 10240 + side * 5120;
        for (int u = tid; u < 320; u += 256) {
            int tg = u / 80;                   // token group 0..3 -> t = tg*4+r
            int j = (u - tg * 80) * 4;
            int h = j >> 6;
            int t0 = tg * 4;
            float acc[4][4] = {};
            #pragma unroll
            for (int mq = 0; mq < 4; mq++) {
                float ar[4][4];
                #pragma unroll
                for (int r = 0; r < 4; r++)
                    *(float4*)ar[r] = *(const float4*)&A0[(h * 16 + t0 + r) * 16 + mq * 4];
                #pragma unroll
                for (int mi = 0; mi < 4; mi++) {
                    float4 v4 = *(const float4*)(Vs + (mq * 4 + mi) * SR + j);
                    #pragma unroll
                    for (int r = 0; r < 4; r++) {
                        float a = ar[r][mi];
                        acc[r][0] += a * v4.x; acc[r][1] += a * v4.y;
                        acc[r][2] += a * v4.z; acc[r][3] += a * v4.w;
                    }
                }
            }
            #pragma unroll
            for (int r = 0; r < 4; r++)
                *(float4*)(ctxout + (size_t)(t0 + r) * 320 + j) = *(float4*)acc[r];
            if (side == 0 && tg == 0)   // in-side token 0 -> compact C0 for TT GEMM
                *(float4*)(g_C0 + (size_t)n * E_ + j) = *(float4*)acc[0];
        }
        __syncthreads();
    }
}

// ---------------- final-layer scores + softmax + U (L2-served CTX) ----------------
__global__ void __launch_bounds__(256) finscore_kernel()
{
    int n = blockIdx.x;
    int tid = threadIdx.x, lane = tid & 31, w = tid >> 5;
    __shared__ float Ts[640];
    __shared__ float sA[32];
    __shared__ float sc[2];
    __shared__ float s_sain;
    const float* ctxn = g_CTX + (size_t)n * 10240;

    for (int i = tid; i < 640; i += 256) Ts[i] = g_TT[(size_t)n * 640 + i];
    __syncthreads();
    #pragma unroll
    for (int ii = 0; ii < 4; ii++) {
        int t = w * 4 + ii;
        int side = t >> 4, tok = t & 15;
        const float* cr = ctxn + side * 5120 + tok * 320;
        const float* tv = Ts + side * 320;
        float acc = 0.f;
        #pragma unroll
        for (int i = 0; i < 10; i++) acc += cr[lane + 32 * i] * tv[lane + 32 * i];
        #pragma unroll
        for (int o = 16; o; o >>= 1) acc += __shfl_xor_sync(0xffffffffu, acc, o);
        if (lane == 0) sA[t] = acc;
    }
    if (w < 2) {     // sc = ctx0 . w_side + b_side
        const float* cr = ctxn;
        const float* tv = g_wv + w * 320;
        float acc = 0.f;
        #pragma unroll
        for (int i = 0; i < 10; i++) acc += cr[lane + 32 * i] * tv[lane + 32 * i];
        #pragma unroll
        for (int o = 16; o; o >>= 1) acc += __shfl_xor_sync(0xffffffffu, acc, o);
        if (lane == 0) sc[w] = acc + g_wb[w];
    }
    __syncthreads();
    if (tid < 32) {  // softmax over 32 (scale = 320^-0.5)
        float v = (sA[tid] + sc[tid >> 4]) * 0.05590169943749474f;
        float mx = v;
        #pragma unroll
        for (int o = 16; o; o >>= 1) mx = fmaxf(mx, __shfl_xor_sync(0xffffffffu, mx, o));
        float e = __expf(v - mx);
        float ssum = e;
        #pragma unroll
        for (int o = 16; o; o >>= 1) ssum += __shfl_xor_sync(0xffffffffu, ssum, o);
        float a = e / ssum;
        sA[tid] = a;
        float ain = (tid < 16) ? a : 0.f;
        #pragma unroll
        for (int o = 16; o; o >>= 1) ain += __shfl_xor_sync(0xffffffffu, ain, o);
        if (tid == 0) s_sain = ain;
    }
    __syncthreads();
    float sain = s_sain;
    float* urow = g_U + (size_t)n * UK;
    if (tid < 160) {          // 160 float4 columns = 640 floats
        int side = tid >= 80;
        int off = (tid - side * 80) * 4;
        const float* cb = ctxn + side * 5120;
        const float* av = sA + side * 16;
        float4 acc = make_float4(0.f, 0.f, 0.f, 0.f);
        #pragma unroll
        for (int t = 0; t < 16; t++) {
            float a = av[t];
            float4 v = *(const float4*)(cb + t * 320 + off);
            acc.x += a * v.x; acc.y += a * v.y;
            acc.z += a * v.z; acc.w += a * v.w;
        }
        *(float4*)(urow + side * 320 + off) = acc;
    } else if (tid < 164) {   // tail 640..655
        int base = 640 + (tid - 160) * 4;
        float4 v = make_float4(0.f, 0.f, 0.f, 0.f);
        if (tid == 160) { v.x = sain; v.y = 1.f - sain; }
        *(float4*)(urow + base) = v;
    }
}

// ---------------- out = elu(U @ G + cW), 4 nodes per warp ----------------
__global__ void __launch_bounds__(256) outproj_kernel(float* __restrict__ out)
{
    extern __shared__ float sm2[];
    float* Gs = sm2;                 // 656*32
    float* Us = sm2 + UK * 32;       // 32*656
    int tid = threadIdx.x;
    int n0 = blockIdx.x * 32;

    for (int i = tid; i < (UK * 32) / 4; i += 256)
        ((float4*)Gs)[i] = ((const float4*)g_G)[i];
    const float* usrc = g_U + (size_t)n0 * UK;
    for (int i = tid; i < (32 * UK) / 4; i += 256)
        ((float4*)Us)[i] = ((const float4*)usrc)[i];
    __syncthreads();

    int w = tid >> 5, lane = tid & 31;
    const float* ur0 = Us + (w * 4 + 0) * UK;
    const float* ur1 = Us + (w * 4 + 1) * UK;
    const float* ur2 = Us + (w * 4 + 2) * UK;
    const float* ur3 = Us + (w * 4 + 3) * UK;
    float a0 = 0.f, a1 = 0.f, a2 = 0.f, a3 = 0.f;
    for (int i = 0; i < UK; i += 4) {
        float g0 = Gs[(i + 0) * 32 + lane];
        float g1 = Gs[(i + 1) * 32 + lane];
        float g2 = Gs[(i + 2) * 32 + lane];
        float g3 = Gs[(i + 3) * 32 + lane];
        float4 u0 = *(const float4*)(ur0 + i);
        float4 u1 = *(const float4*)(ur1 + i);
        float4 u2 = *(const float4*)(ur2 + i);
        float4 u3 = *(const float4*)(ur3 + i);
        a0 += u0.x * g0 + u0.y * g1 + u0.z * g2 + u0.w * g3;
        a1 += u1.x * g0 + u1.y * g1 + u1.z * g2 + u1.w * g3;
        a2 += u2.x * g0 + u2.y * g1 + u2.z * g2 + u2.w * g3;
        a3 += u3.x * g0 + u3.y * g1 + u3.z * g2 + u3.w * g3;
    }
    if (lane < OUT_) {
        float cw = g_cW[lane];
        int n = n0 + w * 4;
        float r0 = a0 + cw, r1 = a1 + cw, r2 = a2 + cw, r3 = a3 + cw;
        if (n + 0 < N_NODES) out[(n + 0) * OUT_ + lane] = r0 > 0.f ? r0 : expm1f(r0);
        if (n + 1 < N_NODES) out[(n + 1) * OUT_ + lane] = r1 > 0.f ? r1 : expm1f(r1);
        if (n + 2 < N_NODES) out[(n + 2) * OUT_ + lane] = r2 > 0.f ? r2 : expm1f(r2);
        if (n + 3 < N_NODES) out[(n + 3) * OUT_ + lane] = r3 > 0.f ? r3 : expm1f(r3);
    }
}

// ---------------- host ----------------
extern "C" void kernel_launch(void* const* d_in, const int* in_sizes, int n_in,
                              void* d_out, int out_size)
{
    const float* X         = (const float*)d_in[0];
    const int*   in_idx    = (const int*)  d_in[1];
    const int*   out_idx   = (const int*)  d_in[2];
    const float* in_Wq     = (const float*)d_in[3];
    const float* in_Wk     = (const float*)d_in[4];
    const float* in_Wv     = (const float*)d_in[5];
    const float* in_qkv_w  = (const float*)d_in[6];
    const float* in_qkv_b  = (const float*)d_in[7];
    const float* in_o_w    = (const float*)d_in[8];
    const float* in_o_b    = (const float*)d_in[9];
    const float* out_Wq    = (const float*)d_in[10];
    const float* out_Wk    = (const float*)d_in[11];
    const float* out_Wv    = (const float*)d_in[12];
    const float* out_qkv_w = (const float*)d_in[13];
    const float* out_qkv_b = (const float*)d_in[14];
    const float* out_o_w   = (const float*)d_in[15];
    const float* out_o_b   = (const float*)d_in[16];
    const float* fin_qkv_w = (const float*)d_in[17];
    const float* fin_qkv_b = (const float*)d_in[18];
    const float* fin_o_w   = (const float*)d_in[19];
    const float* fin_o_b   = (const float*)d_in[20];
    const float* Wmat      = (const float*)d_in[21];
    float* out = (float*)d_out;

    float *pMA, *pMq, *pMKin, *pMKout, *pMVin, *pMVout, *pPW, *pMqKcatT, *pG,
          *pXP, *pCTX, *pC0, *pTT, *pU, *pcqK;
    cudaGetSymbolAddress((void**)&pMA, g_MA);
    cudaGetSymbolAddress((void**)&pMq, g_Mq);
    cudaGetSymbolAddress((void**)&pMKin, g_MKin);
    cudaGetSymbolAddress((void**)&pMKout, g_MKout);
    cudaGetSymbolAddress((void**)&pMVin, g_MVin);
    cudaGetSymbolAddress((void**)&pMVout, g_MVout);
    cudaGetSymbolAddress((void**)&pPW, g_PW);
    cudaGetSymbolAddress((void**)&pMqKcatT, g_MqKcat);
    cudaGetSymbolAddress((void**)&pG, g_G);
    cudaGetSymbolAddress((void**)&pXP, g_XP);
    cudaGetSymbolAddress((void**)&pCTX, g_CTX);
    cudaGetSymbolAddress((void**)&pC0, g_C0);
    cudaGetSymbolAddress((void**)&pTT, g_TT);
    cudaGetSymbolAddress((void**)&pU, g_U);
    cudaGetSymbolAddress((void**)&pcqK, g_cqK);

    const int ATTN_SMEM = (3 * T_ * SR + 2 * 1280) * (int)sizeof(float);
    const int OUT_SMEM  = (2 * UK * 32) * (int)sizeof(float);
    const int TF_SMEM   = 2 * 2 * 128 * TFPAD * (int)sizeof(uint32_t);   // 81920
    cudaFuncSetAttribute(attn_kernel, cudaFuncAttributeMaxDynamicSharedMemorySize, ATTN_SMEM);
    cudaFuncSetAttribute(outproj_kernel, cudaFuncAttributeMaxDynamicSharedMemorySize, OUT_SMEM);
    cudaFuncSetAttribute(tf32gemm, cudaFuncAttributeMaxDynamicSharedMemorySize, TF_SMEM);

    // ---- launch 0: compose level 1 (batched, z=12) ----
    GemmBatch L1 = {};
    const float* Ws6[6] = {in_Wq, in_Wk, in_Wv, out_Wq, out_Wk, out_Wv};
    const float* Qw6[6] = {in_qkv_w, in_qkv_w + E_ * E_, in_qkv_w + 2 * E_ * E_,
                           out_qkv_w, out_qkv_w + E_ * E_, out_qkv_w + 2 * E_ * E_};
    for (int s = 0; s < 6; s++)
        L1.d[s] = {Qw6[s], Ws6[s], pMA + s * E_ * E_, nullptr,
                   E_, E_, E_, E_, E_, E_, 0};
    L1.d[6]  = {fin_qkv_w,               in_o_w,  pMq,    nullptr, E_, E_,  E_, E_, E_, E_, 1};
    L1.d[7]  = {fin_qkv_w + E_ * E_,     in_o_w,  pMKin,  nullptr, E_, E_,  E_, E_, E_, E_, 1};
    L1.d[8]  = {fin_qkv_w + E_ * E_,     out_o_w, pMKout, nullptr, E_, E_,  E_, E_, E_, E_, 1};
    L1.d[9]  = {fin_qkv_w + 2 * E_ * E_, in_o_w,  pMVin,  nullptr, E_, E_,  E_, E_, E_, E_, 1};
    L1.d[10] = {fin_qkv_w + 2 * E_ * E_, out_o_w, pMVout, nullptr, E_, E_,  E_, E_, E_, E_, 1};
    L1.d[11] = {fin_o_w,                 Wmat,    pPW,    nullptr, E_, OUT_, E_, E_, OUT_, 32, 2};
    sgemm64<<<dim3(5, 5, 12), 256>>>(L1);

    // ---- launch 1: XP = X @ MA^T  (tf32 tensor cores; needs only L1) ----
    GemmDesc xp = {X, pMA, pXP, nullptr, N_NODES, 1920, E_, E_, E_, 1920, 0};
    tf32gemm<<<dim3(15, 79), 256, TF_SMEM>>>(xp);

    // ---- launch 2: raw-input small vectors + zero G ----
    compose_small2<<<225, 256>>>(fin_qkv_w, fin_qkv_b, fin_o_b, in_o_b, out_o_b, Wmat);

    // ---- launch 3 (ncu capture slot): per-node attention ----
    attn_kernel<<<N_NODES, 256, ATTN_SMEM>>>(in_idx, out_idx, in_qkv_b, out_qkv_b);

    // ---- launch 4: compose level 2 (batched, z=4) ----
    GemmBatch L2 = {};
    L2.d[0] = {pMKin,  pMq, pMqKcatT,            nullptr, E_, E_,  E_, E_, E_, E_, 2};
    L2.d[1] = {pMKout, pMq, pMqKcatT + E_ * E_,  nullptr, E_, E_,  E_, E_, E_, E_, 2};
    L2.d[2] = {pMVin,  pPW, pG,                  nullptr, E_, OUT_, E_, E_, 32, 32, 2};
    L2.d[3] = {pMVout, pPW, pG + E_ * 32,        nullptr, E_, OUT_, E_, E_, 32, 32, 2};
    sgemm64<<<dim3(5, 5, 4), 256>>>(L2);

    // ---- launch 5: level-2 vectors ----
    smallvec_kernel<<<168, 256>>>();

    // ---- launch 6: [Tin|Tout] = C0 @ MqKcatT^T + cqK  (tf32 NT) ----
    GemmDesc tt = {pC0, pMqKcatT, pTT, pcqK, N_NODES, 640, E_, E_, E_, 640, 0};
    tf32gemm<<<dim3(5, 79), 256, TF_SMEM>>>(tt);

    // ---- launch 7: final scores + softmax + U ----
    finscore_kernel<<<N_NODES, 256>>>();

    // ---- launch 8: out = elu(U @ G + cW) ----
    outproj_kernel<<<(N_NODES + 31) / 32, 256, OUT_SMEM>>>(out);
}

// round 15
// speedup vs baseline: 1.6059x; 1.1331x over previous
#include <cuda_runtime.h>
#include <cstdint>
#include <cstddef>

#define N_NODES 10000
#define E_ 320
#define D_ 15
#define T_ 16
#define OUT_ 30
#define UK 656
#define SR 328
#define TFPAD 40

// ---------------- scratch (device globals) ----------------
__device__ float g_MA[6 * E_ * E_];        // composed QKV mats [1920][320]
__device__ float g_Mq[E_ * E_];
__device__ float g_MKin[E_ * E_];
__device__ float g_MKout[E_ * E_];
__device__ float g_MVin[E_ * E_];
__device__ float g_MVout[E_ * E_];
__device__ float g_PW[E_ * 32];            // fo_w^T @ W, padded to 32 cols
__device__ float g_MqKcat[640 * E_];       // [640][320] = [(Mq^T MKin)^T ; (Mq^T MKout)^T]
__device__ float g_G[UK * 32];             // [656][32] out-projection matrix
__device__ float g_cq[E_];
__device__ float g_ckin[E_];
__device__ float g_ckout[E_];
__device__ float g_cvin[E_];
__device__ float g_cvout[E_];
__device__ float g_cW[32];
__device__ float g_wv[640];                // [win | wout]
__device__ float g_wb[2];                  // bin, bout
__device__ float g_cqK[640];               // [cq@MKin | cq@MKout]
__device__ float g_XP[(size_t)N_NODES * 1920];
__device__ float g_CTX[(size_t)N_NODES * 10240];
__device__ float g_C0[(size_t)N_NODES * E_];   // compact copy of in-side ctx token 0
__device__ float g_TT[(size_t)N_NODES * 640];
__device__ float g_U[(size_t)(N_NODES + 32) * UK];

struct GemmDesc {
    const float* A; const float* B; float* C; const float* bias;
    int M, N, K, lda, ldb, ldc, op;  // op: 0=NT, 1=NN, 2=TN
};
struct GemmBatch { GemmDesc d[12]; };

// ---------------- async-copy + mma helpers ----------------
__device__ __forceinline__ void cp_async16(uint32_t dst, const void* src, int src_bytes) {
    asm volatile("cp.async.ca.shared.global [%0], [%1], 16, %2;"
                 :: "r"(dst), "l"(src), "r"(src_bytes) : "memory");
}
__device__ __forceinline__ void cp_commit() {
    asm volatile("cp.async.commit_group;" ::: "memory");
}
template <int N>
__device__ __forceinline__ void cp_wait() {
    asm volatile("cp.async.wait_group %0;" :: "n"(N) : "memory");
}

#define MMA_TF32(d, a, b) \
    asm volatile("mma.sync.aligned.m16n8k8.row.col.f32.tf32.tf32.f32 " \
        "{%0,%1,%2,%3}, {%4,%5,%6,%7}, {%8,%9}, {%0,%1,%2,%3};" \
        : "+f"((d)[0]), "+f"((d)[1]), "+f"((d)[2]), "+f"((d)[3]) \
        : "r"((a)[0]), "r"((a)[1]), "r"((a)[2]), "r"((a)[3]), \
          "r"((b)[0]), "r"((b)[1]))

// ---------------- tf32 tensor-core GEMM (NT): C[m][n] = sum_k A[m][k]*B[n][k] ----------------
__global__ void __launch_bounds__(256) tf32gemm(GemmDesc g)
{
    extern __shared__ uint32_t ts[];
    uint32_t* Asm = ts;                       // [2][128][TFPAD]
    uint32_t* Bsm = ts + 2 * 128 * TFPAD;     // [2][128][TFPAD]
    int tid = threadIdx.x, warp = tid >> 5, lane = tid & 31;
    int wm = (warp >> 2) * 64, wn = (warp & 3) * 32;
    int gr = lane >> 2, gc2 = (lane & 3) << 1;
    int m0 = blockIdx.y * 128, n0 = blockIdx.x * 128;

    float acc[4][4][4] = {};

    int fr = tid >> 1, fc = (tid & 1) << 4;
    const float* Ap = g.A + (size_t)(m0 + fr) * g.lda + fc;
    const float* Bp = g.B + (size_t)(n0 + fr) * g.ldb + fc;
    int asz = ((m0 + fr) < g.M) ? 16 : 0;

    uint32_t aBase = (uint32_t)__cvta_generic_to_shared(Asm);
    uint32_t bBase = (uint32_t)__cvta_generic_to_shared(Bsm);
    uint32_t aDst = aBase + (fr * TFPAD + fc) * 4;
    uint32_t bDst = bBase + (fr * TFPAD + fc) * 4;
    const uint32_t bufStride = 128 * TFPAD * 4;

    int niter = g.K / 32;
    #pragma unroll
    for (int i = 0; i < 4; i++) {
        cp_async16(aDst + i * 16, Ap + i * 4, asz);
        cp_async16(bDst + i * 16, Bp + i * 4, 16);
    }
    cp_commit();
    if (niter > 1) {
        #pragma unroll
        for (int i = 0; i < 4; i++) {
            cp_async16(aDst + bufStride + i * 16, Ap + 32 + i * 4, asz);
            cp_async16(bDst + bufStride + i * 16, Bp + 32 + i * 4, 16);
        }
        cp_commit();
    }

    for (int it = 0; it < niter; it++) {
        if (it + 1 < niter) cp_wait<1>(); else cp_wait<0>();
        __syncthreads();
        const uint32_t* Ab = Asm + (it & 1) * (128 * TFPAD);
        const uint32_t* Bb = Bsm + (it & 1) * (128 * TFPAD);
        #pragma unroll
        for (int ks = 0; ks < 32; ks += 8) {
            uint32_t af[4][4], bf[4][2];
            #pragma unroll
            for (int mt = 0; mt < 4; mt++) {
                int r = wm + mt * 16 + gr;
                uint2 v0 = *(const uint2*)&Ab[r * TFPAD + ks + gc2];
                uint2 v1 = *(const uint2*)&Ab[(r + 8) * TFPAD + ks + gc2];
                af[mt][0] = v0.x; af[mt][2] = v0.y;
                af[mt][1] = v1.x; af[mt][3] = v1.y;
            }
            #pragma unroll
            for (int nt = 0; nt < 4; nt++) {
                int c = wn + nt * 8 + gr;
                uint2 w0 = *(const uint2*)&Bb[c * TFPAD + ks + gc2];
                bf[nt][0] = w0.x; bf[nt][1] = w0.y;
            }
            #pragma unroll
            for (int mt = 0; mt < 4; mt++)
                #pragma unroll
                for (int nt = 0; nt < 4; nt++)
                    MMA_TF32(acc[mt][nt], af[mt], bf[nt]);
        }
        __syncthreads();
        if (it + 2 < niter) {
            int ko = (it + 2) * 32;
            uint32_t boff = (it & 1) * bufStride;
            #pragma unroll
            for (int i = 0; i < 4; i++) {
                cp_async16(aDst + boff + i * 16, Ap + ko + i * 4, asz);
                cp_async16(bDst + boff + i * 16, Bp + ko + i * 4, 16);
            }
            cp_commit();
        }
    }

    int gc = lane & 3;
    #pragma unroll
    for (int mt = 0; mt < 4; mt++) {
        int r = m0 + wm + mt * 16 + gr;
        bool ok0 = r < g.M, ok1 = (r + 8) < g.M;
        float* Crow0 = g.C + (size_t)r * g.ldc;
        #pragma unroll
        for (int nt = 0; nt < 4; nt++) {
            int c = n0 + wn + nt * 8 + 2 * gc;
            float b0 = 0.f, b1 = 0.f;
            if (g.bias) { b0 = g.bias[c]; b1 = g.bias[c + 1]; }
            if (ok0) {
                float2 v = make_float2(acc[mt][nt][0] + b0, acc[mt][nt][1] + b1);
                *(float2*)(Crow0 + c) = v;
            }
            if (ok1) {
                float2 v = make_float2(acc[mt][nt][2] + b0, acc[mt][nt][3] + b1);
                *(float2*)(Crow0 + (size_t)8 * g.ldc + c) = v;
            }
        }
    }
}

// ---------------- small batched GEMM: 64x64 tile, 4x4 micro ----------------
__global__ void __launch_bounds__(256) sgemm64(GemmBatch batch)
{
    GemmDesc g = batch.d[blockIdx.z];
    int m0 = blockIdx.y * 64, n0 = blockIdx.x * 64;
    if (m0 >= g.M || n0 >= g.N) return;
    __shared__ float As[64][17];
    __shared__ float Bs[64][17];
    int tid = threadIdx.x;
    int tx = tid & 15, ty = tid >> 4;
    float acc[4][4] = {};

    for (int k0 = 0; k0 < g.K; k0 += 16) {
        if (g.op == 2) {   // A [K][M]
            #pragma unroll
            for (int i = 0; i < 4; i++) {
                int li = tid + 256 * i;
                int m = li & 63, k = li >> 6;
                int gm = m0 + m;
                As[m][k] = (gm < g.M) ? g.A[(size_t)(k0 + k) * g.lda + gm] : 0.f;
            }
        } else {           // A [M][K]
            #pragma unroll
            for (int i = 0; i < 4; i++) {
                int li = tid + 256 * i;
                int k = li & 15, m = li >> 4;
                int gm = m0 + m;
                As[m][k] = (gm < g.M) ? g.A[(size_t)gm * g.lda + k0 + k] : 0.f;
            }
        }
        if (g.op == 0) {   // B [N][K]
            #pragma unroll
            for (int i = 0; i < 4; i++) {
                int li = tid + 256 * i;
                int k = li & 15, n = li >> 4;
                int gn = n0 + n;
                Bs[n][k] = (gn < g.N) ? g.B[(size_t)gn * g.ldb + k0 + k] : 0.f;
            }
        } else {           // B [K][N]
            #pragma unroll
            for (int i = 0; i < 4; i++) {
                int li = tid + 256 * i;
                int n = li & 63, k = li >> 6;
                int gn = n0 + n;
                Bs[n][k] = (gn < g.N) ? g.B[(size_t)(k0 + k) * g.ldb + gn] : 0.f;
            }
        }
        __syncthreads();
        #pragma unroll
        for (int kk = 0; kk < 16; kk++) {
            float af[4], bf[4];
            #pragma unroll
            for (int r = 0; r < 4; r++) af[r] = As[ty * 4 + r][kk];
            #pragma unroll
            for (int c = 0; c < 4; c++) bf[c] = Bs[tx * 4 + c][kk];
            #pragma unroll
            for (int r = 0; r < 4; r++)
                #pragma unroll
                for (int c = 0; c < 4; c++)
                    acc[r][c] += af[r] * bf[c];
        }
        __syncthreads();
    }
    #pragma unroll
    for (int r = 0; r < 4; r++) {
        int gm = m0 + ty * 4 + r;
        if (gm >= g.M) continue;
        #pragma unroll
        for (int c = 0; c < 4; c++) {
            int gn = n0 + tx * 4 + c;
            if (gn < g.N)
                g.C[(size_t)gm * g.ldc + gn] = acc[r][c] + (g.bias ? g.bias[gn] : 0.f);
        }
    }
}

// ---------------- warp-parallel raw-input vectors + zero init of G ----------------
__global__ void __launch_bounds__(256) compose_small2(
    const float* __restrict__ finw, const float* __restrict__ finb,
    const float* __restrict__ fob,
    const float* __restrict__ inob, const float* __restrict__ outob,
    const float* __restrict__ W)
{
    if (blockIdx.x >= 204) {
        int i = (blockIdx.x - 204) * 256 + threadIdx.x;
        if (i < (UK * 32) / 4) ((float4*)g_G)[i] = make_float4(0.f, 0.f, 0.f, 0.f);
        return;
    }
    int gw = blockIdx.x * 8 + (threadIdx.x >> 5);
    int lane = threadIdx.x & 31;
    float acc = 0.f;
    if (gw < 1600) {
        int grp = gw / 320, j = gw - grp * 320;
        const float* row;
        const float* vec;
        float b;
        if (grp == 0)      { row = finw + (size_t)j * E_;            vec = inob;  b = finb[j]; }
        else if (grp == 1) { row = finw + (size_t)(E_ + j) * E_;     vec = inob;  b = finb[E_ + j]; }
        else if (grp == 2) { row = finw + (size_t)(E_ + j) * E_;     vec = outob; b = finb[E_ + j]; }
        else if (grp == 3) { row = finw + (size_t)(2 * E_ + j) * E_; vec = inob;  b = finb[2 * E_ + j]; }
        else               { row = finw + (size_t)(2 * E_ + j) * E_; vec = outob; b = finb[2 * E_ + j]; }
        #pragma unroll
        for (int i = 0; i < 10; i++) acc += row[lane + 32 * i] * vec[lane + 32 * i];
        #pragma unroll
        for (int o = 16; o; o >>= 1) acc += __shfl_xor_sync(0xffffffffu, acc, o);
        if (lane == 0) {
            acc += b;
            if (grp == 0)      g_cq[j] = acc;
            else if (grp == 1) g_ckin[j] = acc;
            else if (grp == 2) g_ckout[j] = acc;
            else if (grp == 3) g_cvin[j] = acc;
            else               g_cvout[j] = acc;
        }
    } else if (gw < 1632) {
        int o = gw - 1600;
        if (o < OUT_) {
            #pragma unroll
            for (int i = 0; i < 10; i++) {
                int k = lane + 32 * i;
                acc += fob[k] * W[k * OUT_ + o];
            }
        }
        #pragma unroll
        for (int oo = 16; oo; oo >>= 1) acc += __shfl_xor_sync(0xffffffffu, acc, oo);
        if (lane == 0) g_cW[o] = (o < OUT_) ? acc : 0.f;
    }
}

// ---------------- warp-parallel level-2 vectors ----------------
__global__ void __launch_bounds__(256) smallvec_kernel()
{
    int gw = blockIdx.x * 8 + (threadIdx.x >> 5);
    int lane = threadIdx.x & 31;
    float acc = 0.f;
    if (gw < 640) {                        // wv[i] = sum_j Mq[j][i] * ck[j]
        int side = gw >= 320;
        int i = gw - side * 320;
        const float* ck = side ? g_ckout : g_ckin;
        #pragma unroll
        for (int q = 0; q < 10; q++) {
            int j = lane + 32 * q;
            acc += g_Mq[(size_t)j * E_ + i] * ck[j];
        }
        #pragma unroll
        for (int o = 16; o; o >>= 1) acc += __shfl_xor_sync(0xffffffffu, acc, o);
        if (lane == 0) g_wv[gw] = acc;
    } else if (gw < 1280) {                // cqK[c] = sum_j cq[j] * MK[j][c]
        int side = gw >= 960;
        int c = gw - 640 - side * 320;
        const float* MK = side ? g_MKout : g_MKin;
        #pragma unroll
        for (int q = 0; q < 10; q++) {
            int j = lane + 32 * q;
            acc += g_cq[j] * MK[(size_t)j * E_ + c];
        }
        #pragma unroll
        for (int o = 16; o; o >>= 1) acc += __shfl_xor_sync(0xffffffffu, acc, o);
        if (lane == 0) g_cqK[side * 320 + c] = acc;
    } else if (gw < 1340) {                // G rows 640/641 = PW^T cv
        int r = gw - 1280;
        int row = r >= 30;
        int o = r - row * 30;
        const float* cv = row ? g_cvout : g_cvin;
        #pragma unroll
        for (int q = 0; q < 10; q++) {
            int c = lane + 32 * q;
            acc += cv[c] * g_PW[c * 32 + o];
        }
        #pragma unroll
        for (int oo = 16; oo; oo >>= 1) acc += __shfl_xor_sync(0xffffffffu, acc, oo);
        if (lane == 0) g_G[(640 + row) * 32 + o] = acc;
    } else if (gw < 1342) {                // wb = cq . ck
        int w = gw - 1340;
        const float* ck = w ? g_ckout : g_ckin;
        #pragma unroll
        for (int q = 0; q < 10; q++) {
            int j = lane + 32 * q;
            acc += g_cq[j] * ck[j];
        }
        #pragma unroll
        for (int o = 16; o; o >>= 1) acc += __shfl_xor_sync(0xffffffffu, acc, o);
        if (lane == 0) g_wb[w] = acc;
    }
}

// ---------------- per-node 5-head attention (tf32 tensor-core scores+ctx) ----------------
// Smem: Qs/Ks/Vs [16][SR] (SR=328: ctx V-fragment loads conflict-free), Ss [5][16][16].
// Scores: warp h<5 computes S_h = Q_h K_h^T via m16n8k8 (8 k-steps x 2 n-tiles).
// Ctx: 10 col-slices of 32 across 8 warps; C = P_h @ V (2 k-steps x 4 n-tiles per slice).
__global__ void __launch_bounds__(256, 3) attn_kernel(
    const int* __restrict__ in_idx, const int* __restrict__ out_idx,
    const float* __restrict__ in_b, const float* __restrict__ out_b)
{
    int n = blockIdx.x;
    int tid = threadIdx.x, warp = tid >> 5, lane = tid & 31;
    int gr = lane >> 2, gc = lane & 3;
    extern __shared__ float sm[];
    float* Qs = sm;                 // 16*SR
    float* Ks = Qs + T_ * SR;
    float* Vs = Ks + T_ * SR;
    float* Ss = Vs + T_ * SR;       // 5*16*16 = 1280 (scores -> probs)
    __shared__ int rows[2][T_];

    if (tid < 32) {
        int s = tid >> 4, t = tid & 15;
        const int* idx = s ? out_idx : in_idx;
        rows[s][t] = t ? idx[n * D_ + t - 1] : n;
    }
    __syncthreads();

    for (int side = 0; side < 2; side++) {
        const float* bias = side ? out_b : in_b;
        int colbase = side * 960;
        // gather Q,K,V rows + bias (float4)
        for (int e = tid; e < 3840; e += 256) {
            int a = e / 1280, r = e - a * 1280;
            int t = r / 80, j = (r - t * 80) * 4;
            const float* src = g_XP + (size_t)rows[side][t] * 1920 + colbase + a * 320 + j;
            float4 v = *(const float4*)src;
            float4 bv = *(const float4*)(bias + a * 320 + j);
            v.x += bv.x; v.y += bv.y; v.z += bv.z; v.w += bv.w;
            float* dst = (a == 0 ? Qs : (a == 1 ? Ks : Vs)) + t * SR + j;
            *(float4*)dst = v;
        }
        __syncthreads();
        // scores: warp h (<5): S_h[16][16] = Q_h @ K_h^T, tf32 mma
        if (warp < 5) {
            int hb = warp * 64;
            float acc[2][4] = {};
            #pragma unroll
            for (int k0 = 0; k0 < 64; k0 += 8) {
                uint32_t a[4], b0[2], b1[2];
                const float* qb = Qs + hb + k0 + gc;
                a[0] = __float_as_uint(qb[gr * SR]);
                a[1] = __float_as_uint(qb[(gr + 8) * SR]);
                a[2] = __float_as_uint(qb[gr * SR + 4]);
                a[3] = __float_as_uint(qb[(gr + 8) * SR + 4]);
                const float* kb = Ks + hb + k0 + gc;
                b0[0] = __float_as_uint(kb[gr * SR]);
                b0[1] = __float_as_uint(kb[gr * SR + 4]);
                b1[0] = __float_as_uint(kb[(gr + 8) * SR]);
                b1[1] = __float_as_uint(kb[(gr + 8) * SR + 4]);
                MMA_TF32(acc[0], a, b0);
                MMA_TF32(acc[1], a, b1);
            }
            float* srow = Ss + warp * 256;
            #pragma unroll
            for (int nt = 0; nt < 2; nt++) {
                *(float2*)&srow[gr * 16 + nt * 8 + 2 * gc] =
                    make_float2(acc[nt][0], acc[nt][1]);
                *(float2*)&srow[(gr + 8) * 16 + nt * 8 + 2 * gc] =
                    make_float2(acc[nt][2], acc[nt][3]);
            }
        }
        __syncthreads();
        // softmax: 80 (h,l) rows of 16, scale 1/8
        if (tid < 80) {
            float* row = Ss + tid * 16;
            float v[16];
            float mx = -1e30f;
            #pragma unroll
            for (int m = 0; m < 16; m++) {
                v[m] = row[m] * 0.125f;
                mx = fmaxf(mx, v[m]);
            }
            float ssum = 0.f;
            #pragma unroll
            for (int m = 0; m < 16; m++) { v[m] = __expf(v[m] - mx); ssum += v[m]; }
            float inv = 1.f / ssum;
            #pragma unroll
            for (int m = 0; m < 16; m++) row[m] = v[m] * inv;
        }
        __syncthreads();
        // ctx = P @ V via tf32 mma: 10 slices of 32 cols over 8 warps
        float* ctxout = g_CTX + (size_t)n * 10240 + side * 5120;
        for (int sl = warp; sl < 10; sl += 8) {
            int ns = sl * 32;
            int h = ns >> 6;
            const float* P = Ss + h * 256;
            float acc[4][4] = {};
            #pragma unroll
            for (int k0 = 0; k0 < 16; k0 += 8) {
                uint32_t a[4];
                a[0] = __float_as_uint(P[gr * 16 + k0 + gc]);
                a[1] = __float_as_uint(P[(gr + 8) * 16 + k0 + gc]);
                a[2] = __float_as_uint(P[gr * 16 + k0 + gc + 4]);
                a[3] = __float_as_uint(P[(gr + 8) * 16 + k0 + gc + 4]);
                #pragma unroll
                for (int nt = 0; nt < 4; nt++) {
                    uint32_t b[2];
                    const float* vb = Vs + ns + nt * 8 + gr;
                    b[0] = __float_as_uint(vb[(k0 + gc) * SR]);
                    b[1] = __float_as_uint(vb[(k0 + gc + 4) * SR]);
                    MMA_TF32(acc[nt], a, b);
                }
            }
            #pragma unroll
            for (int nt = 0; nt < 4; nt++) {
                int c = ns + nt * 8 + 2 * gc;
                *(float2*)(ctxout + (size_t)gr * 320 + c) =
                    make_float2(acc[nt][0], acc[nt][1]);
                *(float2*)(ctxout + (size_t)(gr + 8) * 320 + c) =
                    make_float2(acc[nt][2], acc[nt][3]);
                if (side == 0 && gr == 0)
                    *(float2*)(g_C0 + (size_t)n * E_ + c) =
                        make_float2(acc[nt][0], acc[nt][1]);
            }
        }
        __syncthreads();
    }
}

// ---------------- final-layer scores + softmax + U (L2-served CTX) ----------------
__global__ void __launch_bounds__(256) finscore_kernel()
{
    int n = blockIdx.x;
    int tid = threadIdx.x, lane = tid & 31, w = tid >> 5;
    __shared__ float Ts[640];
    __shared__ float sA[32];
    __shared__ float sc[2];
    __shared__ float s_sain;
    const float* ctxn = g_CTX + (size_t)n * 10240;

    for (int i = tid; i < 640; i += 256) Ts[i] = g_TT[(size_t)n * 640 + i];
    __syncthreads();
    #pragma unroll
    for (int ii = 0; ii < 4; ii++) {
        int t = w * 4 + ii;
        int side = t >> 4, tok = t & 15;
        const float* cr = ctxn + side * 5120 + tok * 320;
        const float* tv = Ts + side * 320;
        float acc = 0.f;
        #pragma unroll
        for (int i = 0; i < 10; i++) acc += cr[lane + 32 * i] * tv[lane + 32 * i];
        #pragma unroll
        for (int o = 16; o; o >>= 1) acc += __shfl_xor_sync(0xffffffffu, acc, o);
        if (lane == 0) sA[t] = acc;
    }
    if (w < 2) {     // sc = ctx0 . w_side + b_side
        const float* cr = ctxn;
        const float* tv = g_wv + w * 320;
        float acc = 0.f;
        #pragma unroll
        for (int i = 0; i < 10; i++) acc += cr[lane + 32 * i] * tv[lane + 32 * i];
        #pragma unroll
        for (int o = 16; o; o >>= 1) acc += __shfl_xor_sync(0xffffffffu, acc, o);
        if (lane == 0) sc[w] = acc + g_wb[w];
    }
    __syncthreads();
    if (tid < 32) {  // softmax over 32 (scale = 320^-0.5)
        float v = (sA[tid] + sc[tid >> 4]) * 0.05590169943749474f;
        float mx = v;
        #pragma unroll
        for (int o = 16; o; o >>= 1) mx = fmaxf(mx, __shfl_xor_sync(0xffffffffu, mx, o));
        float e = __expf(v - mx);
        float ssum = e;
        #pragma unroll
        for (int o = 16; o; o >>= 1) ssum += __shfl_xor_sync(0xffffffffu, ssum, o);
        float a = e / ssum;
        sA[tid] = a;
        float ain = (tid < 16) ? a : 0.f;
        #pragma unroll
        for (int o = 16; o; o >>= 1) ain += __shfl_xor_sync(0xffffffffu, ain, o);
        if (tid == 0) s_sain = ain;
    }
    __syncthreads();
    float sain = s_sain;
    float* urow = g_U + (size_t)n * UK;
    if (tid < 160) {          // 160 float4 columns = 640 floats
        int side = tid >= 80;
        int off = (tid - side * 80) * 4;
        const float* cb = ctxn + side * 5120;
        const float* av = sA + side * 16;
        float4 acc = make_float4(0.f, 0.f, 0.f, 0.f);
        #pragma unroll
        for (int t = 0; t < 16; t++) {
            float a = av[t];
            float4 v = *(const float4*)(cb + t * 320 + off);
            acc.x += a * v.x; acc.y += a * v.y;
            acc.z += a * v.z; acc.w += a * v.w;
        }
        *(float4*)(urow + side * 320 + off) = acc;
    } else if (tid < 164) {   // tail 640..655
        int base = 640 + (tid - 160) * 4;
        float4 v = make_float4(0.f, 0.f, 0.f, 0.f);
        if (tid == 160) { v.x = sain; v.y = 1.f - sain; }
        *(float4*)(urow + base) = v;
    }
}

// ---------------- out = elu(U @ G + cW), 4 nodes per warp ----------------
__global__ void __launch_bounds__(256) outproj_kernel(float* __restrict__ out)
{
    extern __shared__ float sm2[];
    float* Gs = sm2;                 // 656*32
    float* Us = sm2 + UK * 32;       // 32*656
    int tid = threadIdx.x;
    int n0 = blockIdx.x * 32;

    for (int i = tid; i < (UK * 32) / 4; i += 256)
        ((float4*)Gs)[i] = ((const float4*)g_G)[i];
    const float* usrc = g_U + (size_t)n0 * UK;
    for (int i = tid; i < (32 * UK) / 4; i += 256)
        ((float4*)Us)[i] = ((const float4*)usrc)[i];
    __syncthreads();

    int w = tid >> 5, lane = tid & 31;
    const float* ur0 = Us + (w * 4 + 0) * UK;
    const float* ur1 = Us + (w * 4 + 1) * UK;
    const float* ur2 = Us + (w * 4 + 2) * UK;
    const float* ur3 = Us + (w * 4 + 3) * UK;
    float a0 = 0.f, a1 = 0.f, a2 = 0.f, a3 = 0.f;
    for (int i = 0; i < UK; i += 4) {
        float g0 = Gs[(i + 0) * 32 + lane];
        float g1 = Gs[(i + 1) * 32 + lane];
        float g2 = Gs[(i + 2) * 32 + lane];
        float g3 = Gs[(i + 3) * 32 + lane];
        float4 u0 = *(const float4*)(ur0 + i);
        float4 u1 = *(const float4*)(ur1 + i);
        float4 u2 = *(const float4*)(ur2 + i);
        float4 u3 = *(const float4*)(ur3 + i);
        a0 += u0.x * g0 + u0.y * g1 + u0.z * g2 + u0.w * g3;
        a1 += u1.x * g0 + u1.y * g1 + u1.z * g2 + u1.w * g3;
        a2 += u2.x * g0 + u2.y * g1 + u2.z * g2 + u2.w * g3;
        a3 += u3.x * g0 + u3.y * g1 + u3.z * g2 + u3.w * g3;
    }
    if (lane < OUT_) {
        float cw = g_cW[lane];
        int n = n0 + w * 4;
        float r0 = a0 + cw, r1 = a1 + cw, r2 = a2 + cw, r3 = a3 + cw;
        if (n + 0 < N_NODES) out[(n + 0) * OUT_ + lane] = r0 > 0.f ? r0 : expm1f(r0);
        if (n + 1 < N_NODES) out[(n + 1) * OUT_ + lane] = r1 > 0.f ? r1 : expm1f(r1);
        if (n + 2 < N_NODES) out[(n + 2) * OUT_ + lane] = r2 > 0.f ? r2 : expm1f(r2);
        if (n + 3 < N_NODES) out[(n + 3) * OUT_ + lane] = r3 > 0.f ? r3 : expm1f(r3);
    }
}

// ---------------- host ----------------
extern "C" void kernel_launch(void* const* d_in, const int* in_sizes, int n_in,
                              void* d_out, int out_size)
{
    const float* X         = (const float*)d_in[0];
    const int*   in_idx    = (const int*)  d_in[1];
    const int*   out_idx   = (const int*)  d_in[2];
    const float* in_Wq     = (const float*)d_in[3];
    const float* in_Wk     = (const float*)d_in[4];
    const float* in_Wv     = (const float*)d_in[5];
    const float* in_qkv_w  = (const float*)d_in[6];
    const float* in_qkv_b  = (const float*)d_in[7];
    const float* in_o_w    = (const float*)d_in[8];
    const float* in_o_b    = (const float*)d_in[9];
    const float* out_Wq    = (const float*)d_in[10];
    const float* out_Wk    = (const float*)d_in[11];
    const float* out_Wv    = (const float*)d_in[12];
    const float* out_qkv_w = (const float*)d_in[13];
    const float* out_qkv_b = (const float*)d_in[14];
    const float* out_o_w   = (const float*)d_in[15];
    const float* out_o_b   = (const float*)d_in[16];
    const float* fin_qkv_w = (const float*)d_in[17];
    const float* fin_qkv_b = (const float*)d_in[18];
    const float* fin_o_w   = (const float*)d_in[19];
    const float* fin_o_b   = (const float*)d_in[20];
    const float* Wmat      = (const float*)d_in[21];
    float* out = (float*)d_out;

    float *pMA, *pMq, *pMKin, *pMKout, *pMVin, *pMVout, *pPW, *pMqKcatT, *pG,
          *pXP, *pCTX, *pC0, *pTT, *pU, *pcqK;
    cudaGetSymbolAddress((void**)&pMA, g_MA);
    cudaGetSymbolAddress((void**)&pMq, g_Mq);
    cudaGetSymbolAddress((void**)&pMKin, g_MKin);
    cudaGetSymbolAddress((void**)&pMKout, g_MKout);
    cudaGetSymbolAddress((void**)&pMVin, g_MVin);
    cudaGetSymbolAddress((void**)&pMVout, g_MVout);
    cudaGetSymbolAddress((void**)&pPW, g_PW);
    cudaGetSymbolAddress((void**)&pMqKcatT, g_MqKcat);
    cudaGetSymbolAddress((void**)&pG, g_G);
    cudaGetSymbolAddress((void**)&pXP, g_XP);
    cudaGetSymbolAddress((void**)&pCTX, g_CTX);
    cudaGetSymbolAddress((void**)&pC0, g_C0);
    cudaGetSymbolAddress((void**)&pTT, g_TT);
    cudaGetSymbolAddress((void**)&pU, g_U);
    cudaGetSymbolAddress((void**)&pcqK, g_cqK);

    const int ATTN_SMEM = (3 * T_ * SR + 5 * 16 * 16) * (int)sizeof(float);
    const int OUT_SMEM  = (2 * UK * 32) * (int)sizeof(float);
    const int TF_SMEM   = 2 * 2 * 128 * TFPAD * (int)sizeof(uint32_t);   // 81920
    cudaFuncSetAttribute(attn_kernel, cudaFuncAttributeMaxDynamicSharedMemorySize, ATTN_SMEM);
    cudaFuncSetAttribute(outproj_kernel, cudaFuncAttributeMaxDynamicSharedMemorySize, OUT_SMEM);
    cudaFuncSetAttribute(tf32gemm, cudaFuncAttributeMaxDynamicSharedMemorySize, TF_SMEM);

    // ---- launch 0: compose level 1 (batched, z=12) ----
    GemmBatch L1 = {};
    const float* Ws6[6] = {in_Wq, in_Wk, in_Wv, out_Wq, out_Wk, out_Wv};
    const float* Qw6[6] = {in_qkv_w, in_qkv_w + E_ * E_, in_qkv_w + 2 * E_ * E_,
                           out_qkv_w, out_qkv_w + E_ * E_, out_qkv_w + 2 * E_ * E_};
    for (int s = 0; s < 6; s++)
        L1.d[s] = {Qw6[s], Ws6[s], pMA + s * E_ * E_, nullptr,
                   E_, E_, E_, E_, E_, E_, 0};
    L1.d[6]  = {fin_qkv_w,               in_o_w,  pMq,    nullptr, E_, E_,  E_, E_, E_, E_, 1};
    L1.d[7]  = {fin_qkv_w + E_ * E_,     in_o_w,  pMKin,  nullptr, E_, E_,  E_, E_, E_, E_, 1};
    L1.d[8]  = {fin_qkv_w + E_ * E_,     out_o_w, pMKout, nullptr, E_, E_,  E_, E_, E_, E_, 1};
    L1.d[9]  = {fin_qkv_w + 2 * E_ * E_, in_o_w,  pMVin,  nullptr, E_, E_,  E_, E_, E_, E_, 1};
    L1.d[10] = {fin_qkv_w + 2 * E_ * E_, out_o_w, pMVout, nullptr, E_, E_,  E_, E_, E_, E_, 1};
    L1.d[11] = {fin_o_w,                 Wmat,    pPW,    nullptr, E_, OUT_, E_, E_, OUT_, 32, 2};
    sgemm64<<<dim3(5, 5, 12), 256>>>(L1);

    // ---- launch 1: XP = X @ MA^T  (tf32 tensor cores; needs only L1) ----
    GemmDesc xp = {X, pMA, pXP, nullptr, N_NODES, 1920, E_, E_, E_, 1920, 0};
    tf32gemm<<<dim3(15, 79), 256, TF_SMEM>>>(xp);

    // ---- launch 2: raw-input small vectors + zero G ----
    compose_small2<<<225, 256>>>(fin_qkv_w, fin_qkv_b, fin_o_b, in_o_b, out_o_b, Wmat);

    // ---- launch 3 (ncu capture slot): per-node attention ----
    attn_kernel<<<N_NODES, 256, ATTN_SMEM>>>(in_idx, out_idx, in_qkv_b, out_qkv_b);

    // ---- launch 4: compose level 2 (batched, z=4) ----
    GemmBatch L2 = {};
    L2.d[0] = {pMKin,  pMq, pMqKcatT,            nullptr, E_, E_,  E_, E_, E_, E_, 2};
    L2.d[1] = {pMKout, pMq, pMqKcatT + E_ * E_,  nullptr, E_, E_,  E_, E_, E_, E_, 2};
    L2.d[2] = {pMVin,  pPW, pG,                  nullptr, E_, OUT_, E_, E_, 32, 32, 2};
    L2.d[3] = {pMVout, pPW, pG + E_ * 32,        nullptr, E_, OUT_, E_, E_, 32, 32, 2};
    sgemm64<<<dim3(5, 5, 4), 256>>>(L2);

    // ---- launch 5: level-2 vectors ----
    smallvec_kernel<<<168, 256>>>();

    // ---- launch 6: [Tin|Tout] = C0 @ MqKcatT^T + cqK  (tf32 NT) ----
    GemmDesc tt = {pC0, pMqKcatT, pTT, pcqK, N_NODES, 640, E_, E_, E_, 640, 0};
    tf32gemm<<<dim3(5, 79), 256, TF_SMEM>>>(tt);

    // ---- launch 7: final scores + softmax + U ----
    finscore_kernel<<<N_NODES, 256>>>();

    // ---- launch 8: out = elu(U @ G + cW) ----
    outproj_kernel<<<(N_NODES + 31) / 32, 256, OUT_SMEM>>>(out);
}

// round 16
// speedup vs baseline: 1.9978x; 1.2441x over previous
#include <cuda_runtime.h>
#include <cstdint>
#include <cstddef>

#define N_NODES 10000
#define E_ 320
#define D_ 15
#define T_ 16
#define OUT_ 30
#define UK 656
#define SR 328
#define TFPAD 40

// ---------------- scratch (device globals) ----------------
__device__ float g_MA[6 * E_ * E_];        // composed QKV mats [1920][320]
__device__ float g_Mq[E_ * E_];
__device__ float g_MKin[E_ * E_];
__device__ float g_MKout[E_ * E_];
__device__ float g_MVin[E_ * E_];
__device__ float g_MVout[E_ * E_];
__device__ float g_PW[E_ * 32];            // fo_w^T @ W, padded to 32 cols
__device__ float g_MqKcat[640 * E_];       // [640][320] = [(Mq^T MKin)^T ; (Mq^T MKout)^T]
__device__ float g_G[UK * 32];             // [656][32] out-projection matrix
__device__ float g_bcat[1920];             // [in_qkv_b | out_qkv_b] folded into XP
__device__ float g_cq[E_];
__device__ float g_ckin[E_];
__device__ float g_ckout[E_];
__device__ float g_cvin[E_];
__device__ float g_cvout[E_];
__device__ float g_cW[32];
__device__ float g_wv[640];                // [win | wout]
__device__ float g_wb[2];                  // bin, bout
__device__ float g_cqK[640];               // [cq@MKin | cq@MKout]
__device__ float g_XP[(size_t)N_NODES * 1920];
__device__ float g_CTX[(size_t)N_NODES * 10240];
__device__ float g_C0[(size_t)N_NODES * E_];   // compact copy of in-side ctx token 0
__device__ float g_TT[(size_t)N_NODES * 640];
__device__ float g_U[(size_t)(N_NODES + 32) * UK];

struct GemmDesc {
    const float* A; const float* B; float* C; const float* bias;
    int M, N, K, lda, ldb, ldc, op;  // op: 0=NT, 1=NN, 2=TN
};
struct GemmBatch { GemmDesc d[12]; };

// ---------------- async-copy + mma helpers ----------------
__device__ __forceinline__ void cp_async16(uint32_t dst, const void* src, int src_bytes) {
    asm volatile("cp.async.ca.shared.global [%0], [%1], 16, %2;"
                 :: "r"(dst), "l"(src), "r"(src_bytes) : "memory");
}
__device__ __forceinline__ void cp_commit() {
    asm volatile("cp.async.commit_group;" ::: "memory");
}
template <int N>
__device__ __forceinline__ void cp_wait() {
    asm volatile("cp.async.wait_group %0;" :: "n"(N) : "memory");
}

#define MMA_TF32(d, a, b) \
    asm volatile("mma.sync.aligned.m16n8k8.row.col.f32.tf32.tf32.f32 " \
        "{%0,%1,%2,%3}, {%4,%5,%6,%7}, {%8,%9}, {%0,%1,%2,%3};" \
        : "+f"((d)[0]), "+f"((d)[1]), "+f"((d)[2]), "+f"((d)[3]) \
        : "r"((a)[0]), "r"((a)[1]), "r"((a)[2]), "r"((a)[3]), \
          "r"((b)[0]), "r"((b)[1]))

// ---------------- tf32 tensor-core GEMM (NT): C[m][n] = sum_k A[m][k]*B[n][k] ----------------
__global__ void __launch_bounds__(256) tf32gemm(GemmDesc g)
{
    extern __shared__ uint32_t ts[];
    uint32_t* Asm = ts;                       // [2][128][TFPAD]
    uint32_t* Bsm = ts + 2 * 128 * TFPAD;     // [2][128][TFPAD]
    int tid = threadIdx.x, warp = tid >> 5, lane = tid & 31;
    int wm = (warp >> 2) * 64, wn = (warp & 3) * 32;
    int gr = lane >> 2, gc2 = (lane & 3) << 1;
    int m0 = blockIdx.y * 128, n0 = blockIdx.x * 128;

    float acc[4][4][4] = {};

    int fr = tid >> 1, fc = (tid & 1) << 4;
    const float* Ap = g.A + (size_t)(m0 + fr) * g.lda + fc;
    const float* Bp = g.B + (size_t)(n0 + fr) * g.ldb + fc;
    int asz = ((m0 + fr) < g.M) ? 16 : 0;

    uint32_t aBase = (uint32_t)__cvta_generic_to_shared(Asm);
    uint32_t bBase = (uint32_t)__cvta_generic_to_shared(Bsm);
    uint32_t aDst = aBase + (fr * TFPAD + fc) * 4;
    uint32_t bDst = bBase + (fr * TFPAD + fc) * 4;
    const uint32_t bufStride = 128 * TFPAD * 4;

    int niter = g.K / 32;
    #pragma unroll
    for (int i = 0; i < 4; i++) {
        cp_async16(aDst + i * 16, Ap + i * 4, asz);
        cp_async16(bDst + i * 16, Bp + i * 4, 16);
    }
    cp_commit();
    if (niter > 1) {
        #pragma unroll
        for (int i = 0; i < 4; i++) {
            cp_async16(aDst + bufStride + i * 16, Ap + 32 + i * 4, asz);
            cp_async16(bDst + bufStride + i * 16, Bp + 32 + i * 4, 16);
        }
        cp_commit();
    }

    for (int it = 0; it < niter; it++) {
        if (it + 1 < niter) cp_wait<1>(); else cp_wait<0>();
        __syncthreads();
        const uint32_t* Ab = Asm + (it & 1) * (128 * TFPAD);
        const uint32_t* Bb = Bsm + (it & 1) * (128 * TFPAD);
        #pragma unroll
        for (int ks = 0; ks < 32; ks += 8) {
            uint32_t af[4][4], bf[4][2];
            #pragma unroll
            for (int mt = 0; mt < 4; mt++) {
                int r = wm + mt * 16 + gr;
                uint2 v0 = *(const uint2*)&Ab[r * TFPAD + ks + gc2];
                uint2 v1 = *(const uint2*)&Ab[(r + 8) * TFPAD + ks + gc2];
                af[mt][0] = v0.x; af[mt][2] = v0.y;
                af[mt][1] = v1.x; af[mt][3] = v1.y;
            }
            #pragma unroll
            for (int nt = 0; nt < 4; nt++) {
                int c = wn + nt * 8 + gr;
                uint2 w0 = *(const uint2*)&Bb[c * TFPAD + ks + gc2];
                bf[nt][0] = w0.x; bf[nt][1] = w0.y;
            }
            #pragma unroll
            for (int mt = 0; mt < 4; mt++)
                #pragma unroll
                for (int nt = 0; nt < 4; nt++)
                    MMA_TF32(acc[mt][nt], af[mt], bf[nt]);
        }
        __syncthreads();
        if (it + 2 < niter) {
            int ko = (it + 2) * 32;
            uint32_t boff = (it & 1) * bufStride;
            #pragma unroll
            for (int i = 0; i < 4; i++) {
                cp_async16(aDst + boff + i * 16, Ap + ko + i * 4, asz);
                cp_async16(bDst + boff + i * 16, Bp + ko + i * 4, 16);
            }
            cp_commit();
        }
    }

    int gc = lane & 3;
    #pragma unroll
    for (int mt = 0; mt < 4; mt++) {
        int r = m0 + wm + mt * 16 + gr;
        bool ok0 = r < g.M, ok1 = (r + 8) < g.M;
        float* Crow0 = g.C + (size_t)r * g.ldc;
        #pragma unroll
        for (int nt = 0; nt < 4; nt++) {
            int c = n0 + wn + nt * 8 + 2 * gc;
            float b0 = 0.f, b1 = 0.f;
            if (g.bias) { b0 = g.bias[c]; b1 = g.bias[c + 1]; }
            if (ok0) {
                float2 v = make_float2(acc[mt][nt][0] + b0, acc[mt][nt][1] + b1);
                *(float2*)(Crow0 + c) = v;
            }
            if (ok1) {
                float2 v = make_float2(acc[mt][nt][2] + b0, acc[mt][nt][3] + b1);
                *(float2*)(Crow0 + (size_t)8 * g.ldc + c) = v;
            }
        }
    }
}

// ---------------- small batched GEMM: 64x64 tile, 4x4 micro ----------------
__global__ void __launch_bounds__(256) sgemm64(GemmBatch batch)
{
    GemmDesc g = batch.d[blockIdx.z];
    int m0 = blockIdx.y * 64, n0 = blockIdx.x * 64;
    if (m0 >= g.M || n0 >= g.N) return;
    __shared__ float As[64][17];
    __shared__ float Bs[64][17];
    int tid = threadIdx.x;
    int tx = tid & 15, ty = tid >> 4;
    float acc[4][4] = {};

    for (int k0 = 0; k0 < g.K; k0 += 16) {
        if (g.op == 2) {   // A [K][M]
            #pragma unroll
            for (int i = 0; i < 4; i++) {
                int li = tid + 256 * i;
                int m = li & 63, k = li >> 6;
                int gm = m0 + m;
                As[m][k] = (gm < g.M) ? g.A[(size_t)(k0 + k) * g.lda + gm] : 0.f;
            }
        } else {           // A [M][K]
            #pragma unroll
            for (int i = 0; i < 4; i++) {
                int li = tid + 256 * i;
                int k = li & 15, m = li >> 4;
                int gm = m0 + m;
                As[m][k] = (gm < g.M) ? g.A[(size_t)gm * g.lda + k0 + k] : 0.f;
            }
        }
        if (g.op == 0) {   // B [N][K]
            #pragma unroll
            for (int i = 0; i < 4; i++) {
                int li = tid + 256 * i;
                int k = li & 15, n = li >> 4;
                int gn = n0 + n;
                Bs[n][k] = (gn < g.N) ? g.B[(size_t)gn * g.ldb + k0 + k] : 0.f;
            }
        } else {           // B [K][N]
            #pragma unroll
            for (int i = 0; i < 4; i++) {
                int li = tid + 256 * i;
                int n = li & 63, k = li >> 6;
                int gn = n0 + n;
                Bs[n][k] = (gn < g.N) ? g.B[(size_t)(k0 + k) * g.ldb + gn] : 0.f;
            }
        }
        __syncthreads();
        #pragma unroll
        for (int kk = 0; kk < 16; kk++) {
            float af[4], bf[4];
            #pragma unroll
            for (int r = 0; r < 4; r++) af[r] = As[ty * 4 + r][kk];
            #pragma unroll
            for (int c = 0; c < 4; c++) bf[c] = Bs[tx * 4 + c][kk];
            #pragma unroll
            for (int r = 0; r < 4; r++)
                #pragma unroll
                for (int c = 0; c < 4; c++)
                    acc[r][c] += af[r] * bf[c];
        }
        __syncthreads();
    }
    #pragma unroll
    for (int r = 0; r < 4; r++) {
        int gm = m0 + ty * 4 + r;
        if (gm >= g.M) continue;
        #pragma unroll
        for (int c = 0; c < 4; c++) {
            int gn = n0 + tx * 4 + c;
            if (gn < g.N)
                g.C[(size_t)gm * g.ldc + gn] = acc[r][c] + (g.bias ? g.bias[gn] : 0.f);
        }
    }
}

// ---------------- warp-parallel raw-input vectors + zero G + bcat ----------------
__global__ void __launch_bounds__(256) compose_small2(
    const float* __restrict__ finw, const float* __restrict__ finb,
    const float* __restrict__ fob,
    const float* __restrict__ inob, const float* __restrict__ outob,
    const float* __restrict__ W,
    const float* __restrict__ inqb, const float* __restrict__ outqb)
{
    if (blockIdx.x >= 225) {               // bcat = [in_qkv_b | out_qkv_b]
        int i = (blockIdx.x - 225) * 256 + threadIdx.x;
        if (i < 480) {
            int f = i * 4;
            float4 v = (f < 960) ? *(const float4*)(inqb + f)
                                 : *(const float4*)(outqb + f - 960);
            *(float4*)(g_bcat + f) = v;
        }
        return;
    }
    if (blockIdx.x >= 204) {
        int i = (blockIdx.x - 204) * 256 + threadIdx.x;
        if (i < (UK * 32) / 4) ((float4*)g_G)[i] = make_float4(0.f, 0.f, 0.f, 0.f);
        return;
    }
    int gw = blockIdx.x * 8 + (threadIdx.x >> 5);
    int lane = threadIdx.x & 31;
    float acc = 0.f;
    if (gw < 1600) {
        int grp = gw / 320, j = gw - grp * 320;
        const float* row;
        const float* vec;
        float b;
        if (grp == 0)      { row = finw + (size_t)j * E_;            vec = inob;  b = finb[j]; }
        else if (grp == 1) { row = finw + (size_t)(E_ + j) * E_;     vec = inob;  b = finb[E_ + j]; }
        else if (grp == 2) { row = finw + (size_t)(E_ + j) * E_;     vec = outob; b = finb[E_ + j]; }
        else if (grp == 3) { row = finw + (size_t)(2 * E_ + j) * E_; vec = inob;  b = finb[2 * E_ + j]; }
        else               { row = finw + (size_t)(2 * E_ + j) * E_; vec = outob; b = finb[2 * E_ + j]; }
        #pragma unroll
        for (int i = 0; i < 10; i++) acc += row[lane + 32 * i] * vec[lane + 32 * i];
        #pragma unroll
        for (int o = 16; o; o >>= 1) acc += __shfl_xor_sync(0xffffffffu, acc, o);
        if (lane == 0) {
            acc += b;
            if (grp == 0)      g_cq[j] = acc;
            else if (grp == 1) g_ckin[j] = acc;
            else if (grp == 2) g_ckout[j] = acc;
            else if (grp == 3) g_cvin[j] = acc;
            else               g_cvout[j] = acc;
        }
    } else if (gw < 1632) {
        int o = gw - 1600;
        if (o < OUT_) {
            #pragma unroll
            for (int i = 0; i < 10; i++) {
                int k = lane + 32 * i;
                acc += fob[k] * W[k * OUT_ + o];
            }
        }
        #pragma unroll
        for (int oo = 16; oo; oo >>= 1) acc += __shfl_xor_sync(0xffffffffu, acc, oo);
        if (lane == 0) g_cW[o] = (o < OUT_) ? acc : 0.f;
    }
}

// ---------------- warp-parallel level-2 vectors ----------------
__global__ void __launch_bounds__(256) smallvec_kernel()
{
    int gw = blockIdx.x * 8 + (threadIdx.x >> 5);
    int lane = threadIdx.x & 31;
    float acc = 0.f;
    if (gw < 640) {                        // wv[i] = sum_j Mq[j][i] * ck[j]
        int side = gw >= 320;
        int i = gw - side * 320;
        const float* ck = side ? g_ckout : g_ckin;
        #pragma unroll
        for (int q = 0; q < 10; q++) {
            int j = lane + 32 * q;
            acc += g_Mq[(size_t)j * E_ + i] * ck[j];
        }
        #pragma unroll
        for (int o = 16; o; o >>= 1) acc += __shfl_xor_sync(0xffffffffu, acc, o);
        if (lane == 0) g_wv[gw] = acc;
    } else if (gw < 1280) {                // cqK[c] = sum_j cq[j] * MK[j][c]
        int side = gw >= 960;
        int c = gw - 640 - side * 320;
        const float* MK = side ? g_MKout : g_MKin;
        #pragma unroll
        for (int q = 0; q < 10; q++) {
            int j = lane + 32 * q;
            acc += g_cq[j] * MK[(size_t)j * E_ + c];
        }
        #pragma unroll
        for (int o = 16; o; o >>= 1) acc += __shfl_xor_sync(0xffffffffu, acc, o);
        if (lane == 0) g_cqK[side * 320 + c] = acc;
    } else if (gw < 1340) {                // G rows 640/641 = PW^T cv
        int r = gw - 1280;
        int row = r >= 30;
        int o = r - row * 30;
        const float* cv = row ? g_cvout : g_cvin;
        #pragma unroll
        for (int q = 0; q < 10; q++) {
            int c = lane + 32 * q;
            acc += cv[c] * g_PW[c * 32 + o];
        }
        #pragma unroll
        for (int oo = 16; oo; oo >>= 1) acc += __shfl_xor_sync(0xffffffffu, acc, oo);
        if (lane == 0) g_G[(640 + row) * 32 + o] = acc;
    } else if (gw < 1342) {                // wb = cq . ck
        int w = gw - 1340;
        const float* ck = w ? g_ckout : g_ckin;
        #pragma unroll
        for (int q = 0; q < 10; q++) {
            int j = lane + 32 * q;
            acc += g_cq[j] * ck[j];
        }
        #pragma unroll
        for (int o = 16; o; o >>= 1) acc += __shfl_xor_sync(0xffffffffu, acc, o);
        if (lane == 0) g_wb[w] = acc;
    }
}

// ---------------- per-node 5-head attention (tf32 mma; cp.async gather, bias pre-folded) ----------------
__global__ void __launch_bounds__(256, 3) attn_kernel(
    const int* __restrict__ in_idx, const int* __restrict__ out_idx)
{
    int n = blockIdx.x;
    int tid = threadIdx.x, warp = tid >> 5, lane = tid & 31;
    int gr = lane >> 2, gc = lane & 3;
    extern __shared__ float sm[];
    float* Qs = sm;                 // 16*SR ; Ks, Vs contiguous after
    float* Ks = Qs + T_ * SR;
    float* Vs = Ks + T_ * SR;
    float* Ss = Vs + T_ * SR;       // 5*16*16 = 1280 (scores -> probs)
    __shared__ int rows[2][T_];
    uint32_t smBase = (uint32_t)__cvta_generic_to_shared(sm);

    if (tid < 32) {
        int s = tid >> 4, t = tid & 15;
        const int* idx = s ? out_idx : in_idx;
        rows[s][t] = t ? idx[n * D_ + t - 1] : n;
    }
    __syncthreads();

    for (int side = 0; side < 2; side++) {
        int colbase = side * 960;
        // gather Q,K,V rows: pure cp.async copies (bias already folded into XP)
        #pragma unroll
        for (int i = 0; i < 15; i++) {
            int e = tid + 256 * i;
            int a = e / 1280, r = e - a * 1280;
            int t = r / 80, j = (r - t * 80) * 4;
            const float* src = g_XP + (size_t)rows[side][t] * 1920 + colbase + a * 320 + j;
            cp_async16(smBase + (uint32_t)(a * T_ * SR + t * SR + j) * 4, src, 16);
        }
        cp_commit();
        cp_wait<0>();
        __syncthreads();
        // scores: warp h (<5): S_h[16][16] = Q_h @ K_h^T, tf32 mma
        if (warp < 5) {
            int hb = warp * 64;
            float acc[2][4] = {};
            #pragma unroll
            for (int k0 = 0; k0 < 64; k0 += 8) {
                uint32_t a[4], b0[2], b1[2];
                const float* qb = Qs + hb + k0 + gc;
                a[0] = __float_as_uint(qb[gr * SR]);
                a[1] = __float_as_uint(qb[(gr + 8) * SR]);
                a[2] = __float_as_uint(qb[gr * SR + 4]);
                a[3] = __float_as_uint(qb[(gr + 8) * SR + 4]);
                const float* kb = Ks + hb + k0 + gc;
                b0[0] = __float_as_uint(kb[gr * SR]);
                b0[1] = __float_as_uint(kb[gr * SR + 4]);
                b1[0] = __float_as_uint(kb[(gr + 8) * SR]);
                b1[1] = __float_as_uint(kb[(gr + 8) * SR + 4]);
                MMA_TF32(acc[0], a, b0);
                MMA_TF32(acc[1], a, b1);
            }
            float* srow = Ss + warp * 256;
            #pragma unroll
            for (int nt = 0; nt < 2; nt++) {
                *(float2*)&srow[gr * 16 + nt * 8 + 2 * gc] =
                    make_float2(acc[nt][0], acc[nt][1]);
                *(float2*)&srow[(gr + 8) * 16 + nt * 8 + 2 * gc] =
                    make_float2(acc[nt][2], acc[nt][3]);
            }
        }
        __syncthreads();
        // softmax: 80 (h,l) rows of 16, scale 1/8
        if (tid < 80) {
            float* row = Ss + tid * 16;
            float v[16];
            float mx = -1e30f;
            #pragma unroll
            for (int m = 0; m < 16; m++) {
                v[m] = row[m] * 0.125f;
                mx = fmaxf(mx, v[m]);
            }
            float ssum = 0.f;
            #pragma unroll
            for (int m = 0; m < 16; m++) { v[m] = __expf(v[m] - mx); ssum += v[m]; }
            float inv = 1.f / ssum;
            #pragma unroll
            for (int m = 0; m < 16; m++) row[m] = v[m] * inv;
        }
        __syncthreads();
        // ctx = P @ V via tf32 mma: 10 slices of 32 cols over 8 warps
        float* ctxout = g_CTX + (size_t)n * 10240 + side * 5120;
        for (int sl = warp; sl < 10; sl += 8) {
            int ns = sl * 32;
            int h = ns >> 6;
            const float* P = Ss + h * 256;
            float acc[4][4] = {};
            #pragma unroll
            for (int k0 = 0; k0 < 16; k0 += 8) {
                uint32_t a[4];
                a[0] = __float_as_uint(P[gr * 16 + k0 + gc]);
                a[1] = __float_as_uint(P[(gr + 8) * 16 + k0 + gc]);
                a[2] = __float_as_uint(P[gr * 16 + k0 + gc + 4]);
                a[3] = __float_as_uint(P[(gr + 8) * 16 + k0 + gc + 4]);
                #pragma unroll
                for (int nt = 0; nt < 4; nt++) {
                    uint32_t b[2];
                    const float* vb = Vs + ns + nt * 8 + gr;
                    b[0] = __float_as_uint(vb[(k0 + gc) * SR]);
                    b[1] = __float_as_uint(vb[(k0 + gc + 4) * SR]);
                    MMA_TF32(acc[nt], a, b);
                }
            }
            #pragma unroll
            for (int nt = 0; nt < 4; nt++) {
                int c = ns + nt * 8 + 2 * gc;
                *(float2*)(ctxout + (size_t)gr * 320 + c) =
                    make_float2(acc[nt][0], acc[nt][1]);
                *(float2*)(ctxout + (size_t)(gr + 8) * 320 + c) =
                    make_float2(acc[nt][2], acc[nt][3]);
                if (side == 0 && gr == 0)
                    *(float2*)(g_C0 + (size_t)n * E_ + c) =
                        make_float2(acc[nt][0], acc[nt][1]);
            }
        }
        __syncthreads();
    }
}

// ---------------- final-layer scores + softmax + U (L2-served CTX) ----------------
__global__ void __launch_bounds__(256) finscore_kernel()
{
    int n = blockIdx.x;
    int tid = threadIdx.x, lane = tid & 31, w = tid >> 5;
    __shared__ float Ts[640];
    __shared__ float sA[32];
    __shared__ float sc[2];
    __shared__ float s_sain;
    const float* ctxn = g_CTX + (size_t)n * 10240;

    for (int i = tid; i < 640; i += 256) Ts[i] = g_TT[(size_t)n * 640 + i];
    __syncthreads();
    #pragma unroll
    for (int ii = 0; ii < 4; ii++) {
        int t = w * 4 + ii;
        int side = t >> 4, tok = t & 15;
        const float* cr = ctxn + side * 5120 + tok * 320;
        const float* tv = Ts + side * 320;
        float acc = 0.f;
        #pragma unroll
        for (int i = 0; i < 10; i++) acc += cr[lane + 32 * i] * tv[lane + 32 * i];
        #pragma unroll
        for (int o = 16; o; o >>= 1) acc += __shfl_xor_sync(0xffffffffu, acc, o);
        if (lane == 0) sA[t] = acc;
    }
    if (w < 2) {     // sc = ctx0 . w_side + b_side
        const float* cr = ctxn;
        const float* tv = g_wv + w * 320;
        float acc = 0.f;
        #pragma unroll
        for (int i = 0; i < 10; i++) acc += cr[lane + 32 * i] * tv[lane + 32 * i];
        #pragma unroll
        for (int o = 16; o; o >>= 1) acc += __shfl_xor_sync(0xffffffffu, acc, o);
        if (lane == 0) sc[w] = acc + g_wb[w];
    }
    __syncthreads();
    if (tid < 32) {  // softmax over 32 (scale = 320^-0.5)
        float v = (sA[tid] + sc[tid >> 4]) * 0.05590169943749474f;
        float mx = v;
        #pragma unroll
        for (int o = 16; o; o >>= 1) mx = fmaxf(mx, __shfl_xor_sync(0xffffffffu, mx, o));
        float e = __expf(v - mx);
        float ssum = e;
        #pragma unroll
        for (int o = 16; o; o >>= 1) ssum += __shfl_xor_sync(0xffffffffu, ssum, o);
        float a = e / ssum;
        sA[tid] = a;
        float ain = (tid < 16) ? a : 0.f;
        #pragma unroll
        for (int o = 16; o; o >>= 1) ain += __shfl_xor_sync(0xffffffffu, ain, o);
        if (tid == 0) s_sain = ain;
    }
    __syncthreads();
    float sain = s_sain;
    float* urow = g_U + (size_t)n * UK;
    if (tid < 160) {          // 160 float4 columns = 640 floats
        int side = tid >= 80;
        int off = (tid - side * 80) * 4;
        const float* cb = ctxn + side * 5120;
        const float* av = sA + side * 16;
        float4 acc = make_float4(0.f, 0.f, 0.f, 0.f);
        #pragma unroll
        for (int t = 0; t < 16; t++) {
            float a = av[t];
            float4 v = *(const float4*)(cb + t * 320 + off);
            acc.x += a * v.x; acc.y += a * v.y;
            acc.z += a * v.z; acc.w += a * v.w;
        }
        *(float4*)(urow + side * 320 + off) = acc;
    } else if (tid < 164) {   // tail 640..655
        int base = 640 + (tid - 160) * 4;
        float4 v = make_float4(0.f, 0.f, 0.f, 0.f);
        if (tid == 160) { v.x = sain; v.y = 1.f - sain; }
        *(float4*)(urow + base) = v;
    }
}

// ---------------- out = elu(U @ G + cW), 4 nodes per warp ----------------
__global__ void __launch_bounds__(256) outproj_kernel(float* __restrict__ out)
{
    extern __shared__ float sm2[];
    float* Gs = sm2;                 // 656*32
    float* Us = sm2 + UK * 32;       // 32*656
    int tid = threadIdx.x;
    int n0 = blockIdx.x * 32;

    for (int i = tid; i < (UK * 32) / 4; i += 256)
        ((float4*)Gs)[i] = ((const float4*)g_G)[i];
    const float* usrc = g_U + (size_t)n0 * UK;
    for (int i = tid; i < (32 * UK) / 4; i += 256)
        ((float4*)Us)[i] = ((const float4*)usrc)[i];
    __syncthreads();

    int w = tid >> 5, lane = tid & 31;
    const float* ur0 = Us + (w * 4 + 0) * UK;
    const float* ur1 = Us + (w * 4 + 1) * UK;
    const float* ur2 = Us + (w * 4 + 2) * UK;
    const float* ur3 = Us + (w * 4 + 3) * UK;
    float a0 = 0.f, a1 = 0.f, a2 = 0.f, a3 = 0.f;
    for (int i = 0; i < UK; i += 4) {
        float g0 = Gs[(i + 0) * 32 + lane];
        float g1 = Gs[(i + 1) * 32 + lane];
        float g2 = Gs[(i + 2) * 32 + lane];
        float g3 = Gs[(i + 3) * 32 + lane];
        float4 u0 = *(const float4*)(ur0 + i);
        float4 u1 = *(const float4*)(ur1 + i);
        float4 u2 = *(const float4*)(ur2 + i);
        float4 u3 = *(const float4*)(ur3 + i);
        a0 += u0.x * g0 + u0.y * g1 + u0.z * g2 + u0.w * g3;
        a1 += u1.x * g0 + u1.y * g1 + u1.z * g2 + u1.w * g3;
        a2 += u2.x * g0 + u2.y * g1 + u2.z * g2 + u2.w * g3;
        a3 += u3.x * g0 + u3.y * g1 + u3.z * g2 + u3.w * g3;
    }
    if (lane < OUT_) {
        float cw = g_cW[lane];
        int n = n0 + w * 4;
        float r0 = a0 + cw, r1 = a1 + cw, r2 = a2 + cw, r3 = a3 + cw;
        if (n + 0 < N_NODES) out[(n + 0) * OUT_ + lane] = r0 > 0.f ? r0 : expm1f(r0);
        if (n + 1 < N_NODES) out[(n + 1) * OUT_ + lane] = r1 > 0.f ? r1 : expm1f(r1);
        if (n + 2 < N_NODES) out[(n + 2) * OUT_ + lane] = r2 > 0.f ? r2 : expm1f(r2);
        if (n + 3 < N_NODES) out[(n + 3) * OUT_ + lane] = r3 > 0.f ? r3 : expm1f(r3);
    }
}

// ---------------- host ----------------
extern "C" void kernel_launch(void* const* d_in, const int* in_sizes, int n_in,
                              void* d_out, int out_size)
{
    const float* X         = (const float*)d_in[0];
    const int*   in_idx    = (const int*)  d_in[1];
    const int*   out_idx   = (const int*)  d_in[2];
    const float* in_Wq     = (const float*)d_in[3];
    const float* in_Wk     = (const float*)d_in[4];
    const float* in_Wv     = (const float*)d_in[5];
    const float* in_qkv_w  = (const float*)d_in[6];
    const float* in_qkv_b  = (const float*)d_in[7];
    const float* in_o_w    = (const float*)d_in[8];
    const float* in_o_b    = (const float*)d_in[9];
    const float* out_Wq    = (const float*)d_in[10];
    const float* out_Wk    = (const float*)d_in[11];
    const float* out_Wv    = (const float*)d_in[12];
    const float* out_qkv_w = (const float*)d_in[13];
    const float* out_qkv_b = (const float*)d_in[14];
    const float* out_o_w   = (const float*)d_in[15];
    const float* out_o_b   = (const float*)d_in[16];
    const float* fin_qkv_w = (const float*)d_in[17];
    const float* fin_qkv_b = (const float*)d_in[18];
    const float* fin_o_w   = (const float*)d_in[19];
    const float* fin_o_b   = (const float*)d_in[20];
    const float* Wmat      = (const float*)d_in[21];
    float* out = (float*)d_out;

    float *pMA, *pMq, *pMKin, *pMKout, *pMVin, *pMVout, *pPW, *pMqKcatT, *pG,
          *pXP, *pCTX, *pC0, *pTT, *pU, *pcqK, *pbcat;
    cudaGetSymbolAddress((void**)&pMA, g_MA);
    cudaGetSymbolAddress((void**)&pMq, g_Mq);
    cudaGetSymbolAddress((void**)&pMKin, g_MKin);
    cudaGetSymbolAddress((void**)&pMKout, g_MKout);
    cudaGetSymbolAddress((void**)&pMVin, g_MVin);
    cudaGetSymbolAddress((void**)&pMVout, g_MVout);
    cudaGetSymbolAddress((void**)&pPW, g_PW);
    cudaGetSymbolAddress((void**)&pMqKcatT, g_MqKcat);
    cudaGetSymbolAddress((void**)&pG, g_G);
    cudaGetSymbolAddress((void**)&pXP, g_XP);
    cudaGetSymbolAddress((void**)&pCTX, g_CTX);
    cudaGetSymbolAddress((void**)&pC0, g_C0);
    cudaGetSymbolAddress((void**)&pTT, g_TT);
    cudaGetSymbolAddress((void**)&pU, g_U);
    cudaGetSymbolAddress((void**)&pcqK, g_cqK);
    cudaGetSymbolAddress((void**)&pbcat, g_bcat);

    const int ATTN_SMEM = (3 * T_ * SR + 5 * 16 * 16) * (int)sizeof(float);
    const int OUT_SMEM  = (2 * UK * 32) * (int)sizeof(float);
    const int TF_SMEM   = 2 * 2 * 128 * TFPAD * (int)sizeof(uint32_t);   // 81920
    cudaFuncSetAttribute(attn_kernel, cudaFuncAttributeMaxDynamicSharedMemorySize, ATTN_SMEM);
    cudaFuncSetAttribute(outproj_kernel, cudaFuncAttributeMaxDynamicSharedMemorySize, OUT_SMEM);
    cudaFuncSetAttribute(tf32gemm, cudaFuncAttributeMaxDynamicSharedMemorySize, TF_SMEM);

    // ---- launch 0: compose level 1 (batched, z=12) ----
    GemmBatch L1 = {};
    const float* Ws6[6] = {in_Wq, in_Wk, in_Wv, out_Wq, out_Wk, out_Wv};
    const float* Qw6[6] = {in_qkv_w, in_qkv_w + E_ * E_, in_qkv_w + 2 * E_ * E_,
                           out_qkv_w, out_qkv_w + E_ * E_, out_qkv_w + 2 * E_ * E_};
    for (int s = 0; s < 6; s++)
        L1.d[s] = {Qw6[s], Ws6[s], pMA + s * E_ * E_, nullptr,
                   E_, E_, E_, E_, E_, E_, 0};
    L1.d[6]  = {fin_qkv_w,               in_o_w,  pMq,    nullptr, E_, E_,  E_, E_, E_, E_, 1};
    L1.d[7]  = {fin_qkv_w + E_ * E_,     in_o_w,  pMKin,  nullptr, E_, E_,  E_, E_, E_, E_, 1};
    L1.d[8]  = {fin_qkv_w + E_ * E_,     out_o_w, pMKout, nullptr, E_, E_,  E_, E_, E_, E_, 1};
    L1.d[9]  = {fin_qkv_w + 2 * E_ * E_, in_o_w,  pMVin,  nullptr, E_, E_,  E_, E_, E_, E_, 1};
    L1.d[10] = {fin_qkv_w + 2 * E_ * E_, out_o_w, pMVout, nullptr, E_, E_,  E_, E_, E_, E_, 1};
    L1.d[11] = {fin_o_w,                 Wmat,    pPW,    nullptr, E_, OUT_, E_, E_, OUT_, 32, 2};
    sgemm64<<<dim3(5, 5, 12), 256>>>(L1);

    // ---- launch 1: raw-input small vectors + zero G + bcat (before XP: bcat feeds XP bias) ----
    compose_small2<<<227, 256>>>(fin_qkv_w, fin_qkv_b, fin_o_b, in_o_b, out_o_b, Wmat,
                                 in_qkv_b, out_qkv_b);

    // ---- launch 2: XP = X @ MA^T + bcat  (tf32 tensor cores) ----
    GemmDesc xp = {X, pMA, pXP, pbcat, N_NODES, 1920, E_, E_, E_, 1920, 0};
    tf32gemm<<<dim3(15, 79), 256, TF_SMEM>>>(xp);

    // ---- launch 3 (ncu capture slot): per-node attention ----
    attn_kernel<<<N_NODES, 256, ATTN_SMEM>>>(in_idx, out_idx);

    // ---- launch 4: compose level 2 (batched, z=4) ----
    GemmBatch L2 = {};
    L2.d[0] = {pMKin,  pMq, pMqKcatT,            nullptr, E_, E_,  E_, E_, E_, E_, 2};
    L2.d[1] = {pMKout, pMq, pMqKcatT + E_ * E_,  nullptr, E_, E_,  E_, E_, E_, E_, 2};
    L2.d[2] = {pMVin,  pPW, pG,                  nullptr, E_, OUT_, E_, E_, 32, 32, 2};
    L2.d[3] = {pMVout, pPW, pG + E_ * 32,        nullptr, E_, OUT_, E_, E_, 32, 32, 2};
    sgemm64<<<dim3(5, 5, 4), 256>>>(L2);

    // ---- launch 5: level-2 vectors ----
    smallvec_kernel<<<168, 256>>>();

    // ---- launch 6: [Tin|Tout] = C0 @ MqKcatT^T + cqK  (tf32 NT) ----
    GemmDesc tt = {pC0, pMqKcatT, pTT, pcqK, N_NODES, 640, E_, E_, E_, 640, 0};
    tf32gemm<<<dim3(5, 79), 256, TF_SMEM>>>(tt);

    // ---- launch 7: final scores + softmax + U ----
    finscore_kernel<<<N_NODES, 256>>>();

    // ---- launch 8: out = elu(U @ G + cW) ----
    outproj_kernel<<<(N_NODES + 31) / 32, 256, OUT_SMEM>>>(out);
}